// round 10
// baseline (speedup 1.0000x reference)
#include <cuda_runtime.h>
#include <cuda_bf16.h>
#include <math.h>
#include <stdint.h>

#define NA   4096
#define HD   256
#define HG   256
#define ACT  64
#define MMB  1024

// ---------------- device scratch ----------------
__device__ float g_hWT[HG*NA];
__device__ float g_commT[HG*NA];
__device__ float g_bsum[4*HD];
__device__ __nv_bfloat16 g_Ah[NA*512];       // [obs | h0] gates A (ld 512)
__device__ __nv_bfloat16 g_Al[NA*512];
__device__ __nv_bfloat16 g_A2h[NA*256];      // Wih perm split (wgemm A)
__device__ __nv_bfloat16 g_A2l[NA*256];
__device__ __nv_bfloat16 g_B0h[256*256], g_B0l[256*256];    // Wobs raw
__device__ __nv_bfloat16 g_Bgh[1024*512], g_Bgl[1024*512];  // [Wobs*Wih^T | Whh] perm
__device__ __nv_bfloat16 g_B1h[256*256], g_B1l[256*256];    // W1^T
__device__ __nv_bfloat16 g_B2h[256*256], g_B2l[256*256];    // W2^T
__device__ float g_ci[4*NA];
__device__ float g_cj[4*NA];
__device__ int   g_kcount[4*NA];
__device__ int   g_sidx[4*NA];
__device__ float g_wA[4*NA];
__device__ float g_wB[4*NA];
__device__ float g_rn[4*NA];
__device__ float g_invd[4*NA];
__device__ float g_pmin[MMB];
__device__ float g_pmax[MMB];
__device__ double g_loss;

__device__ __forceinline__ void bf16split(float x, __nv_bfloat16* hi, __nv_bfloat16* lo) {
    __nv_bfloat16 h = __float2bfloat16(x);
    *hi = h;
    *lo = __float2bfloat16(x - __bfloat162float(h));
}

// ---------------- fused prep ----------------
#define WQ0 (NA*256)
#define WQ1 (WQ0 + NA*256)
#define WQ2 (WQ1 + 65536)
#define WQ3 (WQ2 + 262144)
#define WQ4 (WQ3 + 262144)
#define WQ5 (WQ4 + 65536)
#define WQ6 (WQ5 + 65536)
#define WQ7 (WQ6 + 16384)
#define WQ8 (WQ7 + 32768)
__global__ void wprep(const float* __restrict__ obs, const float* __restrict__ h0,
                      const float* __restrict__ Wobs,
                      const float* __restrict__ Wih, const float* __restrict__ Whh,
                      const float* __restrict__ W1, const float* __restrict__ W2,
                      const float* __restrict__ bih, const float* __restrict__ bhh,
                      const float* __restrict__ bobs)
{
    int idx = blockIdx.x*256 + threadIdx.x;
    if (idx == 0) g_loss = 0.0;
    if (idx < WQ0) {
        int n = idx >> 8, k = idx & 255;
        int d = n*512 + k;
        bf16split(obs[idx], &g_Ah[d], &g_Al[d]);
    } else if (idx < WQ1) {
        int j = idx - WQ0;
        int n = j >> 8, k = j & 255;
        int d = n*512 + 256 + k;
        bf16split(h0[j], &g_Ah[d], &g_Al[d]);
    } else if (idx < WQ2) {
        int j = idx - WQ1;
        bf16split(Wobs[j], &g_B0h[j], &g_B0l[j]);
    } else if (idx < WQ3) {
        int j = idx - WQ2;
        int r = j >> 8, k = j & 255;
        int G = (r >> 3) & 3;
        int u = ((r >> 5) << 3) | (r & 7);
        bf16split(Wih[(G*256 + u)*256 + k], &g_A2h[j], &g_A2l[j]);
    } else if (idx < WQ4) {
        int j = idx - WQ3;
        int r = j >> 8, k = j & 255;
        int G = (r >> 3) & 3;
        int u = ((r >> 5) << 3) | (r & 7);
        int d = r*512 + 256 + k;
        bf16split(Whh[(G*256 + u)*256 + k], &g_Bgh[d], &g_Bgl[d]);
    } else if (idx < WQ5) {
        int j = idx - WQ4;
        int n = j >> 8, k = j & 255;
        bf16split(W1[k*256 + n], &g_B1h[j], &g_B1l[j]);
    } else if (idx < WQ6) {
        int j = idx - WQ5;
        int n = j >> 8, k = j & 255;
        bf16split(W2[k*256 + n], &g_B2h[j], &g_B2l[j]);
    } else if (idx < WQ7) {
        int j = idx - WQ6;
        g_ci[j] = 0.f; g_cj[j] = 0.f;
    } else if (idx < WQ8) {
        int t = idx - WQ7;
        int r = t >> 5, lane = t & 31;
        int G = (r >> 3) & 3;
        int u = ((r >> 5) << 3) | (r & 7);
        int orow = G*256 + u;
        float s = 0.f;
        #pragma unroll
        for (int k = lane; k < 256; k += 32)
            s = fmaf(bobs[k], Wih[orow*256 + k], s);
        for (int o = 16; o > 0; o >>= 1) s += __shfl_down_sync(0xffffffffu, s, o);
        if (lane == 0) g_bsum[r] = s + bih[orow] + bhh[orow];
    }
}

// ---------------- mma.sync helpers ----------------
__device__ __forceinline__ uint32_t cvta_sm(const void* p) {
    uint32_t a;
    asm("{ .reg .u64 t; cvta.to.shared.u64 t, %1; cvt.u32.u64 %0, t; }" : "=r"(a) : "l"(p));
    return a;
}
__device__ __forceinline__ void ldm_x4(uint32_t (&d)[4], uint32_t addr) {
    asm volatile("ldmatrix.sync.aligned.m8n8.x4.shared.b16 {%0,%1,%2,%3}, [%4];"
        : "=r"(d[0]), "=r"(d[1]), "=r"(d[2]), "=r"(d[3]) : "r"(addr));
}
__device__ __forceinline__ void mma16816(float (&c)[4], const uint32_t (&a)[4],
                                         uint32_t b0, uint32_t b1) {
    asm volatile("mma.sync.aligned.m16n8k16.row.col.f32.bf16.bf16.f32 "
        "{%0,%1,%2,%3},{%4,%5,%6,%7},{%8,%9},{%0,%1,%2,%3};"
        : "+f"(c[0]), "+f"(c[1]), "+f"(c[2]), "+f"(c[3])
        : "r"(a[0]), "r"(a[1]), "r"(a[2]), "r"(a[3]), "r"(b0), "r"(b1));
}

// ---------------- split-bf16 tensor GEMM, cp.async 2-stage pipeline ----------
// Modes: bf16 A (Ah/Al) OR fp32 A with fused fake-quant (Aq, aTrans).
// Outputs: Shi/Slo split; hwT transposed (+ci/cj atomics); LSTM epilogue (BM=128).
#define TG_STRIDE 40
#define STAGF 2304            // fp32 staging floats per stage (max of 64*36, 32*68)

template<int BM>
__global__ void __launch_bounds__(256, BM == 64 ? 2 : 1)
tgemm(const __nv_bfloat16* __restrict__ Ah, const __nv_bfloat16* __restrict__ Al,
      const __nv_bfloat16* __restrict__ Bh, const __nv_bfloat16* __restrict__ Bl,
      const float* __restrict__ bias,
      __nv_bfloat16* __restrict__ Shi, __nv_bfloat16* __restrict__ Slo, int ldS,
      float* __restrict__ hwT, const float* __restrict__ aivec,
      const float* __restrict__ ajvec, int Gh,
      const float* __restrict__ c0v, float* __restrict__ hOut, float* __restrict__ cOut,
      const float* __restrict__ Aq, int aTrans, int npart,
      int N, int K)
{
    constexpr int A_ELE = BM * TG_STRIDE;
    constexpr int B_ELE = 128 * TG_STRIDE;
    constexpr int STAGE = 2*A_ELE + 2*B_ELE;
    constexpr int NWM  = BM / 32;
    constexpr int WN   = 128 / (8 / NWM);
    constexpr int NB16 = WN / 16;
    constexpr int NB   = WN / 8;
    constexpr int A_U4 = BM * 4;
    constexpr int B_U4 = 512;
    constexpr int TOT_U4 = 2*A_U4 + 2*B_U4;

    extern __shared__ __nv_bfloat16 sm[];
    int tid = threadIdx.x, lane = tid & 31, wid = tid >> 5;
    int col0 = blockIdx.x * 128, row0 = blockIdx.y * BM;
    int wm = (wid % NWM) * 32, wn = (wid / NWM) * WN;
    uint32_t sb = cvta_sm(sm);
    float* stagF = (float*)(sm + 2*STAGE);   // 2 stages x STAGF floats

    __shared__ float s_qp[2];
    __shared__ double sdl[256];
    bool doLoss = (Aq != nullptr) && (blockIdx.x == 0);
    double lpart = 0.0;

    if (Aq) {
        // per-CTA qparam from producer's min/max partials
        __shared__ float smn[256], smx[256];
        float mn = (tid < npart) ? g_pmin[tid] : 1e30f;
        float mx = (tid < npart) ? g_pmax[tid] : -1e30f;
        smn[tid] = mn; smx[tid] = mx; __syncthreads();
        for (int s = 128; s > 0; s >>= 1) {
            if (tid < s) {
                smn[tid] = fminf(smn[tid], smn[tid+s]);
                smx[tid] = fmaxf(smx[tid], smx[tid+s]);
            }
            __syncthreads();
        }
        if (tid == 0) {
            float a = smn[0], b = smx[0];
            if (a == b) { a -= 0.01f; b += 0.01f; }
            float scale = (b - a) / 255.f;
            s_qp[0] = scale;
            s_qp[1] = rintf(-a / scale);
        }
        __syncthreads();
    }

    float acc[2][NB][4] = {};

    auto issue = [&](int stage, int k0) {
        uint32_t stb = sb + (uint32_t)stage * STAGE * 2;
        if (Aq) {
            uint32_t sfb = cvta_sm(stagF + stage * STAGF);
            #pragma unroll
            for (int l = 0; l < 6; l++) {             // 1536 u4 total
                int i = tid + l * 256;
                if (i < 512) {
                    const float* src;
                    uint32_t dstf;
                    if (!aTrans) {
                        int r = i >> 3, c4 = i & 7;
                        src = Aq + (size_t)(row0 + r) * K + k0 + c4 * 4;
                        dstf = (uint32_t)(r * 36 + c4 * 4);
                    } else {
                        int c = i >> 4, n4 = i & 15;
                        src = Aq + (size_t)(k0 + c) * NA + row0 + n4 * 4;
                        dstf = (uint32_t)(c * 68 + n4 * 4);
                    }
                    asm volatile("cp.async.cg.shared.global [%0], [%1], 16;"
                                 :: "r"(sfb + dstf * 4), "l"(src));
                } else {
                    int i2 = i - 512;
                    int a = i2 / B_U4, j = i2 % B_U4;
                    int r = j >> 2, c8 = j & 3;
                    const __nv_bfloat16* src = (a ? Bl : Bh) + (size_t)(col0 + r) * K + k0 + c8 * 8;
                    uint32_t dst = stb + ((2*A_ELE + (uint32_t)a * B_ELE) + r * TG_STRIDE + c8 * 8) * 2;
                    asm volatile("cp.async.cg.shared.global [%0], [%1], 16;" :: "r"(dst), "l"(src));
                }
            }
        } else {
            #pragma unroll
            for (int l = 0; l < TOT_U4/256; l++) {
                int i = tid + l * 256;
                const __nv_bfloat16* src;
                int r, c8;
                uint32_t soff;
                if (i < 2*A_U4) {
                    int a = i / A_U4, j = i % A_U4;
                    r = j >> 2; c8 = j & 3;
                    src = (a ? Al : Ah) + (size_t)(row0 + r) * K;
                    soff = (uint32_t)a * A_ELE;
                } else {
                    int i2 = i - 2*A_U4;
                    int a = i2 / B_U4, j = i2 % B_U4;
                    r = j >> 2; c8 = j & 3;
                    src = (a ? Bl : Bh) + (size_t)(col0 + r) * K;
                    soff = 2*A_ELE + (uint32_t)a * B_ELE;
                }
                uint32_t dst = stb + (soff + r * TG_STRIDE + c8 * 8) * 2;
                const __nv_bfloat16* g = src + k0 + c8 * 8;
                asm volatile("cp.async.cg.shared.global [%0], [%1], 16;" :: "r"(dst), "l"(g));
            }
        }
        asm volatile("cp.async.commit_group;" ::: "memory");
    };

    auto convert = [&](int stage) {
        // quantize fp32 staging -> Ah/Al bf16 tiles (ldmatrix layout)
        const float* st = stagF + stage * STAGF;
        __nv_bfloat16* Ah_sm = sm + (uint32_t)stage * STAGE;
        __nv_bfloat16* Al_sm = Ah_sm + A_ELE;
        float scale = s_qp[0], zp = s_qp[1];
        if (!aTrans) {
            int c = tid & 31;
            int rg = tid >> 5;           // 0..7
            #pragma unroll
            for (int rr = 0; rr < 8; rr++) {
                int r = rg * 8 + rr;
                float t = st[r * 36 + c];
                float q = rintf(t / scale + zp);
                q = fminf(fmaxf(q, 0.f), 255.f);
                float d = (q - zp) * scale;
                if (doLoss) lpart += (double)log2f(510.f * fabsf(d) + 1.f);
                bf16split(d, &Ah_sm[r * TG_STRIDE + c], &Al_sm[r * TG_STRIDE + c]);
            }
        } else {
            int n = tid & 63;
            int cg = tid >> 6;           // 0..3
            #pragma unroll
            for (int e = 0; e < 8; e++) {
                int c = cg * 8 + e;
                float t = st[c * 68 + n];
                float q = rintf(t / scale + zp);
                q = fminf(fmaxf(q, 0.f), 255.f);
                float d = (q - zp) * scale;
                if (doLoss) lpart += (double)log2f(510.f * fabsf(d) + 1.f);
                bf16split(d, &Ah_sm[n * TG_STRIDE + c], &Al_sm[n * TG_STRIDE + c]);
            }
        }
    };

    auto compute = [&](int stage) {
        uint32_t stb = sb + (uint32_t)stage * STAGE * 2;
        uint32_t bA_h = stb, bA_l = stb + A_ELE*2;
        uint32_t bB_h = stb + 2*A_ELE*2, bB_l = stb + (2*A_ELE + B_ELE)*2;
        #pragma unroll
        for (int kk = 0; kk < 32; kk += 16) {
            uint32_t ah[2][4], al[2][4];
            #pragma unroll
            for (int mb = 0; mb < 2; mb++) {
                int r = wm + mb * 16 + (lane & 15);
                int c = kk + (lane >> 4) * 8;
                uint32_t off = (uint32_t)(r * TG_STRIDE + c) * 2;
                ldm_x4(ah[mb], bA_h + off);
                ldm_x4(al[mb], bA_l + off);
            }
            #pragma unroll
            for (int nb = 0; nb < NB16; nb++) {
                int r = wn + nb * 16 + ((lane >> 4) << 3) + (lane & 7);
                int c = kk + ((lane >> 3) & 1) * 8;
                uint32_t off = (uint32_t)(r * TG_STRIDE + c) * 2;
                uint32_t bh[4], bl[4];
                ldm_x4(bh, bB_h + off);
                ldm_x4(bl, bB_l + off);
                #pragma unroll
                for (int mb = 0; mb < 2; mb++) {
                    mma16816(acc[mb][2*nb+0], ah[mb], bh[0], bh[1]);
                    mma16816(acc[mb][2*nb+1], ah[mb], bh[2], bh[3]);
                    mma16816(acc[mb][2*nb+0], ah[mb], bl[0], bl[1]);
                    mma16816(acc[mb][2*nb+1], ah[mb], bl[2], bl[3]);
                    mma16816(acc[mb][2*nb+0], al[mb], bh[0], bh[1]);
                    mma16816(acc[mb][2*nb+1], al[mb], bh[2], bh[3]);
                }
            }
        }
    };

    int nch = K >> 5;
    issue(0, 0);
    for (int ck = 0; ck < nch; ck++) {
        if (ck + 1 < nch) {
            issue((ck + 1) & 1, (ck + 1) << 5);
            asm volatile("cp.async.wait_group 1;" ::: "memory");
        } else {
            asm volatile("cp.async.wait_group 0;" ::: "memory");
        }
        __syncthreads();
        if (Aq) { convert(ck & 1); __syncthreads(); }
        compute(ck & 1);
        __syncthreads();
    }

    if (doLoss) {
        sdl[tid] = lpart; __syncthreads();
        for (int s = 128; s > 0; s >>= 1) {
            if (tid < s) sdl[tid] += sdl[tid + s];
            __syncthreads();
        }
        if (tid == 0) atomicAdd(&g_loss, sdl[0]);
    }

    int g = lane >> 2, tg = lane & 3;

    if constexpr (BM == 128) {
        if (c0v) {
            float mn = 1e30f, mx = -1e30f;
            #pragma unroll
            for (int mb = 0; mb < 2; mb++) {
                #pragma unroll
                for (int ug = 0; ug < 2; ug++) {
                    int cb = col0 + wn + ug*32;
                    int u0 = ((cb >> 5) << 3) + 2*tg;
                    float iv[4], fv[4], gv[4], ov[4];
                    #pragma unroll
                    for (int e = 0; e < 4; e++) {
                        int co = 2*tg + (e & 1);
                        iv[e] = acc[mb][ug*4+0][e] + bias[cb + 0  + co];
                        fv[e] = acc[mb][ug*4+1][e] + bias[cb + 8  + co];
                        gv[e] = acc[mb][ug*4+2][e] + bias[cb + 16 + co];
                        ov[e] = acc[mb][ug*4+3][e] + bias[cb + 24 + co];
                    }
                    #pragma unroll
                    for (int half = 0; half < 2; half++) {
                        int row = row0 + wm + mb*16 + g + half*8;
                        float2 cc = *(const float2*)(c0v + (size_t)row*256 + u0);
                        float cin[2] = {cc.x, cc.y};
                        float hh[2], c2[2];
                        #pragma unroll
                        for (int e2 = 0; e2 < 2; e2++) {
                            int e = half*2 + e2;
                            float si = 1.f/(1.f+expf(-iv[e]));
                            float sf = 1.f/(1.f+expf(-fv[e]));
                            float so = 1.f/(1.f+expf(-ov[e]));
                            c2[e2] = sf * cin[e2] + si * tanhf(gv[e]);
                            hh[e2] = so * tanhf(c2[e2]);
                            mn = fminf(mn, hh[e2]); mx = fmaxf(mx, hh[e2]);
                        }
                        *(float2*)(hOut + (size_t)row*256 + u0) = make_float2(hh[0], hh[1]);
                        *(float2*)(cOut + (size_t)row*256 + u0) = make_float2(c2[0], c2[1]);
                    }
                }
            }
            __shared__ float smn2[256], smx2[256];
            smn2[tid] = mn; smx2[tid] = mx; __syncthreads();
            for (int s = 128; s > 0; s >>= 1) {
                if (tid < s) {
                    smn2[tid] = fminf(smn2[tid], smn2[tid+s]);
                    smx2[tid] = fmaxf(smx2[tid], smx2[tid+s]);
                }
                __syncthreads();
            }
            if (tid == 0) {
                int bid = blockIdx.y * gridDim.x + blockIdx.x;
                g_pmin[bid] = smn2[0]; g_pmax[bid] = smx2[0];
            }
            return;
        }
    }

    float cia[2][2] = {}, cja[2][2] = {};
    #pragma unroll
    for (int mb = 0; mb < 2; mb++) {
        #pragma unroll
        for (int n8 = 0; n8 < NB; n8++) {
            int row = row0 + wm + mb * 16 + g;
            int col = col0 + wn + n8 * 8 + 2 * tg;
            float b0 = bias ? bias[col]   : 0.f;
            float b1 = bias ? bias[col+1] : 0.f;
            float v00 = acc[mb][n8][0] + b0, v01 = acc[mb][n8][1] + b1;
            float v10 = acc[mb][n8][2] + b0, v11 = acc[mb][n8][3] + b1;
            if (Shi) {
                size_t d0 = (size_t)row * ldS + col;
                size_t d1 = (size_t)(row + 8) * ldS + col;
                bf16split(v00, &Shi[d0],   &Slo[d0]);
                bf16split(v01, &Shi[d0+1], &Slo[d0+1]);
                bf16split(v10, &Shi[d1],   &Slo[d1]);
                bf16split(v11, &Shi[d1+1], &Slo[d1+1]);
            }
            if (hwT) {
                hwT[(size_t)col*NA + row]         = v00;
                hwT[(size_t)(col+1)*NA + row]     = v01;
                hwT[(size_t)col*NA + row + 8]     = v10;
                hwT[(size_t)(col+1)*NA + row + 8] = v11;
            }
            if (aivec) {
                float a0 = aivec[col], a1 = aivec[col+1];
                float j0 = ajvec[col], j1 = ajvec[col+1];
                cia[mb][0] += v00*a0 + v01*a1;
                cia[mb][1] += v10*a0 + v11*a1;
                cja[mb][0] += v00*j0 + v01*j1;
                cja[mb][1] += v10*j0 + v11*j1;
            }
        }
    }
    if (aivec) {
        int hh = (col0 + wn) / Gh;
        #pragma unroll
        for (int mb = 0; mb < 2; mb++) {
            #pragma unroll
            for (int hf = 0; hf < 2; hf++) {
                float ci = cia[mb][hf], cj = cja[mb][hf];
                ci += __shfl_xor_sync(0xffffffffu, ci, 1);
                ci += __shfl_xor_sync(0xffffffffu, ci, 2);
                cj += __shfl_xor_sync(0xffffffffu, cj, 1);
                cj += __shfl_xor_sync(0xffffffffu, cj, 2);
                if (tg == 0) {
                    int row = row0 + wm + mb * 16 + g + hf * 8;
                    atomicAdd(&g_ci[hh*NA + row], ci);
                    atomicAdd(&g_cj[hh*NA + row], cj);
                }
            }
        }
    }
}

// ---------------- sortk: bitonic (warp-local inner stages) + scans + denom ----
__global__ void __launch_bounds__(1024)
sortk()
{
    extern __shared__ char sms[];
    float* key = (float*)sms;
    int*   idx = (int*)(key + NA);
    float* sA  = (float*)(idx + NA);
    float* sB  = sA + NA;
    __shared__ float wsum[32];
    int h = blockIdx.x;
    int tid = threadIdx.x, lane = tid & 31, warp = tid >> 5;

    for (int i = tid; i < NA; i += 1024) { key[i] = g_cj[h*NA + i]; idx[i] = i; }
    __syncthreads();
    for (int k = 2; k <= NA; k <<= 1) {
        int j = k >> 1;
        for (; j >= 128; j >>= 1) {
            #pragma unroll 2
            for (int p = tid; p < NA/2; p += 1024) {
                int i = ((p & ~(j-1)) << 1) | (p & (j-1));
                int il = i | j;
                bool up = ((i & k) == 0);
                float a = key[i], b = key[il];
                if (up ? (a > b) : (a < b)) {
                    key[i] = b; key[il] = a;
                    int tmp = idx[i]; idx[i] = idx[il]; idx[il] = tmp;
                }
            }
            __syncthreads();
        }
        for (; j >= 1; j >>= 1) {
            #pragma unroll 2
            for (int q = lane; q < 64; q += 32) {
                int p = (warp << 6) | q;
                int i = ((p & ~(j-1)) << 1) | (p & (j-1));
                int il = i | j;
                bool up = ((i & k) == 0);
                float a = key[i], b = key[il];
                if (up ? (a > b) : (a < b)) {
                    key[i] = b; key[il] = a;
                    int tmp = idx[i]; idx[i] = idx[il]; idx[il] = tmp;
                }
            }
            __syncwarp();
        }
        __syncthreads();
    }
    float cm = key[NA-1];

    int t0 = tid * 4;
    float kw0 = key[t0], kw1 = key[t0+1], kw2 = key[t0+2], kw3 = key[t0+3];
    float wB0 = expf(0.2f*(kw0-cm)), wB1 = expf(0.2f*(kw1-cm));
    float wB2 = expf(0.2f*(kw2-cm)), wB3 = expf(0.2f*(kw3-cm));
    float wA0 = expf(kw0-cm), wA1 = expf(kw1-cm), wA2 = expf(kw2-cm), wA3 = expf(kw3-cm);
    *(int4*)&g_sidx[h*NA + t0] = make_int4(idx[t0], idx[t0+1], idx[t0+2], idx[t0+3]);
    *(float4*)&g_wA[h*NA + t0] = make_float4(wA0, wA1, wA2, wA3);
    *(float4*)&g_wB[h*NA + t0] = make_float4(wB0, wB1, wB2, wB3);

    {
        float v0 = wB0, v1 = v0+wB1, v2 = v1+wB2, v3 = v2+wB3;
        float tot = v3, s = tot;
        #pragma unroll
        for (int o = 1; o < 32; o <<= 1) { float u = __shfl_up_sync(0xffffffffu, s, o); if (lane >= o) s += u; }
        if (lane == 31) wsum[warp] = s;
        __syncthreads();
        if (warp == 0) {
            float y = wsum[lane];
            #pragma unroll
            for (int o = 1; o < 32; o <<= 1) { float u = __shfl_up_sync(0xffffffffu, y, o); if (lane >= o) y += u; }
            wsum[lane] = y;
        }
        __syncthreads();
        float off = (warp ? wsum[warp-1] : 0.f) + (s - tot);
        sB[t0] = off+v0; sB[t0+1] = off+v1; sB[t0+2] = off+v2; sB[t0+3] = off+v3;
    }
    __syncthreads();
    {
        int rb = NA - 4 - t0;
        float a0 = expf(key[rb]-cm),   a1 = expf(key[rb+1]-cm);
        float a2 = expf(key[rb+2]-cm), a3 = expf(key[rb+3]-cm);
        float u0 = a3, u1 = u0+a2, u2 = u1+a1, u3 = u2+a0;
        float tot = u3, s = tot;
        #pragma unroll
        for (int o = 1; o < 32; o <<= 1) { float u = __shfl_up_sync(0xffffffffu, s, o); if (lane >= o) s += u; }
        if (lane == 31) wsum[warp] = s;
        __syncthreads();
        if (warp == 0) {
            float y = wsum[lane];
            #pragma unroll
            for (int o = 1; o < 32; o <<= 1) { float u = __shfl_up_sync(0xffffffffu, y, o); if (lane >= o) y += u; }
            wsum[lane] = y;
        }
        __syncthreads();
        float off = (warp ? wsum[warp-1] : 0.f) + (s - tot);
        sA[rb] = off+u3; sA[rb+1] = off+u2; sA[rb+2] = off+u1; sA[rb+3] = off+u0;
    }
    __syncthreads();

    for (int l = 0; l < 4; l++) {
        int n = tid + l*1024;
        float cin = g_ci[h*NA + n];
        float t = -cin;
        int lo = 0, hi = NA;
        while (lo < hi) {
            int mid = (lo + hi) >> 1;
            if (key[mid] <= t) lo = mid + 1; else hi = mid;
        }
        float r = expf(0.8f * (cin + cm));
        float A = (lo < NA) ? sA[lo]     : 0.f;
        float B = (lo > 0)  ? sB[lo - 1] : 0.f;
        g_kcount[h*NA + n] = lo;
        g_rn[h*NA + n]     = r;
        g_invd[h*NA + n]   = 1.f / (r*A + B);
        g_ci[h*NA + n] = 0.f;
        g_cj[h*NA + n] = 0.f;
    }
}

// ---------------- scomb: 512 threads, per-column scan + transposed output ----
__global__ void __launch_bounds__(512)
scomb(const float* __restrict__ bias, float* __restrict__ outT,
      int G, int do_elu, int do_mm)
{
    __shared__ float s_pre[NA];
    __shared__ float s_suf[NA];
    __shared__ float wsum[16];
    int c = blockIdx.x;
    int h = c / G;
    int tid = threadIdx.x, lane = tid & 31, warp = tid >> 5;
    int t0 = tid * 8;
    const float* xrow = g_hWT + (size_t)c * NA;

    {
        int4 iva = *(const int4*)&g_sidx[h*NA + t0];
        int4 ivb = *(const int4*)&g_sidx[h*NA + t0 + 4];
        float4 wa = *(const float4*)&g_wB[h*NA + t0];
        float4 wb = *(const float4*)&g_wB[h*NA + t0 + 4];
        float v[8];
        float run = wa.x * xrow[iva.x];              v[0] = run;
        run += wa.y * xrow[iva.y];                   v[1] = run;
        run += wa.z * xrow[iva.z];                   v[2] = run;
        run += wa.w * xrow[iva.w];                   v[3] = run;
        run += wb.x * xrow[ivb.x];                   v[4] = run;
        run += wb.y * xrow[ivb.y];                   v[5] = run;
        run += wb.z * xrow[ivb.z];                   v[6] = run;
        run += wb.w * xrow[ivb.w];                   v[7] = run;
        float tot = run, s = tot;
        #pragma unroll
        for (int o = 1; o < 32; o <<= 1) { float u = __shfl_up_sync(0xffffffffu, s, o); if (lane >= o) s += u; }
        if (lane == 31) wsum[warp] = s;
        __syncthreads();
        if (warp == 0 && lane < 16) {
            float y = wsum[lane];
            #pragma unroll
            for (int o = 1; o < 16; o <<= 1) { float u = __shfl_up_sync(0xffffu, y, o); if (lane >= o) y += u; }
            wsum[lane] = y;
        }
        __syncthreads();
        float off = (warp ? wsum[warp-1] : 0.f) + (s - tot);
        #pragma unroll
        for (int e = 0; e < 8; e++) s_pre[t0+e] = off + v[e];
    }
    __syncthreads();
    {
        int rb = NA - 8 - t0;
        int4 iva = *(const int4*)&g_sidx[h*NA + rb];
        int4 ivb = *(const int4*)&g_sidx[h*NA + rb + 4];
        float4 wa = *(const float4*)&g_wA[h*NA + rb];
        float4 wb = *(const float4*)&g_wA[h*NA + rb + 4];
        float xs[8] = { xrow[iva.x], xrow[iva.y], xrow[iva.z], xrow[iva.w],
                        xrow[ivb.x], xrow[ivb.y], xrow[ivb.z], xrow[ivb.w] };
        float ws[8] = { wa.x, wa.y, wa.z, wa.w, wb.x, wb.y, wb.z, wb.w };
        float u[8];
        float run = ws[7]*xs[7];  u[0] = run;
        #pragma unroll
        for (int e = 1; e < 8; e++) { run += ws[7-e]*xs[7-e]; u[e] = run; }
        float tot = run, s = tot;
        #pragma unroll
        for (int o = 1; o < 32; o <<= 1) { float uu = __shfl_up_sync(0xffffffffu, s, o); if (lane >= o) s += uu; }
        if (lane == 31) wsum[warp] = s;
        __syncthreads();
        if (warp == 0 && lane < 16) {
            float y = wsum[lane];
            #pragma unroll
            for (int o = 1; o < 16; o <<= 1) { float uu = __shfl_up_sync(0xffffu, y, o); if (lane >= o) y += uu; }
            wsum[lane] = y;
        }
        __syncthreads();
        float off = (warp ? wsum[warp-1] : 0.f) + (s - tot);
        #pragma unroll
        for (int e = 0; e < 8; e++) s_suf[rb + 7 - e] = off + u[e];
    }
    __syncthreads();

    float bv = bias[c];
    float mn = 1e30f, mx = -1e30f;
    #pragma unroll
    for (int l = 0; l < 8; l++) {
        int n = tid + l*512;
        int k = g_kcount[h*NA + n];
        float r = g_rn[h*NA + n];
        float invd = g_invd[h*NA + n];
        float Av = (k < NA) ? s_suf[k]     : 0.f;
        float Bv = (k > 0)  ? s_pre[k - 1] : 0.f;
        float val = (r*Av + Bv) * invd + bv;
        if (do_elu) val = (val > 0.f) ? val : expm1f(val);
        mn = fminf(mn, val); mx = fmaxf(mx, val);
        outT[(size_t)c*NA + n] = val;
    }
    if (do_mm) {
        __shared__ float smn[512], smx[512];
        smn[tid] = mn; smx[tid] = mx; __syncthreads();
        for (int s = 256; s > 0; s >>= 1) {
            if (tid < s) {
                smn[tid] = fminf(smn[tid], smn[tid+s]);
                smx[tid] = fmaxf(smx[tid], smx[tid+s]);
            }
            __syncthreads();
        }
        if (tid == 0) { g_pmin[c] = smn[0]; g_pmax[c] = smx[0]; }
    }
}

// ---------------- fused policy + value head (+ loss write) ----------------
__global__ void __launch_bounds__(256)
policyk(const float* __restrict__ A0, const float* __restrict__ A1T,
        const float* __restrict__ Wa, const float* __restrict__ ba,
        const float* __restrict__ Wv, const float* __restrict__ bv,
        float* __restrict__ out_logp, float* __restrict__ out_value,
        float* __restrict__ out_loss)
{
    if (blockIdx.x == 0 && threadIdx.x == 0) out_loss[0] = (float)g_loss;
    __shared__ float As[16][68];
    __shared__ float Bs[16][68];
    __shared__ float Ss[64][65];
    int tid = threadIdx.x;
    int tx = tid % 16, ty = tid / 16;
    int row0 = blockIdx.x * 64;
    float acc[4][4] = {};
    float vacc = 0.f;

    for (int k0 = 0; k0 < 512; k0 += 16) {
        if (k0 < 256) {
            int lin = tid * 4;
            int m = lin >> 4, kk = lin & 15;
            float4 v = *(const float4*)&A0[(size_t)(row0+m)*256 + k0 + kk];
            As[kk+0][m] = v.x; As[kk+1][m] = v.y; As[kk+2][m] = v.z; As[kk+3][m] = v.w;
        } else {
            int lin = tid * 4;
            int kk = lin >> 6, m4 = lin & 63;
            float4 v = *(const float4*)&A1T[(size_t)(k0-256+kk)*NA + row0 + m4];
            *(float4*)&As[kk][m4] = v;
        }
        {
            int lin = tid * 4;
            int kk = lin >> 6, n = lin & 63;
            *(float4*)&Bs[kk][n] = *(const float4*)&Wa[(size_t)(k0+kk)*64 + n];
        }
        __syncthreads();
        #pragma unroll
        for (int kk = 0; kk < 16; kk++) {
            float a[4], bb[4];
            #pragma unroll
            for (int i = 0; i < 4; i++) a[i] = As[kk][ty*4+i];
            #pragma unroll
            for (int j = 0; j < 4; j++) bb[j] = Bs[kk][tx*4+j];
            #pragma unroll
            for (int i = 0; i < 4; i++)
                #pragma unroll
                for (int j = 0; j < 4; j++)
                    acc[i][j] = fmaf(a[i], bb[j], acc[i][j]);
        }
        if (tid < 64) {
            #pragma unroll
            for (int kk = 0; kk < 16; kk++)
                vacc = fmaf(As[kk][tid], Wv[k0+kk], vacc);
        }
        __syncthreads();
    }
    if (tid < 64) out_value[row0 + tid] = vacc + bv[0];

    #pragma unroll
    for (int i = 0; i < 4; i++)
        #pragma unroll
        for (int j = 0; j < 4; j++)
            Ss[ty*4+i][tx*4+j] = acc[i][j] + ba[tx*4+j];
    __syncthreads();

    int row = tid >> 2, quad = tid & 3;
    float m = -1e30f;
    #pragma unroll
    for (int c = 0; c < 16; c++) m = fmaxf(m, Ss[row][quad*16 + c]);
    m = fmaxf(m, __shfl_xor_sync(0xffffffffu, m, 1));
    m = fmaxf(m, __shfl_xor_sync(0xffffffffu, m, 2));
    float s = 0.f;
    #pragma unroll
    for (int c = 0; c < 16; c++) s += expf(Ss[row][quad*16 + c] - m);
    s += __shfl_xor_sync(0xffffffffu, s, 1);
    s += __shfl_xor_sync(0xffffffffu, s, 2);
    float lse = m + logf(s);
    #pragma unroll
    for (int c = 0; c < 16; c++)
        out_logp[(size_t)(row0+row)*64 + quad*16 + c] = Ss[row][quad*16 + c] - lse;
}

// ---------------- host ----------------
extern "C" void kernel_launch(void* const* d_in, const int* in_sizes, int n_in,
                              void* d_out, int out_size)
{
    const float* obs  = (const float*)d_in[0];
    const float* h0   = (const float*)d_in[1];
    const float* c0   = (const float*)d_in[2];
    const float* Wobs = (const float*)d_in[3];
    const float* bobs = (const float*)d_in[4];
    const float* Wih  = (const float*)d_in[5];
    const float* Whh  = (const float*)d_in[6];
    const float* bih  = (const float*)d_in[7];
    const float* bhh  = (const float*)d_in[8];
    const float* W1   = (const float*)d_in[9];
    const float* ai1  = (const float*)d_in[10];
    const float* aj1  = (const float*)d_in[11];
    const float* b1   = (const float*)d_in[12];
    const float* W2   = (const float*)d_in[13];
    const float* ai2  = (const float*)d_in[14];
    const float* aj2  = (const float*)d_in[15];
    const float* b2   = (const float*)d_in[16];
    const float* Wv   = (const float*)d_in[17];
    const float* bv   = (const float*)d_in[18];
    const float* Wa   = (const float*)d_in[19];
    const float* ba   = (const float*)d_in[20];

    float* out       = (float*)d_out;
    float* out_logp  = out;
    float* out_value = out + NA*ACT;
    float* out_h     = out_value + NA;
    float* out_c     = out_h + NA*HD;
    float* out_loss  = out_c + NA*HD;

    float *p_hWT, *p_commT, *p_bsum;
    __nv_bfloat16 *p_Ah, *p_Al, *p_A2h, *p_A2l;
    __nv_bfloat16 *p_B0h, *p_B0l, *p_Bgh, *p_Bgl, *p_B1h, *p_B1l, *p_B2h, *p_B2l;
    cudaGetSymbolAddress((void**)&p_hWT,    g_hWT);
    cudaGetSymbolAddress((void**)&p_commT,  g_commT);
    cudaGetSymbolAddress((void**)&p_bsum,   g_bsum);
    cudaGetSymbolAddress((void**)&p_Ah,     g_Ah);
    cudaGetSymbolAddress((void**)&p_Al,     g_Al);
    cudaGetSymbolAddress((void**)&p_A2h,    g_A2h);
    cudaGetSymbolAddress((void**)&p_A2l,    g_A2l);
    cudaGetSymbolAddress((void**)&p_B0h,    g_B0h);
    cudaGetSymbolAddress((void**)&p_B0l,    g_B0l);
    cudaGetSymbolAddress((void**)&p_Bgh,    g_Bgh);
    cudaGetSymbolAddress((void**)&p_Bgl,    g_Bgl);
    cudaGetSymbolAddress((void**)&p_B1h,    g_B1h);
    cudaGetSymbolAddress((void**)&p_B1l,    g_B1l);
    cudaGetSymbolAddress((void**)&p_B2h,    g_B2h);
    cudaGetSymbolAddress((void**)&p_B2l,    g_B2l);

    const int SM128 = (2*(2*128*TG_STRIDE + 2*128*TG_STRIDE)) * 2;
    const int SM64  = (2*(2*64*TG_STRIDE  + 2*128*TG_STRIDE)) * 2 + 2*STAGF*4;
    const int SMSORT = NA * 16;
    cudaFuncSetAttribute((const void*)tgemm<128>, cudaFuncAttributeMaxDynamicSharedMemorySize, SM128);
    cudaFuncSetAttribute((const void*)tgemm<64>,  cudaFuncAttributeMaxDynamicSharedMemorySize, SM64);
    cudaFuncSetAttribute((const void*)sortk,      cudaFuncAttributeMaxDynamicSharedMemorySize, SMSORT);

    // 1. prep
    wprep<<<WQ8/256, 256>>>(obs, h0, Wobs, Wih, Whh, W1, W2, bih, bhh, bobs);
    // 2. weight-product GEMM -> Bg cols 0..255 (split output)
    tgemm<64><<<dim3(2, 16), 256, SM64>>>(p_A2h, p_A2l, p_B0h, p_B0l, nullptr,
                                          p_Bgh, p_Bgl, 512,
                                          nullptr, nullptr, nullptr, 0,
                                          nullptr, nullptr, nullptr,
                                          nullptr, 0, 0, 256, 256);
    // 3. gates GEMM ([obs|h0] @ Bg^T) + fused LSTM -> out_h, out_c, minmax[256]
    tgemm<128><<<dim3(8, 32), 256, SM128>>>(p_Ah, p_Al, p_Bgh, p_Bgl, p_bsum,
                                            nullptr, nullptr, 0,
                                            nullptr, nullptr, nullptr, 0,
                                            c0, out_h, out_c,
                                            nullptr, 0, 0, 1024, 512);
    // 4. GAT1 projection: fused quant(h) on load -> hWT + ci/cj + loss
    tgemm<64><<<dim3(2, 64), 256, SM64>>>(nullptr, nullptr, p_B1h, p_B1l, nullptr,
                                          nullptr, nullptr, 0,
                                          p_hWT, ai1, aj1, 64,
                                          nullptr, nullptr, nullptr,
                                          out_h, 0, 256, 256, 256);
    // 5-6. GAT1 attention
    sortk<<<4, 1024, SMSORT>>>();
    scomb<<<256, 512>>>(b1, p_commT, 64, 1, 1);
    // 7. GAT2 projection: fused quant(comm1T) transposed on load -> hWT + ci/cj + loss
    tgemm<64><<<dim3(2, 64), 256, SM64>>>(nullptr, nullptr, p_B2h, p_B2l, nullptr,
                                          nullptr, nullptr, 0,
                                          p_hWT, ai2, aj2, 256,
                                          nullptr, nullptr, nullptr,
                                          p_commT, 1, 256, 256, 256);
    // 8-9. GAT2 attention
    sortk<<<1, 1024, SMSORT>>>();
    scomb<<<256, 512>>>(b2, p_commT, 256, 0, 0);
    // 10. fused policy + value heads + loss
    policyk<<<NA/64, 256>>>(out_h, p_commT, Wa, ba, Wv, bv, out_logp, out_value, out_loss);
}

// round 12
// speedup vs baseline: 1.0362x; 1.0362x over previous
#include <cuda_runtime.h>
#include <cuda_bf16.h>
#include <math.h>
#include <stdint.h>

#define NA   4096
#define HD   256
#define HG   256
#define ACT  64
#define MMB  1024

// ---------------- device scratch ----------------
__device__ float g_hWT[HG*NA];
__device__ float g_commT[HG*NA];
__device__ float g_bsum[4*HD];
__device__ __nv_bfloat16 g_Ah[NA*512];       // [obs | h0] gates A (ld 512)
__device__ __nv_bfloat16 g_Al[NA*512];
__device__ __nv_bfloat16 g_A2h[NA*256];      // Wih perm split (wgemm A) / quant splits
__device__ __nv_bfloat16 g_A2l[NA*256];
__device__ __nv_bfloat16 g_B0h[256*256], g_B0l[256*256];    // Wobs raw
__device__ __nv_bfloat16 g_Bgh[1024*512], g_Bgl[1024*512];  // [Wobs*Wih^T | Whh] perm
__device__ __nv_bfloat16 g_B1h[256*256], g_B1l[256*256];    // W1^T
__device__ __nv_bfloat16 g_B2h[256*256], g_B2l[256*256];    // W2^T
__device__ float g_ci[4*NA];
__device__ float g_cj[4*NA];
__device__ int   g_kcount[4*NA];
__device__ int   g_sidx[4*NA];
__device__ float g_wA[4*NA];
__device__ float g_wB[4*NA];
__device__ float g_rn[4*NA];
__device__ float g_invd[4*NA];
__device__ float g_pmin[MMB];
__device__ float g_pmax[MMB];
__device__ double g_loss;

__device__ __forceinline__ void bf16split(float x, __nv_bfloat16* hi, __nv_bfloat16* lo) {
    __nv_bfloat16 h = __float2bfloat16(x);
    *hi = h;
    *lo = __float2bfloat16(x - __bfloat162float(h));
}

// ---------------- fused prep ----------------
#define WQ0 (NA*256)
#define WQ1 (WQ0 + NA*256)
#define WQ2 (WQ1 + 65536)
#define WQ3 (WQ2 + 262144)
#define WQ4 (WQ3 + 262144)
#define WQ5 (WQ4 + 65536)
#define WQ6 (WQ5 + 65536)
#define WQ7 (WQ6 + 16384)
#define WQ8 (WQ7 + 32768)
__global__ void wprep(const float* __restrict__ obs, const float* __restrict__ h0,
                      const float* __restrict__ Wobs,
                      const float* __restrict__ Wih, const float* __restrict__ Whh,
                      const float* __restrict__ W1, const float* __restrict__ W2,
                      const float* __restrict__ bih, const float* __restrict__ bhh,
                      const float* __restrict__ bobs)
{
    int idx = blockIdx.x*256 + threadIdx.x;
    if (idx == 0) g_loss = 0.0;
    if (idx < WQ0) {
        int n = idx >> 8, k = idx & 255;
        int d = n*512 + k;
        bf16split(obs[idx], &g_Ah[d], &g_Al[d]);
    } else if (idx < WQ1) {
        int j = idx - WQ0;
        int n = j >> 8, k = j & 255;
        int d = n*512 + 256 + k;
        bf16split(h0[j], &g_Ah[d], &g_Al[d]);
    } else if (idx < WQ2) {
        int j = idx - WQ1;
        bf16split(Wobs[j], &g_B0h[j], &g_B0l[j]);
    } else if (idx < WQ3) {
        int j = idx - WQ2;
        int r = j >> 8, k = j & 255;
        int G = (r >> 3) & 3;
        int u = ((r >> 5) << 3) | (r & 7);
        bf16split(Wih[(G*256 + u)*256 + k], &g_A2h[j], &g_A2l[j]);
    } else if (idx < WQ4) {
        int j = idx - WQ3;
        int r = j >> 8, k = j & 255;
        int G = (r >> 3) & 3;
        int u = ((r >> 5) << 3) | (r & 7);
        int d = r*512 + 256 + k;
        bf16split(Whh[(G*256 + u)*256 + k], &g_Bgh[d], &g_Bgl[d]);
    } else if (idx < WQ5) {
        int j = idx - WQ4;
        int n = j >> 8, k = j & 255;
        bf16split(W1[k*256 + n], &g_B1h[j], &g_B1l[j]);
    } else if (idx < WQ6) {
        int j = idx - WQ5;
        int n = j >> 8, k = j & 255;
        bf16split(W2[k*256 + n], &g_B2h[j], &g_B2l[j]);
    } else if (idx < WQ7) {
        int j = idx - WQ6;
        g_ci[j] = 0.f; g_cj[j] = 0.f;
    } else if (idx < WQ8) {
        int t = idx - WQ7;
        int r = t >> 5, lane = t & 31;
        int G = (r >> 3) & 3;
        int u = ((r >> 5) << 3) | (r & 7);
        int orow = G*256 + u;
        float s = 0.f;
        #pragma unroll
        for (int k = lane; k < 256; k += 32)
            s = fmaf(bobs[k], Wih[orow*256 + k], s);
        for (int o = 16; o > 0; o >>= 1) s += __shfl_down_sync(0xffffffffu, s, o);
        if (lane == 0) g_bsum[r] = s + bih[orow] + bhh[orow];
    }
}

// ---------------- mma.sync helpers ----------------
__device__ __forceinline__ uint32_t cvta_sm(const void* p) {
    uint32_t a;
    asm("{ .reg .u64 t; cvta.to.shared.u64 t, %1; cvt.u32.u64 %0, t; }" : "=r"(a) : "l"(p));
    return a;
}
__device__ __forceinline__ void ldm_x4(uint32_t (&d)[4], uint32_t addr) {
    asm volatile("ldmatrix.sync.aligned.m8n8.x4.shared.b16 {%0,%1,%2,%3}, [%4];"
        : "=r"(d[0]), "=r"(d[1]), "=r"(d[2]), "=r"(d[3]) : "r"(addr));
}
__device__ __forceinline__ void mma16816(float (&c)[4], const uint32_t (&a)[4],
                                         uint32_t b0, uint32_t b1) {
    asm volatile("mma.sync.aligned.m16n8k16.row.col.f32.bf16.bf16.f32 "
        "{%0,%1,%2,%3},{%4,%5,%6,%7},{%8,%9},{%0,%1,%2,%3};"
        : "+f"(c[0]), "+f"(c[1]), "+f"(c[2]), "+f"(c[3])
        : "r"(a[0]), "r"(a[1]), "r"(a[2]), "r"(a[3]), "r"(b0), "r"(b1));
}

// ---------------- split-bf16 tensor GEMM, cp.async 3-stage pipeline ----------
#define TG_STRIDE 40
// per-stage bf16 elems / bytes (shared with host smem sizing)
#define TG_STAGE_ELE(BM)   (2*(BM)*TG_STRIDE + 2*128*TG_STRIDE)
#define TG_SMEM_BYTES(BM)  (3 * TG_STAGE_ELE(BM) * 2)

template<int BM>
__global__ void __launch_bounds__(256, BM == 64 ? 2 : 1)
tgemm(const __nv_bfloat16* __restrict__ Ah, const __nv_bfloat16* __restrict__ Al,
      const __nv_bfloat16* __restrict__ Bh, const __nv_bfloat16* __restrict__ Bl,
      const float* __restrict__ bias,
      __nv_bfloat16* __restrict__ Shi, __nv_bfloat16* __restrict__ Slo, int ldS,
      float* __restrict__ hwT, const float* __restrict__ aivec,
      const float* __restrict__ ajvec, int Gh,
      const float* __restrict__ c0v, float* __restrict__ hOut, float* __restrict__ cOut,
      int N, int K)
{
    constexpr int A_ELE = BM * TG_STRIDE;
    constexpr int B_ELE = 128 * TG_STRIDE;
    constexpr int STAGE = 2*A_ELE + 2*B_ELE;
    static_assert(STAGE == TG_STAGE_ELE(BM), "stage size mismatch");
    constexpr int NWM  = BM / 32;
    constexpr int WN   = 128 / (8 / NWM);
    constexpr int NB16 = WN / 16;
    constexpr int NB   = WN / 8;
    constexpr int A_U4 = BM * 4;
    constexpr int B_U4 = 512;
    constexpr int TOT_U4 = 2*A_U4 + 2*B_U4;

    extern __shared__ __nv_bfloat16 sm[];
    int tid = threadIdx.x, lane = tid & 31, wid = tid >> 5;
    int col0 = blockIdx.x * 128, row0 = blockIdx.y * BM;
    int wm = (wid % NWM) * 32, wn = (wid / NWM) * WN;
    uint32_t sb = cvta_sm(sm);

    float acc[2][NB][4] = {};

    auto issue = [&](int stage, int k0) {
        uint32_t stb = sb + (uint32_t)stage * STAGE * 2;
        #pragma unroll
        for (int l = 0; l < TOT_U4/256; l++) {
            int i = tid + l * 256;
            const __nv_bfloat16* src;
            int r, c8;
            uint32_t soff;
            if (i < 2*A_U4) {
                int a = i / A_U4, j = i % A_U4;
                r = j >> 2; c8 = j & 3;
                src = (a ? Al : Ah) + (size_t)(row0 + r) * K;
                soff = (uint32_t)a * A_ELE;
            } else {
                int i2 = i - 2*A_U4;
                int a = i2 / B_U4, j = i2 % B_U4;
                r = j >> 2; c8 = j & 3;
                src = (a ? Bl : Bh) + (size_t)(col0 + r) * K;
                soff = 2*A_ELE + (uint32_t)a * B_ELE;
            }
            uint32_t dst = stb + (soff + r * TG_STRIDE + c8 * 8) * 2;
            const __nv_bfloat16* g = src + k0 + c8 * 8;
            asm volatile("cp.async.cg.shared.global [%0], [%1], 16;" :: "r"(dst), "l"(g));
        }
        asm volatile("cp.async.commit_group;" ::: "memory");
    };

    auto compute = [&](int stage) {
        uint32_t stb = sb + (uint32_t)stage * STAGE * 2;
        uint32_t bA_h = stb, bA_l = stb + A_ELE*2;
        uint32_t bB_h = stb + 2*A_ELE*2, bB_l = stb + (2*A_ELE + B_ELE)*2;
        #pragma unroll
        for (int kk = 0; kk < 32; kk += 16) {
            uint32_t ah[2][4], al[2][4];
            #pragma unroll
            for (int mb = 0; mb < 2; mb++) {
                int r = wm + mb * 16 + (lane & 15);
                int c = kk + (lane >> 4) * 8;
                uint32_t off = (uint32_t)(r * TG_STRIDE + c) * 2;
                ldm_x4(ah[mb], bA_h + off);
                ldm_x4(al[mb], bA_l + off);
            }
            #pragma unroll
            for (int nb = 0; nb < NB16; nb++) {
                int r = wn + nb * 16 + ((lane >> 4) << 3) + (lane & 7);
                int c = kk + ((lane >> 3) & 1) * 8;
                uint32_t off = (uint32_t)(r * TG_STRIDE + c) * 2;
                uint32_t bh[4], bl[4];
                ldm_x4(bh, bB_h + off);
                ldm_x4(bl, bB_l + off);
                #pragma unroll
                for (int mb = 0; mb < 2; mb++) {
                    mma16816(acc[mb][2*nb+0], ah[mb], bh[0], bh[1]);
                    mma16816(acc[mb][2*nb+1], ah[mb], bh[2], bh[3]);
                    mma16816(acc[mb][2*nb+0], ah[mb], bl[0], bl[1]);
                    mma16816(acc[mb][2*nb+1], ah[mb], bl[2], bl[3]);
                    mma16816(acc[mb][2*nb+0], al[mb], bh[0], bh[1]);
                    mma16816(acc[mb][2*nb+1], al[mb], bh[2], bh[3]);
                }
            }
        }
    };

    // 3-stage pipeline: keep two chunks in flight
    int nch = K >> 5;
    issue(0, 0);
    if (nch > 1) issue(1, 32);
    for (int ck = 0; ck < nch; ck++) {
        if (ck + 2 < nch) {
            issue((ck + 2) % 3, (ck + 2) << 5);
            asm volatile("cp.async.wait_group 2;" ::: "memory");
        } else if (ck + 1 < nch) {
            asm volatile("cp.async.wait_group 1;" ::: "memory");
        } else {
            asm volatile("cp.async.wait_group 0;" ::: "memory");
        }
        __syncthreads();
        compute(ck % 3);
        __syncthreads();
    }

    int g = lane >> 2, tg = lane & 3;

    if constexpr (BM == 128) {
        if (c0v) {
            float mn = 1e30f, mx = -1e30f;
            #pragma unroll
            for (int mb = 0; mb < 2; mb++) {
                #pragma unroll
                for (int ug = 0; ug < 2; ug++) {
                    int cb = col0 + wn + ug*32;
                    int u0 = ((cb >> 5) << 3) + 2*tg;
                    float iv[4], fv[4], gv[4], ov[4];
                    #pragma unroll
                    for (int e = 0; e < 4; e++) {
                        int co = 2*tg + (e & 1);
                        iv[e] = acc[mb][ug*4+0][e] + bias[cb + 0  + co];
                        fv[e] = acc[mb][ug*4+1][e] + bias[cb + 8  + co];
                        gv[e] = acc[mb][ug*4+2][e] + bias[cb + 16 + co];
                        ov[e] = acc[mb][ug*4+3][e] + bias[cb + 24 + co];
                    }
                    #pragma unroll
                    for (int half = 0; half < 2; half++) {
                        int row = row0 + wm + mb*16 + g + half*8;
                        float2 cc = *(const float2*)(c0v + (size_t)row*256 + u0);
                        float cin[2] = {cc.x, cc.y};
                        float hh[2], c2[2];
                        #pragma unroll
                        for (int e2 = 0; e2 < 2; e2++) {
                            int e = half*2 + e2;
                            float si = 1.f/(1.f+expf(-iv[e]));
                            float sf = 1.f/(1.f+expf(-fv[e]));
                            float so = 1.f/(1.f+expf(-ov[e]));
                            c2[e2] = sf * cin[e2] + si * tanhf(gv[e]);
                            hh[e2] = so * tanhf(c2[e2]);
                            mn = fminf(mn, hh[e2]); mx = fmaxf(mx, hh[e2]);
                        }
                        *(float2*)(hOut + (size_t)row*256 + u0) = make_float2(hh[0], hh[1]);
                        *(float2*)(cOut + (size_t)row*256 + u0) = make_float2(c2[0], c2[1]);
                    }
                }
            }
            __shared__ float smn[256], smx[256];
            smn[tid] = mn; smx[tid] = mx; __syncthreads();
            for (int s = 128; s > 0; s >>= 1) {
                if (tid < s) {
                    smn[tid] = fminf(smn[tid], smn[tid+s]);
                    smx[tid] = fmaxf(smx[tid], smx[tid+s]);
                }
                __syncthreads();
            }
            if (tid == 0) {
                int bid = blockIdx.y * gridDim.x + blockIdx.x;
                g_pmin[bid] = smn[0]; g_pmax[bid] = smx[0];
            }
            return;
        }
    }

    float cia[2][2] = {}, cja[2][2] = {};
    #pragma unroll
    for (int mb = 0; mb < 2; mb++) {
        #pragma unroll
        for (int n8 = 0; n8 < NB; n8++) {
            int row = row0 + wm + mb * 16 + g;
            int col = col0 + wn + n8 * 8 + 2 * tg;
            float b0 = bias ? bias[col]   : 0.f;
            float b1 = bias ? bias[col+1] : 0.f;
            float v00 = acc[mb][n8][0] + b0, v01 = acc[mb][n8][1] + b1;
            float v10 = acc[mb][n8][2] + b0, v11 = acc[mb][n8][3] + b1;
            if (Shi) {
                size_t d0 = (size_t)row * ldS + col;
                size_t d1 = (size_t)(row + 8) * ldS + col;
                bf16split(v00, &Shi[d0],   &Slo[d0]);
                bf16split(v01, &Shi[d0+1], &Slo[d0+1]);
                bf16split(v10, &Shi[d1],   &Slo[d1]);
                bf16split(v11, &Shi[d1+1], &Slo[d1+1]);
            }
            if (hwT) {
                hwT[(size_t)col*NA + row]         = v00;
                hwT[(size_t)(col+1)*NA + row]     = v01;
                hwT[(size_t)col*NA + row + 8]     = v10;
                hwT[(size_t)(col+1)*NA + row + 8] = v11;
            }
            if (aivec) {
                float a0 = aivec[col], a1 = aivec[col+1];
                float j0 = ajvec[col], j1 = ajvec[col+1];
                cia[mb][0] += v00*a0 + v01*a1;
                cia[mb][1] += v10*a0 + v11*a1;
                cja[mb][0] += v00*j0 + v01*j1;
                cja[mb][1] += v10*j0 + v11*j1;
            }
        }
    }
    if (aivec) {
        int hh = (col0 + wn) / Gh;
        #pragma unroll
        for (int mb = 0; mb < 2; mb++) {
            #pragma unroll
            for (int hf = 0; hf < 2; hf++) {
                float ci = cia[mb][hf], cj = cja[mb][hf];
                ci += __shfl_xor_sync(0xffffffffu, ci, 1);
                ci += __shfl_xor_sync(0xffffffffu, ci, 2);
                cj += __shfl_xor_sync(0xffffffffu, cj, 1);
                cj += __shfl_xor_sync(0xffffffffu, cj, 2);
                if (tg == 0) {
                    int row = row0 + wm + mb * 16 + g + hf * 8;
                    atomicAdd(&g_ci[hh*NA + row], ci);
                    atomicAdd(&g_cj[hh*NA + row], cj);
                }
            }
        }
    }
}

// ---------------- fake-quant A: 256 blocks, 16 elem/thread -------------------
__global__ void quantA(const float* __restrict__ x,
                       __nv_bfloat16* __restrict__ hi, __nv_bfloat16* __restrict__ lo,
                       int npart)
{
    __shared__ float smn[256], smx[256];
    __shared__ float sparam[2];
    float mn = 1e30f, mx = -1e30f;
    for (int i = threadIdx.x; i < npart; i += 256) {
        mn = fminf(mn, g_pmin[i]); mx = fmaxf(mx, g_pmax[i]);
    }
    smn[threadIdx.x] = mn; smx[threadIdx.x] = mx; __syncthreads();
    for (int s = 128; s > 0; s >>= 1) {
        if (threadIdx.x < s) {
            smn[threadIdx.x] = fminf(smn[threadIdx.x], smn[threadIdx.x+s]);
            smx[threadIdx.x] = fmaxf(smx[threadIdx.x], smx[threadIdx.x+s]);
        }
        __syncthreads();
    }
    if (threadIdx.x == 0) {
        float a = smn[0], b = smx[0];
        if (a == b) { a -= 0.01f; b += 0.01f; }
        float scale = (b - a) / 255.f;
        sparam[0] = scale;
        sparam[1] = rintf(-a / scale);
    }
    __syncthreads();
    float scale = sparam[0], zp = sparam[1];

    double part = 0.0;
    #pragma unroll
    for (int l = 0; l < 4; l++) {
        int i = blockIdx.x*256 + threadIdx.x + l*65536;
        float4 t = ((const float4*)x)[i];
        float ts[4] = {t.x, t.y, t.z, t.w};
        float ds[4];
        #pragma unroll
        for (int q = 0; q < 4; q++) {
            float r = rintf(ts[q]/scale + zp);
            r = fminf(fmaxf(r, 0.f), 255.f);
            float d = (r - zp) * scale;
            ds[q] = d;
            part += (double)log2f(510.f * fabsf(d) + 1.f);
        }
        __nv_bfloat162 h01, h23, l01, l23;
        __nv_bfloat16 hh, ll;
        bf16split(ds[0], &hh, &ll); h01.x = hh; l01.x = ll;
        bf16split(ds[1], &hh, &ll); h01.y = hh; l01.y = ll;
        bf16split(ds[2], &hh, &ll); h23.x = hh; l23.x = ll;
        bf16split(ds[3], &hh, &ll); h23.y = hh; l23.y = ll;
        ((__nv_bfloat162*)hi)[i*2]   = h01;
        ((__nv_bfloat162*)hi)[i*2+1] = h23;
        ((__nv_bfloat162*)lo)[i*2]   = l01;
        ((__nv_bfloat162*)lo)[i*2+1] = l23;
    }
    __shared__ double sd[256];
    sd[threadIdx.x] = part; __syncthreads();
    for (int s = 128; s > 0; s >>= 1) { if (threadIdx.x < s) sd[threadIdx.x] += sd[threadIdx.x+s]; __syncthreads(); }
    if (threadIdx.x == 0) atomicAdd(&g_loss, sd[0]);
}

// ---------------- fake-quant T: 4 transposed 32x32 tiles per block -----------
__global__ void quantT(const float* __restrict__ inT,
                       __nv_bfloat16* __restrict__ hi, __nv_bfloat16* __restrict__ lo,
                       int npart)
{
    __shared__ float tile[32][33];
    __shared__ float smn[256], smx[256];
    __shared__ float sparam[2];
    int tx = threadIdx.x, ty = threadIdx.y;
    int tid = ty*32 + tx;

    float mn = (tid < npart) ? g_pmin[tid] : 1e30f;
    float mx = (tid < npart) ? g_pmax[tid] : -1e30f;
    smn[tid] = mn; smx[tid] = mx; __syncthreads();
    for (int s = 128; s > 0; s >>= 1) {
        if (tid < s) {
            smn[tid] = fminf(smn[tid], smn[tid+s]);
            smx[tid] = fmaxf(smx[tid], smx[tid+s]);
        }
        __syncthreads();
    }
    if (tid == 0) {
        float a = smn[0], b = smx[0];
        if (a == b) { a -= 0.01f; b += 0.01f; }
        float scale = (b - a) / 255.f;
        sparam[0] = scale;
        sparam[1] = rintf(-a / scale);
    }
    __syncthreads();
    float scale = sparam[0], zp = sparam[1];

    int c0 = blockIdx.y * 32;
    double part = 0.0;
    #pragma unroll 1
    for (int nt = 0; nt < 4; nt++) {
        int n0 = blockIdx.x * 128 + nt * 32;
        for (int cc = ty; cc < 32; cc += 8) {
            float t = inT[(size_t)(c0+cc)*NA + n0 + tx];
            float r = rintf(t/scale + zp);
            r = fminf(fmaxf(r, 0.f), 255.f);
            float d = (r - zp) * scale;
            tile[cc][tx] = d;
            part += (double)log2f(510.f * fabsf(d) + 1.f);
        }
        __syncthreads();
        for (int nn = ty; nn < 32; nn += 8) {
            float d = tile[tx][nn];
            size_t o = (size_t)(n0+nn)*256 + c0 + tx;
            bf16split(d, &hi[o], &lo[o]);
        }
        __syncthreads();
    }
    __shared__ double sd[256];
    sd[tid] = part; __syncthreads();
    for (int s = 128; s > 0; s >>= 1) { if (tid < s) sd[tid] += sd[tid+s]; __syncthreads(); }
    if (tid == 0) atomicAdd(&g_loss, sd[0]);
}

// ---------------- sortk: bitonic (warp-local inner stages) + scans + denom ----
__global__ void __launch_bounds__(1024)
sortk()
{
    extern __shared__ char sms[];
    float* key = (float*)sms;
    int*   idx = (int*)(key + NA);
    float* sA  = (float*)(idx + NA);
    float* sB  = sA + NA;
    __shared__ float wsum[32];
    int h = blockIdx.x;
    int tid = threadIdx.x, lane = tid & 31, warp = tid >> 5;

    for (int i = tid; i < NA; i += 1024) { key[i] = g_cj[h*NA + i]; idx[i] = i; }
    __syncthreads();
    for (int k = 2; k <= NA; k <<= 1) {
        int j = k >> 1;
        for (; j >= 128; j >>= 1) {
            #pragma unroll 2
            for (int p = tid; p < NA/2; p += 1024) {
                int i = ((p & ~(j-1)) << 1) | (p & (j-1));
                int il = i | j;
                bool up = ((i & k) == 0);
                float a = key[i], b = key[il];
                if (up ? (a > b) : (a < b)) {
                    key[i] = b; key[il] = a;
                    int tmp = idx[i]; idx[i] = idx[il]; idx[il] = tmp;
                }
            }
            __syncthreads();
        }
        for (; j >= 1; j >>= 1) {
            #pragma unroll 2
            for (int q = lane; q < 64; q += 32) {
                int p = (warp << 6) | q;
                int i = ((p & ~(j-1)) << 1) | (p & (j-1));
                int il = i | j;
                bool up = ((i & k) == 0);
                float a = key[i], b = key[il];
                if (up ? (a > b) : (a < b)) {
                    key[i] = b; key[il] = a;
                    int tmp = idx[i]; idx[i] = idx[il]; idx[il] = tmp;
                }
            }
            __syncwarp();
        }
        __syncthreads();
    }
    float cm = key[NA-1];

    int t0 = tid * 4;
    float kw0 = key[t0], kw1 = key[t0+1], kw2 = key[t0+2], kw3 = key[t0+3];
    float wB0 = expf(0.2f*(kw0-cm)), wB1 = expf(0.2f*(kw1-cm));
    float wB2 = expf(0.2f*(kw2-cm)), wB3 = expf(0.2f*(kw3-cm));
    float wA0 = expf(kw0-cm), wA1 = expf(kw1-cm), wA2 = expf(kw2-cm), wA3 = expf(kw3-cm);
    *(int4*)&g_sidx[h*NA + t0] = make_int4(idx[t0], idx[t0+1], idx[t0+2], idx[t0+3]);
    *(float4*)&g_wA[h*NA + t0] = make_float4(wA0, wA1, wA2, wA3);
    *(float4*)&g_wB[h*NA + t0] = make_float4(wB0, wB1, wB2, wB3);

    {
        float v0 = wB0, v1 = v0+wB1, v2 = v1+wB2, v3 = v2+wB3;
        float tot = v3, s = tot;
        #pragma unroll
        for (int o = 1; o < 32; o <<= 1) { float u = __shfl_up_sync(0xffffffffu, s, o); if (lane >= o) s += u; }
        if (lane == 31) wsum[warp] = s;
        __syncthreads();
        if (warp == 0) {
            float y = wsum[lane];
            #pragma unroll
            for (int o = 1; o < 32; o <<= 1) { float u = __shfl_up_sync(0xffffffffu, y, o); if (lane >= o) y += u; }
            wsum[lane] = y;
        }
        __syncthreads();
        float off = (warp ? wsum[warp-1] : 0.f) + (s - tot);
        sB[t0] = off+v0; sB[t0+1] = off+v1; sB[t0+2] = off+v2; sB[t0+3] = off+v3;
    }
    __syncthreads();
    {
        int rb = NA - 4 - t0;
        float a0 = expf(key[rb]-cm),   a1 = expf(key[rb+1]-cm);
        float a2 = expf(key[rb+2]-cm), a3 = expf(key[rb+3]-cm);
        float u0 = a3, u1 = u0+a2, u2 = u1+a1, u3 = u2+a0;
        float tot = u3, s = tot;
        #pragma unroll
        for (int o = 1; o < 32; o <<= 1) { float u = __shfl_up_sync(0xffffffffu, s, o); if (lane >= o) s += u; }
        if (lane == 31) wsum[warp] = s;
        __syncthreads();
        if (warp == 0) {
            float y = wsum[lane];
            #pragma unroll
            for (int o = 1; o < 32; o <<= 1) { float u = __shfl_up_sync(0xffffffffu, y, o); if (lane >= o) y += u; }
            wsum[lane] = y;
        }
        __syncthreads();
        float off = (warp ? wsum[warp-1] : 0.f) + (s - tot);
        sA[rb] = off+u3; sA[rb+1] = off+u2; sA[rb+2] = off+u1; sA[rb+3] = off+u0;
    }
    __syncthreads();

    for (int l = 0; l < 4; l++) {
        int n = tid + l*1024;
        float cin = g_ci[h*NA + n];
        float t = -cin;
        int lo = 0, hi = NA;
        while (lo < hi) {
            int mid = (lo + hi) >> 1;
            if (key[mid] <= t) lo = mid + 1; else hi = mid;
        }
        float r = expf(0.8f * (cin + cm));
        float A = (lo < NA) ? sA[lo]     : 0.f;
        float B = (lo > 0)  ? sB[lo - 1] : 0.f;
        g_kcount[h*NA + n] = lo;
        g_rn[h*NA + n]     = r;
        g_invd[h*NA + n]   = 1.f / (r*A + B);
        g_ci[h*NA + n] = 0.f;
        g_cj[h*NA + n] = 0.f;
    }
}

// ---------------- scomb: 512 threads, per-column scan + transposed output ----
__global__ void __launch_bounds__(512)
scomb(const float* __restrict__ bias, float* __restrict__ outT,
      int G, int do_elu, int do_mm)
{
    __shared__ float s_pre[NA];
    __shared__ float s_suf[NA];
    __shared__ float wsum[16];
    int c = blockIdx.x;
    int h = c / G;
    int tid = threadIdx.x, lane = tid & 31, warp = tid >> 5;
    int t0 = tid * 8;
    const float* xrow = g_hWT + (size_t)c * NA;

    {
        int4 iva = *(const int4*)&g_sidx[h*NA + t0];
        int4 ivb = *(const int4*)&g_sidx[h*NA + t0 + 4];
        float4 wa = *(const float4*)&g_wB[h*NA + t0];
        float4 wb = *(const float4*)&g_wB[h*NA + t0 + 4];
        float v[8];
        float run = wa.x * xrow[iva.x];              v[0] = run;
        run += wa.y * xrow[iva.y];                   v[1] = run;
        run += wa.z * xrow[iva.z];                   v[2] = run;
        run += wa.w * xrow[iva.w];                   v[3] = run;
        run += wb.x * xrow[ivb.x];                   v[4] = run;
        run += wb.y * xrow[ivb.y];                   v[5] = run;
        run += wb.z * xrow[ivb.z];                   v[6] = run;
        run += wb.w * xrow[ivb.w];                   v[7] = run;
        float tot = run, s = tot;
        #pragma unroll
        for (int o = 1; o < 32; o <<= 1) { float u = __shfl_up_sync(0xffffffffu, s, o); if (lane >= o) s += u; }
        if (lane == 31) wsum[warp] = s;
        __syncthreads();
        if (warp == 0 && lane < 16) {
            float y = wsum[lane];
            #pragma unroll
            for (int o = 1; o < 16; o <<= 1) { float u = __shfl_up_sync(0xffffu, y, o); if (lane >= o) y += u; }
            wsum[lane] = y;
        }
        __syncthreads();
        float off = (warp ? wsum[warp-1] : 0.f) + (s - tot);
        #pragma unroll
        for (int e = 0; e < 8; e++) s_pre[t0+e] = off + v[e];
    }
    __syncthreads();
    {
        int rb = NA - 8 - t0;
        int4 iva = *(const int4*)&g_sidx[h*NA + rb];
        int4 ivb = *(const int4*)&g_sidx[h*NA + rb + 4];
        float4 wa = *(const float4*)&g_wA[h*NA + rb];
        float4 wb = *(const float4*)&g_wA[h*NA + rb + 4];
        float xs[8] = { xrow[iva.x], xrow[iva.y], xrow[iva.z], xrow[iva.w],
                        xrow[ivb.x], xrow[ivb.y], xrow[ivb.z], xrow[ivb.w] };
        float ws[8] = { wa.x, wa.y, wa.z, wa.w, wb.x, wb.y, wb.z, wb.w };
        float u[8];
        float run = ws[7]*xs[7];  u[0] = run;
        #pragma unroll
        for (int e = 1; e < 8; e++) { run += ws[7-e]*xs[7-e]; u[e] = run; }
        float tot = run, s = tot;
        #pragma unroll
        for (int o = 1; o < 32; o <<= 1) { float uu = __shfl_up_sync(0xffffffffu, s, o); if (lane >= o) s += uu; }
        if (lane == 31) wsum[warp] = s;
        __syncthreads();
        if (warp == 0 && lane < 16) {
            float y = wsum[lane];
            #pragma unroll
            for (int o = 1; o < 16; o <<= 1) { float uu = __shfl_up_sync(0xffffu, y, o); if (lane >= o) y += uu; }
            wsum[lane] = y;
        }
        __syncthreads();
        float off = (warp ? wsum[warp-1] : 0.f) + (s - tot);
        #pragma unroll
        for (int e = 0; e < 8; e++) s_suf[rb + 7 - e] = off + u[e];
    }
    __syncthreads();

    float bv = bias[c];
    float mn = 1e30f, mx = -1e30f;
    #pragma unroll
    for (int l = 0; l < 8; l++) {
        int n = tid + l*512;
        int k = g_kcount[h*NA + n];
        float r = g_rn[h*NA + n];
        float invd = g_invd[h*NA + n];
        float Av = (k < NA) ? s_suf[k]     : 0.f;
        float Bv = (k > 0)  ? s_pre[k - 1] : 0.f;
        float val = (r*Av + Bv) * invd + bv;
        if (do_elu) val = (val > 0.f) ? val : expm1f(val);
        mn = fminf(mn, val); mx = fmaxf(mx, val);
        outT[(size_t)c*NA + n] = val;
    }
    if (do_mm) {
        __shared__ float smn[512], smx[512];
        smn[tid] = mn; smx[tid] = mx; __syncthreads();
        for (int s = 256; s > 0; s >>= 1) {
            if (tid < s) {
                smn[tid] = fminf(smn[tid], smn[tid+s]);
                smx[tid] = fmaxf(smx[tid], smx[tid+s]);
            }
            __syncthreads();
        }
        if (tid == 0) { g_pmin[c] = smn[0]; g_pmax[c] = smx[0]; }
    }
}

// ---------------- fused policy + value head (+ loss write) ----------------
__global__ void __launch_bounds__(256)
policyk(const float* __restrict__ A0, const float* __restrict__ A1T,
        const float* __restrict__ Wa, const float* __restrict__ ba,
        const float* __restrict__ Wv, const float* __restrict__ bv,
        float* __restrict__ out_logp, float* __restrict__ out_value,
        float* __restrict__ out_loss)
{
    if (blockIdx.x == 0 && threadIdx.x == 0) out_loss[0] = (float)g_loss;
    __shared__ float As[16][68];
    __shared__ float Bs[16][68];
    __shared__ float Ss[64][65];
    int tid = threadIdx.x;
    int tx = tid % 16, ty = tid / 16;
    int row0 = blockIdx.x * 64;
    float acc[4][4] = {};
    float vacc = 0.f;

    for (int k0 = 0; k0 < 512; k0 += 16) {
        if (k0 < 256) {
            int lin = tid * 4;
            int m = lin >> 4, kk = lin & 15;
            float4 v = *(const float4*)&A0[(size_t)(row0+m)*256 + k0 + kk];
            As[kk+0][m] = v.x; As[kk+1][m] = v.y; As[kk+2][m] = v.z; As[kk+3][m] = v.w;
        } else {
            int lin = tid * 4;
            int kk = lin >> 6, m4 = lin & 63;
            float4 v = *(const float4*)&A1T[(size_t)(k0-256+kk)*NA + row0 + m4];
            *(float4*)&As[kk][m4] = v;
        }
        {
            int lin = tid * 4;
            int kk = lin >> 6, n = lin & 63;
            *(float4*)&Bs[kk][n] = *(const float4*)&Wa[(size_t)(k0+kk)*64 + n];
        }
        __syncthreads();
        #pragma unroll
        for (int kk = 0; kk < 16; kk++) {
            float a[4], bb[4];
            #pragma unroll
            for (int i = 0; i < 4; i++) a[i] = As[kk][ty*4+i];
            #pragma unroll
            for (int j = 0; j < 4; j++) bb[j] = Bs[kk][tx*4+j];
            #pragma unroll
            for (int i = 0; i < 4; i++)
                #pragma unroll
                for (int j = 0; j < 4; j++)
                    acc[i][j] = fmaf(a[i], bb[j], acc[i][j]);
        }
        if (tid < 64) {
            #pragma unroll
            for (int kk = 0; kk < 16; kk++)
                vacc = fmaf(As[kk][tid], Wv[k0+kk], vacc);
        }
        __syncthreads();
    }
    if (tid < 64) out_value[row0 + tid] = vacc + bv[0];

    #pragma unroll
    for (int i = 0; i < 4; i++)
        #pragma unroll
        for (int j = 0; j < 4; j++)
            Ss[ty*4+i][tx*4+j] = acc[i][j] + ba[tx*4+j];
    __syncthreads();

    int row = tid >> 2, quad = tid & 3;
    float m = -1e30f;
    #pragma unroll
    for (int c = 0; c < 16; c++) m = fmaxf(m, Ss[row][quad*16 + c]);
    m = fmaxf(m, __shfl_xor_sync(0xffffffffu, m, 1));
    m = fmaxf(m, __shfl_xor_sync(0xffffffffu, m, 2));
    float s = 0.f;
    #pragma unroll
    for (int c = 0; c < 16; c++) s += expf(Ss[row][quad*16 + c] - m);
    s += __shfl_xor_sync(0xffffffffu, s, 1);
    s += __shfl_xor_sync(0xffffffffu, s, 2);
    float lse = m + logf(s);
    #pragma unroll
    for (int c = 0; c < 16; c++)
        out_logp[(size_t)(row0+row)*64 + quad*16 + c] = Ss[row][quad*16 + c] - lse;
}

// ---------------- host ----------------
extern "C" void kernel_launch(void* const* d_in, const int* in_sizes, int n_in,
                              void* d_out, int out_size)
{
    const float* obs  = (const float*)d_in[0];
    const float* h0   = (const float*)d_in[1];
    const float* c0   = (const float*)d_in[2];
    const float* Wobs = (const float*)d_in[3];
    const float* bobs = (const float*)d_in[4];
    const float* Wih  = (const float*)d_in[5];
    const float* Whh  = (const float*)d_in[6];
    const float* bih  = (const float*)d_in[7];
    const float* bhh  = (const float*)d_in[8];
    const float* W1   = (const float*)d_in[9];
    const float* ai1  = (const float*)d_in[10];
    const float* aj1  = (const float*)d_in[11];
    const float* b1   = (const float*)d_in[12];
    const float* W2   = (const float*)d_in[13];
    const float* ai2  = (const float*)d_in[14];
    const float* aj2  = (const float*)d_in[15];
    const float* b2   = (const float*)d_in[16];
    const float* Wv   = (const float*)d_in[17];
    const float* bv   = (const float*)d_in[18];
    const float* Wa   = (const float*)d_in[19];
    const float* ba   = (const float*)d_in[20];

    float* out       = (float*)d_out;
    float* out_logp  = out;
    float* out_value = out + NA*ACT;
    float* out_h     = out_value + NA;
    float* out_c     = out_h + NA*HD;
    float* out_loss  = out_c + NA*HD;

    float *p_hWT, *p_commT, *p_bsum;
    __nv_bfloat16 *p_Ah, *p_Al, *p_A2h, *p_A2l;
    __nv_bfloat16 *p_B0h, *p_B0l, *p_Bgh, *p_Bgl, *p_B1h, *p_B1l, *p_B2h, *p_B2l;
    cudaGetSymbolAddress((void**)&p_hWT,    g_hWT);
    cudaGetSymbolAddress((void**)&p_commT,  g_commT);
    cudaGetSymbolAddress((void**)&p_bsum,   g_bsum);
    cudaGetSymbolAddress((void**)&p_Ah,     g_Ah);
    cudaGetSymbolAddress((void**)&p_Al,     g_Al);
    cudaGetSymbolAddress((void**)&p_A2h,    g_A2h);
    cudaGetSymbolAddress((void**)&p_A2l,    g_A2l);
    cudaGetSymbolAddress((void**)&p_B0h,    g_B0h);
    cudaGetSymbolAddress((void**)&p_B0l,    g_B0l);
    cudaGetSymbolAddress((void**)&p_Bgh,    g_Bgh);
    cudaGetSymbolAddress((void**)&p_Bgl,    g_Bgl);
    cudaGetSymbolAddress((void**)&p_B1h,    g_B1h);
    cudaGetSymbolAddress((void**)&p_B1l,    g_B1l);
    cudaGetSymbolAddress((void**)&p_B2h,    g_B2h);
    cudaGetSymbolAddress((void**)&p_B2l,    g_B2l);

    // 3-stage pipeline smem — derived from the SAME formula the kernel uses
    const int SM128 = TG_SMEM_BYTES(128);   // 3 * (2*128*40 + 2*128*40) * 2 = 122880
    const int SM64  = TG_SMEM_BYTES(64);    // 3 * (2*64*40  + 2*128*40) * 2 =  92160
    const int SMSORT = NA * 16;
    cudaFuncSetAttribute((const void*)tgemm<128>, cudaFuncAttributeMaxDynamicSharedMemorySize, SM128);
    cudaFuncSetAttribute((const void*)tgemm<64>,  cudaFuncAttributeMaxDynamicSharedMemorySize, SM64);
    cudaFuncSetAttribute((const void*)sortk,      cudaFuncAttributeMaxDynamicSharedMemorySize, SMSORT);

    // 1. prep
    wprep<<<WQ8/256, 256>>>(obs, h0, Wobs, Wih, Whh, W1, W2, bih, bhh, bobs);
    // 2. weight-product GEMM -> Bg cols 0..255 (split output)
    tgemm<64><<<dim3(2, 16), 256, SM64>>>(p_A2h, p_A2l, p_B0h, p_B0l, nullptr,
                                          p_Bgh, p_Bgl, 512,
                                          nullptr, nullptr, nullptr, 0,
                                          nullptr, nullptr, nullptr, 256, 256);
    // 3. gates GEMM ([obs|h0] @ Bg^T) + fused LSTM -> out_h, out_c, minmax[256]
    tgemm<128><<<dim3(8, 32), 256, SM128>>>(p_Ah, p_Al, p_Bgh, p_Bgl, p_bsum,
                                            nullptr, nullptr, 0,
                                            nullptr, nullptr, nullptr, 0,
                                            c0, out_h, out_c, 1024, 512);
    // 4. quant #1 -> splits into A2 (row-major [n][256])
    quantA<<<256, 256>>>(out_h, p_A2h, p_A2l, 256);
    // 5. GAT1 projection -> hWT + fused ci/cj
    tgemm<64><<<dim3(2, 64), 256, SM64>>>(p_A2h, p_A2l, p_B1h, p_B1l, nullptr,
                                          nullptr, nullptr, 0,
                                          p_hWT, ai1, aj1, 64,
                                          nullptr, nullptr, nullptr, 256, 256);
    // 6-7. GAT1 attention
    sortk<<<4, 1024, SMSORT>>>();
    scomb<<<256, 512>>>(b1, p_commT, 64, 1, 1);
    // 8. quant #2 (transposed input)
    quantT<<<dim3(NA/128, 8), dim3(32, 8)>>>(p_commT, p_A2h, p_A2l, 256);
    // 9. GAT2 projection
    tgemm<64><<<dim3(2, 64), 256, SM64>>>(p_A2h, p_A2l, p_B2h, p_B2l, nullptr,
                                          nullptr, nullptr, 0,
                                          p_hWT, ai2, aj2, 256,
                                          nullptr, nullptr, nullptr, 256, 256);
    // 10-11. GAT2 attention
    sortk<<<1, 1024, SMSORT>>>();
    scomb<<<256, 512>>>(b2, p_commT, 256, 0, 0);
    // 12. fused policy + value heads + loss
    policyk<<<NA/64, 256>>>(out_h, p_commT, Wa, ba, Wv, bv, out_logp, out_value, out_loss);
}

// round 13
// speedup vs baseline: 1.0488x; 1.0121x over previous
#include <cuda_runtime.h>
#include <cuda_bf16.h>
#include <math.h>
#include <stdint.h>

#define NA   4096
#define HD   256
#define HG   256
#define ACT  64
#define MMB  1024

// ---------------- device scratch ----------------
__device__ float g_hWT[HG*NA];
__device__ float g_commT[HG*NA];
__device__ float g_bsum[4*HD];
__device__ __nv_bfloat16 g_Ah[NA*512];
__device__ __nv_bfloat16 g_Al[NA*512];
__device__ __nv_bfloat16 g_A2h[NA*256];
__device__ __nv_bfloat16 g_A2l[NA*256];
__device__ __nv_bfloat16 g_B0h[256*256], g_B0l[256*256];
__device__ __nv_bfloat16 g_Bgh[1024*512], g_Bgl[1024*512];
__device__ __nv_bfloat16 g_B1h[256*256], g_B1l[256*256];
__device__ __nv_bfloat16 g_B2h[256*256], g_B2l[256*256];
__device__ float g_ci[4*NA];
__device__ float g_cj[4*NA];
__device__ int   g_kcount[4*NA];
__device__ int   g_sidx[4*NA];
__device__ float g_wA[4*NA];
__device__ float g_wB[4*NA];
__device__ float g_rn[4*NA];
__device__ float g_invd[4*NA];
__device__ float g_pmin[MMB];
__device__ float g_pmax[MMB];
__device__ float g_loss;

__device__ __forceinline__ void bf16split(float x, __nv_bfloat16* hi, __nv_bfloat16* lo) {
    __nv_bfloat16 h = __float2bfloat16(x);
    *hi = h;
    *lo = __float2bfloat16(x - __bfloat162float(h));
}
__device__ __forceinline__ float fsig(float x) { return 1.f / (1.f + __expf(-x)); }
__device__ __forceinline__ float ftanh(float x) {
    float ax = fabsf(x);
    float e = __expf(-2.f * ax);
    float t = (1.f - e) / (1.f + e);
    return copysignf(t, x);
}

// ---------------- fused prep ----------------
#define WQ0 (NA*256)
#define WQ1 (WQ0 + NA*256)
#define WQ2 (WQ1 + 65536)
#define WQ3 (WQ2 + 262144)
#define WQ4 (WQ3 + 262144)
#define WQ5 (WQ4 + 65536)
#define WQ6 (WQ5 + 65536)
#define WQ7 (WQ6 + 16384)
#define WQ8 (WQ7 + 32768)
__global__ void wprep(const float* __restrict__ obs, const float* __restrict__ h0,
                      const float* __restrict__ Wobs,
                      const float* __restrict__ Wih, const float* __restrict__ Whh,
                      const float* __restrict__ W1, const float* __restrict__ W2,
                      const float* __restrict__ bih, const float* __restrict__ bhh,
                      const float* __restrict__ bobs)
{
    int idx = blockIdx.x*256 + threadIdx.x;
    if (idx == 0) g_loss = 0.f;
    if (idx < WQ0) {
        int n = idx >> 8, k = idx & 255;
        int d = n*512 + k;
        bf16split(obs[idx], &g_Ah[d], &g_Al[d]);
    } else if (idx < WQ1) {
        int j = idx - WQ0;
        int n = j >> 8, k = j & 255;
        int d = n*512 + 256 + k;
        bf16split(h0[j], &g_Ah[d], &g_Al[d]);
    } else if (idx < WQ2) {
        int j = idx - WQ1;
        bf16split(Wobs[j], &g_B0h[j], &g_B0l[j]);
    } else if (idx < WQ3) {
        int j = idx - WQ2;
        int r = j >> 8, k = j & 255;
        int G = (r >> 3) & 3;
        int u = ((r >> 5) << 3) | (r & 7);
        bf16split(Wih[(G*256 + u)*256 + k], &g_A2h[j], &g_A2l[j]);
    } else if (idx < WQ4) {
        int j = idx - WQ3;
        int r = j >> 8, k = j & 255;
        int G = (r >> 3) & 3;
        int u = ((r >> 5) << 3) | (r & 7);
        int d = r*512 + 256 + k;
        bf16split(Whh[(G*256 + u)*256 + k], &g_Bgh[d], &g_Bgl[d]);
    } else if (idx < WQ5) {
        int j = idx - WQ4;
        int n = j >> 8, k = j & 255;
        bf16split(W1[k*256 + n], &g_B1h[j], &g_B1l[j]);
    } else if (idx < WQ6) {
        int j = idx - WQ5;
        int n = j >> 8, k = j & 255;
        bf16split(W2[k*256 + n], &g_B2h[j], &g_B2l[j]);
    } else if (idx < WQ7) {
        int j = idx - WQ6;
        g_ci[j] = 0.f; g_cj[j] = 0.f;
    } else if (idx < WQ8) {
        int t = idx - WQ7;
        int r = t >> 5, lane = t & 31;
        int G = (r >> 3) & 3;
        int u = ((r >> 5) << 3) | (r & 7);
        int orow = G*256 + u;
        float s = 0.f;
        #pragma unroll
        for (int k = lane; k < 256; k += 32)
            s = fmaf(bobs[k], Wih[orow*256 + k], s);
        for (int o = 16; o > 0; o >>= 1) s += __shfl_down_sync(0xffffffffu, s, o);
        if (lane == 0) g_bsum[r] = s + bih[orow] + bhh[orow];
    }
}

// ---------------- mma.sync helpers ----------------
__device__ __forceinline__ uint32_t cvta_sm(const void* p) {
    uint32_t a;
    asm("{ .reg .u64 t; cvta.to.shared.u64 t, %1; cvt.u32.u64 %0, t; }" : "=r"(a) : "l"(p));
    return a;
}
__device__ __forceinline__ void ldm_x4(uint32_t (&d)[4], uint32_t addr) {
    asm volatile("ldmatrix.sync.aligned.m8n8.x4.shared.b16 {%0,%1,%2,%3}, [%4];"
        : "=r"(d[0]), "=r"(d[1]), "=r"(d[2]), "=r"(d[3]) : "r"(addr));
}
__device__ __forceinline__ void mma16816(float (&c)[4], const uint32_t (&a)[4],
                                         uint32_t b0, uint32_t b1) {
    asm volatile("mma.sync.aligned.m16n8k16.row.col.f32.bf16.bf16.f32 "
        "{%0,%1,%2,%3},{%4,%5,%6,%7},{%8,%9},{%0,%1,%2,%3};"
        : "+f"(c[0]), "+f"(c[1]), "+f"(c[2]), "+f"(c[3])
        : "r"(a[0]), "r"(a[1]), "r"(a[2]), "r"(a[3]), "r"(b0), "r"(b1));
}

// ---------------- split-bf16 tensor GEMM, cp.async 3-stage pipeline ----------
#define TG_STRIDE 40
#define TG_STAGE_ELE(BM)   (2*(BM)*TG_STRIDE + 2*128*TG_STRIDE)
#define TG_SMEM_BYTES(BM)  (3 * TG_STAGE_ELE(BM) * 2)

template<int BM>
__global__ void __launch_bounds__(256, BM == 64 ? 2 : 1)
tgemm(const __nv_bfloat16* __restrict__ Ah, const __nv_bfloat16* __restrict__ Al,
      const __nv_bfloat16* __restrict__ Bh, const __nv_bfloat16* __restrict__ Bl,
      const float* __restrict__ bias,
      __nv_bfloat16* __restrict__ Shi, __nv_bfloat16* __restrict__ Slo, int ldS,
      float* __restrict__ hwT, const float* __restrict__ aivec,
      const float* __restrict__ ajvec, int Gh,
      const float* __restrict__ c0v, float* __restrict__ hOut, float* __restrict__ cOut,
      int N, int K)
{
    constexpr int A_ELE = BM * TG_STRIDE;
    constexpr int B_ELE = 128 * TG_STRIDE;
    constexpr int STAGE = 2*A_ELE + 2*B_ELE;
    static_assert(STAGE == TG_STAGE_ELE(BM), "stage size mismatch");
    constexpr int NWM  = BM / 32;
    constexpr int WN   = 128 / (8 / NWM);
    constexpr int NB16 = WN / 16;
    constexpr int NB   = WN / 8;
    constexpr int A_U4 = BM * 4;
    constexpr int B_U4 = 512;
    constexpr int TOT_U4 = 2*A_U4 + 2*B_U4;

    extern __shared__ __nv_bfloat16 sm[];
    int tid = threadIdx.x, lane = tid & 31, wid = tid >> 5;
    int col0 = blockIdx.x * 128, row0 = blockIdx.y * BM;
    int wm = (wid % NWM) * 32, wn = (wid / NWM) * WN;
    uint32_t sb = cvta_sm(sm);

    float acc[2][NB][4] = {};

    auto issue = [&](int stage, int k0) {
        uint32_t stb = sb + (uint32_t)stage * STAGE * 2;
        #pragma unroll
        for (int l = 0; l < TOT_U4/256; l++) {
            int i = tid + l * 256;
            const __nv_bfloat16* src;
            int r, c8;
            uint32_t soff;
            if (i < 2*A_U4) {
                int a = i / A_U4, j = i % A_U4;
                r = j >> 2; c8 = j & 3;
                src = (a ? Al : Ah) + (size_t)(row0 + r) * K;
                soff = (uint32_t)a * A_ELE;
            } else {
                int i2 = i - 2*A_U4;
                int a = i2 / B_U4, j = i2 % B_U4;
                r = j >> 2; c8 = j & 3;
                src = (a ? Bl : Bh) + (size_t)(col0 + r) * K;
                soff = 2*A_ELE + (uint32_t)a * B_ELE;
            }
            uint32_t dst = stb + (soff + r * TG_STRIDE + c8 * 8) * 2;
            const __nv_bfloat16* g = src + k0 + c8 * 8;
            asm volatile("cp.async.cg.shared.global [%0], [%1], 16;" :: "r"(dst), "l"(g));
        }
        asm volatile("cp.async.commit_group;" ::: "memory");
    };

    auto compute = [&](int stage) {
        uint32_t stb = sb + (uint32_t)stage * STAGE * 2;
        uint32_t bA_h = stb, bA_l = stb + A_ELE*2;
        uint32_t bB_h = stb + 2*A_ELE*2, bB_l = stb + (2*A_ELE + B_ELE)*2;
        #pragma unroll
        for (int kk = 0; kk < 32; kk += 16) {
            uint32_t ah[2][4], al[2][4];
            #pragma unroll
            for (int mb = 0; mb < 2; mb++) {
                int r = wm + mb * 16 + (lane & 15);
                int c = kk + (lane >> 4) * 8;
                uint32_t off = (uint32_t)(r * TG_STRIDE + c) * 2;
                ldm_x4(ah[mb], bA_h + off);
                ldm_x4(al[mb], bA_l + off);
            }
            #pragma unroll
            for (int nb = 0; nb < NB16; nb++) {
                int r = wn + nb * 16 + ((lane >> 4) << 3) + (lane & 7);
                int c = kk + ((lane >> 3) & 1) * 8;
                uint32_t off = (uint32_t)(r * TG_STRIDE + c) * 2;
                uint32_t bh[4], bl[4];
                ldm_x4(bh, bB_h + off);
                ldm_x4(bl, bB_l + off);
                #pragma unroll
                for (int mb = 0; mb < 2; mb++) {
                    mma16816(acc[mb][2*nb+0], ah[mb], bh[0], bh[1]);
                    mma16816(acc[mb][2*nb+1], ah[mb], bh[2], bh[3]);
                    mma16816(acc[mb][2*nb+0], ah[mb], bl[0], bl[1]);
                    mma16816(acc[mb][2*nb+1], ah[mb], bl[2], bl[3]);
                    mma16816(acc[mb][2*nb+0], al[mb], bh[0], bh[1]);
                    mma16816(acc[mb][2*nb+1], al[mb], bh[2], bh[3]);
                }
            }
        }
    };

    int nch = K >> 5;
    issue(0, 0);
    if (nch > 1) issue(1, 32);
    for (int ck = 0; ck < nch; ck++) {
        if (ck + 2 < nch) {
            issue((ck + 2) % 3, (ck + 2) << 5);
            asm volatile("cp.async.wait_group 2;" ::: "memory");
        } else if (ck + 1 < nch) {
            asm volatile("cp.async.wait_group 1;" ::: "memory");
        } else {
            asm volatile("cp.async.wait_group 0;" ::: "memory");
        }
        __syncthreads();
        compute(ck % 3);
        __syncthreads();
    }

    int g = lane >> 2, tg = lane & 3;

    if constexpr (BM == 128) {
        if (c0v) {
            float mn = 1e30f, mx = -1e30f;
            #pragma unroll
            for (int mb = 0; mb < 2; mb++) {
                #pragma unroll
                for (int ug = 0; ug < 2; ug++) {
                    int cb = col0 + wn + ug*32;
                    int u0 = ((cb >> 5) << 3) + 2*tg;
                    float iv[4], fv[4], gv[4], ov[4];
                    #pragma unroll
                    for (int e = 0; e < 4; e++) {
                        int co = 2*tg + (e & 1);
                        iv[e] = acc[mb][ug*4+0][e] + bias[cb + 0  + co];
                        fv[e] = acc[mb][ug*4+1][e] + bias[cb + 8  + co];
                        gv[e] = acc[mb][ug*4+2][e] + bias[cb + 16 + co];
                        ov[e] = acc[mb][ug*4+3][e] + bias[cb + 24 + co];
                    }
                    #pragma unroll
                    for (int half = 0; half < 2; half++) {
                        int row = row0 + wm + mb*16 + g + half*8;
                        float2 cc = *(const float2*)(c0v + (size_t)row*256 + u0);
                        float cin[2] = {cc.x, cc.y};
                        float hh[2], c2[2];
                        #pragma unroll
                        for (int e2 = 0; e2 < 2; e2++) {
                            int e = half*2 + e2;
                            float si = fsig(iv[e]);
                            float sf = fsig(fv[e]);
                            float so = fsig(ov[e]);
                            c2[e2] = sf * cin[e2] + si * ftanh(gv[e]);
                            hh[e2] = so * ftanh(c2[e2]);
                            mn = fminf(mn, hh[e2]); mx = fmaxf(mx, hh[e2]);
                        }
                        *(float2*)(hOut + (size_t)row*256 + u0) = make_float2(hh[0], hh[1]);
                        *(float2*)(cOut + (size_t)row*256 + u0) = make_float2(c2[0], c2[1]);
                    }
                }
            }
            __shared__ float smn[256], smx[256];
            smn[tid] = mn; smx[tid] = mx; __syncthreads();
            for (int s = 128; s > 0; s >>= 1) {
                if (tid < s) {
                    smn[tid] = fminf(smn[tid], smn[tid+s]);
                    smx[tid] = fmaxf(smx[tid], smx[tid+s]);
                }
                __syncthreads();
            }
            if (tid == 0) {
                int bid = blockIdx.y * gridDim.x + blockIdx.x;
                g_pmin[bid] = smn[0]; g_pmax[bid] = smx[0];
            }
            return;
        }
    }

    float cia[2][2] = {}, cja[2][2] = {};
    #pragma unroll
    for (int mb = 0; mb < 2; mb++) {
        #pragma unroll
        for (int n8 = 0; n8 < NB; n8++) {
            int row = row0 + wm + mb * 16 + g;
            int col = col0 + wn + n8 * 8 + 2 * tg;
            float b0 = bias ? bias[col]   : 0.f;
            float b1 = bias ? bias[col+1] : 0.f;
            float v00 = acc[mb][n8][0] + b0, v01 = acc[mb][n8][1] + b1;
            float v10 = acc[mb][n8][2] + b0, v11 = acc[mb][n8][3] + b1;
            if (Shi) {
                size_t d0 = (size_t)row * ldS + col;
                size_t d1 = (size_t)(row + 8) * ldS + col;
                bf16split(v00, &Shi[d0],   &Slo[d0]);
                bf16split(v01, &Shi[d0+1], &Slo[d0+1]);
                bf16split(v10, &Shi[d1],   &Slo[d1]);
                bf16split(v11, &Shi[d1+1], &Slo[d1+1]);
            }
            if (hwT) {
                hwT[(size_t)col*NA + row]         = v00;
                hwT[(size_t)(col+1)*NA + row]     = v01;
                hwT[(size_t)col*NA + row + 8]     = v10;
                hwT[(size_t)(col+1)*NA + row + 8] = v11;
            }
            if (aivec) {
                float a0 = aivec[col], a1 = aivec[col+1];
                float j0 = ajvec[col], j1 = ajvec[col+1];
                cia[mb][0] += v00*a0 + v01*a1;
                cia[mb][1] += v10*a0 + v11*a1;
                cja[mb][0] += v00*j0 + v01*j1;
                cja[mb][1] += v10*j0 + v11*j1;
            }
        }
    }
    if (aivec) {
        int hh = (col0 + wn) / Gh;
        #pragma unroll
        for (int mb = 0; mb < 2; mb++) {
            #pragma unroll
            for (int hf = 0; hf < 2; hf++) {
                float ci = cia[mb][hf], cj = cja[mb][hf];
                ci += __shfl_xor_sync(0xffffffffu, ci, 1);
                ci += __shfl_xor_sync(0xffffffffu, ci, 2);
                cj += __shfl_xor_sync(0xffffffffu, cj, 1);
                cj += __shfl_xor_sync(0xffffffffu, cj, 2);
                if (tg == 0) {
                    int row = row0 + wm + mb * 16 + g + hf * 8;
                    atomicAdd(&g_ci[hh*NA + row], ci);
                    atomicAdd(&g_cj[hh*NA + row], cj);
                }
            }
        }
    }
}

// ---------------- fake-quant A: float accum + fast log2 ----------------------
__global__ void quantA(const float* __restrict__ x,
                       __nv_bfloat16* __restrict__ hi, __nv_bfloat16* __restrict__ lo,
                       int npart)
{
    __shared__ float smn[256], smx[256];
    __shared__ float sparam[2];
    float mn = 1e30f, mx = -1e30f;
    for (int i = threadIdx.x; i < npart; i += 256) {
        mn = fminf(mn, g_pmin[i]); mx = fmaxf(mx, g_pmax[i]);
    }
    smn[threadIdx.x] = mn; smx[threadIdx.x] = mx; __syncthreads();
    for (int s = 128; s > 0; s >>= 1) {
        if (threadIdx.x < s) {
            smn[threadIdx.x] = fminf(smn[threadIdx.x], smn[threadIdx.x+s]);
            smx[threadIdx.x] = fmaxf(smx[threadIdx.x], smx[threadIdx.x+s]);
        }
        __syncthreads();
    }
    if (threadIdx.x == 0) {
        float a = smn[0], b = smx[0];
        if (a == b) { a -= 0.01f; b += 0.01f; }
        float scale = (b - a) / 255.f;
        sparam[0] = scale;
        sparam[1] = rintf(-a / scale);
    }
    __syncthreads();
    float scale = sparam[0], zp = sparam[1];

    float part = 0.f;
    #pragma unroll
    for (int l = 0; l < 4; l++) {
        int i = blockIdx.x*256 + threadIdx.x + l*65536;
        float4 t = ((const float4*)x)[i];
        float ts[4] = {t.x, t.y, t.z, t.w};
        float ds[4];
        #pragma unroll
        for (int q = 0; q < 4; q++) {
            float r = rintf(ts[q]/scale + zp);
            r = fminf(fmaxf(r, 0.f), 255.f);
            float d = (r - zp) * scale;
            ds[q] = d;
            part += __log2f(fmaf(510.f, fabsf(d), 1.f));
        }
        __nv_bfloat162 h01, h23, l01, l23;
        __nv_bfloat16 hh, ll;
        bf16split(ds[0], &hh, &ll); h01.x = hh; l01.x = ll;
        bf16split(ds[1], &hh, &ll); h01.y = hh; l01.y = ll;
        bf16split(ds[2], &hh, &ll); h23.x = hh; l23.x = ll;
        bf16split(ds[3], &hh, &ll); h23.y = hh; l23.y = ll;
        ((__nv_bfloat162*)hi)[i*2]   = h01;
        ((__nv_bfloat162*)hi)[i*2+1] = h23;
        ((__nv_bfloat162*)lo)[i*2]   = l01;
        ((__nv_bfloat162*)lo)[i*2+1] = l23;
    }
    __shared__ float sd[256];
    sd[threadIdx.x] = part; __syncthreads();
    for (int s = 128; s > 0; s >>= 1) { if (threadIdx.x < s) sd[threadIdx.x] += sd[threadIdx.x+s]; __syncthreads(); }
    if (threadIdx.x == 0) atomicAdd(&g_loss, sd[0]);
}

// ---------------- fake-quant T: float accum + fast log2 ----------------------
__global__ void quantT(const float* __restrict__ inT,
                       __nv_bfloat16* __restrict__ hi, __nv_bfloat16* __restrict__ lo,
                       int npart)
{
    __shared__ float tile[32][33];
    __shared__ float smn[256], smx[256];
    __shared__ float sparam[2];
    int tx = threadIdx.x, ty = threadIdx.y;
    int tid = ty*32 + tx;

    float mn = (tid < npart) ? g_pmin[tid] : 1e30f;
    float mx = (tid < npart) ? g_pmax[tid] : -1e30f;
    smn[tid] = mn; smx[tid] = mx; __syncthreads();
    for (int s = 128; s > 0; s >>= 1) {
        if (tid < s) {
            smn[tid] = fminf(smn[tid], smn[tid+s]);
            smx[tid] = fmaxf(smx[tid], smx[tid+s]);
        }
        __syncthreads();
    }
    if (tid == 0) {
        float a = smn[0], b = smx[0];
        if (a == b) { a -= 0.01f; b += 0.01f; }
        float scale = (b - a) / 255.f;
        sparam[0] = scale;
        sparam[1] = rintf(-a / scale);
    }
    __syncthreads();
    float scale = sparam[0], zp = sparam[1];

    int c0 = blockIdx.y * 32;
    float part = 0.f;
    #pragma unroll 1
    for (int nt = 0; nt < 4; nt++) {
        int n0 = blockIdx.x * 128 + nt * 32;
        for (int cc = ty; cc < 32; cc += 8) {
            float t = inT[(size_t)(c0+cc)*NA + n0 + tx];
            float r = rintf(t/scale + zp);
            r = fminf(fmaxf(r, 0.f), 255.f);
            float d = (r - zp) * scale;
            tile[cc][tx] = d;
            part += __log2f(fmaf(510.f, fabsf(d), 1.f));
        }
        __syncthreads();
        for (int nn = ty; nn < 32; nn += 8) {
            float d = tile[tx][nn];
            size_t o = (size_t)(n0+nn)*256 + c0 + tx;
            bf16split(d, &hi[o], &lo[o]);
        }
        __syncthreads();
    }
    __shared__ float sd[256];
    sd[tid] = part; __syncthreads();
    for (int s = 128; s > 0; s >>= 1) { if (tid < s) sd[tid] += sd[tid+s]; __syncthreads(); }
    if (tid == 0) atomicAdd(&g_loss, sd[0]);
}

// ---------------- sortk: bitonic (warp-local inner stages) + scans + denom ----
__global__ void __launch_bounds__(1024)
sortk()
{
    extern __shared__ char sms[];
    float* key = (float*)sms;
    int*   idx = (int*)(key + NA);
    float* sA  = (float*)(idx + NA);
    float* sB  = sA + NA;
    __shared__ float wsum[32];
    int h = blockIdx.x;
    int tid = threadIdx.x, lane = tid & 31, warp = tid >> 5;

    for (int i = tid; i < NA; i += 1024) { key[i] = g_cj[h*NA + i]; idx[i] = i; }
    __syncthreads();
    for (int k = 2; k <= NA; k <<= 1) {
        int j = k >> 1;
        for (; j >= 128; j >>= 1) {
            #pragma unroll 2
            for (int p = tid; p < NA/2; p += 1024) {
                int i = ((p & ~(j-1)) << 1) | (p & (j-1));
                int il = i | j;
                bool up = ((i & k) == 0);
                float a = key[i], b = key[il];
                if (up ? (a > b) : (a < b)) {
                    key[i] = b; key[il] = a;
                    int tmp = idx[i]; idx[i] = idx[il]; idx[il] = tmp;
                }
            }
            __syncthreads();
        }
        for (; j >= 1; j >>= 1) {
            #pragma unroll 2
            for (int q = lane; q < 64; q += 32) {
                int p = (warp << 6) | q;
                int i = ((p & ~(j-1)) << 1) | (p & (j-1));
                int il = i | j;
                bool up = ((i & k) == 0);
                float a = key[i], b = key[il];
                if (up ? (a > b) : (a < b)) {
                    key[i] = b; key[il] = a;
                    int tmp = idx[i]; idx[i] = idx[il]; idx[il] = tmp;
                }
            }
            __syncwarp();
        }
        __syncthreads();
    }
    float cm = key[NA-1];

    int t0 = tid * 4;
    float kw0 = key[t0], kw1 = key[t0+1], kw2 = key[t0+2], kw3 = key[t0+3];
    float wB0 = expf(0.2f*(kw0-cm)), wB1 = expf(0.2f*(kw1-cm));
    float wB2 = expf(0.2f*(kw2-cm)), wB3 = expf(0.2f*(kw3-cm));
    float wA0 = expf(kw0-cm), wA1 = expf(kw1-cm), wA2 = expf(kw2-cm), wA3 = expf(kw3-cm);
    *(int4*)&g_sidx[h*NA + t0] = make_int4(idx[t0], idx[t0+1], idx[t0+2], idx[t0+3]);
    *(float4*)&g_wA[h*NA + t0] = make_float4(wA0, wA1, wA2, wA3);
    *(float4*)&g_wB[h*NA + t0] = make_float4(wB0, wB1, wB2, wB3);

    {
        float v0 = wB0, v1 = v0+wB1, v2 = v1+wB2, v3 = v2+wB3;
        float tot = v3, s = tot;
        #pragma unroll
        for (int o = 1; o < 32; o <<= 1) { float u = __shfl_up_sync(0xffffffffu, s, o); if (lane >= o) s += u; }
        if (lane == 31) wsum[warp] = s;
        __syncthreads();
        if (warp == 0) {
            float y = wsum[lane];
            #pragma unroll
            for (int o = 1; o < 32; o <<= 1) { float u = __shfl_up_sync(0xffffffffu, y, o); if (lane >= o) y += u; }
            wsum[lane] = y;
        }
        __syncthreads();
        float off = (warp ? wsum[warp-1] : 0.f) + (s - tot);
        sB[t0] = off+v0; sB[t0+1] = off+v1; sB[t0+2] = off+v2; sB[t0+3] = off+v3;
    }
    __syncthreads();
    {
        int rb = NA - 4 - t0;
        float a0 = expf(key[rb]-cm),   a1 = expf(key[rb+1]-cm);
        float a2 = expf(key[rb+2]-cm), a3 = expf(key[rb+3]-cm);
        float u0 = a3, u1 = u0+a2, u2 = u1+a1, u3 = u2+a0;
        float tot = u3, s = tot;
        #pragma unroll
        for (int o = 1; o < 32; o <<= 1) { float u = __shfl_up_sync(0xffffffffu, s, o); if (lane >= o) s += u; }
        if (lane == 31) wsum[warp] = s;
        __syncthreads();
        if (warp == 0) {
            float y = wsum[lane];
            #pragma unroll
            for (int o = 1; o < 32; o <<= 1) { float u = __shfl_up_sync(0xffffffffu, y, o); if (lane >= o) y += u; }
            wsum[lane] = y;
        }
        __syncthreads();
        float off = (warp ? wsum[warp-1] : 0.f) + (s - tot);
        sA[rb] = off+u3; sA[rb+1] = off+u2; sA[rb+2] = off+u1; sA[rb+3] = off+u0;
    }
    __syncthreads();

    for (int l = 0; l < 4; l++) {
        int n = tid + l*1024;
        float cin = g_ci[h*NA + n];
        float t = -cin;
        int lo = 0, hi = NA;
        while (lo < hi) {
            int mid = (lo + hi) >> 1;
            if (key[mid] <= t) lo = mid + 1; else hi = mid;
        }
        float r = expf(0.8f * (cin + cm));
        float A = (lo < NA) ? sA[lo]     : 0.f;
        float B = (lo > 0)  ? sB[lo - 1] : 0.f;
        g_kcount[h*NA + n] = lo;
        g_rn[h*NA + n]     = r;
        g_invd[h*NA + n]   = 1.f / (r*A + B);
        g_ci[h*NA + n] = 0.f;
        g_cj[h*NA + n] = 0.f;
    }
}

// ---------------- scomb: 512 threads, per-column scan + transposed output ----
__global__ void __launch_bounds__(512)
scomb(const float* __restrict__ bias, float* __restrict__ outT,
      int G, int do_elu, int do_mm)
{
    __shared__ float s_pre[NA];
    __shared__ float s_suf[NA];
    __shared__ float wsum[16];
    int c = blockIdx.x;
    int h = c / G;
    int tid = threadIdx.x, lane = tid & 31, warp = tid >> 5;
    int t0 = tid * 8;
    const float* xrow = g_hWT + (size_t)c * NA;

    {
        int4 iva = *(const int4*)&g_sidx[h*NA + t0];
        int4 ivb = *(const int4*)&g_sidx[h*NA + t0 + 4];
        float4 wa = *(const float4*)&g_wB[h*NA + t0];
        float4 wb = *(const float4*)&g_wB[h*NA + t0 + 4];
        float v[8];
        float run = wa.x * xrow[iva.x];              v[0] = run;
        run += wa.y * xrow[iva.y];                   v[1] = run;
        run += wa.z * xrow[iva.z];                   v[2] = run;
        run += wa.w * xrow[iva.w];                   v[3] = run;
        run += wb.x * xrow[ivb.x];                   v[4] = run;
        run += wb.y * xrow[ivb.y];                   v[5] = run;
        run += wb.z * xrow[ivb.z];                   v[6] = run;
        run += wb.w * xrow[ivb.w];                   v[7] = run;
        float tot = run, s = tot;
        #pragma unroll
        for (int o = 1; o < 32; o <<= 1) { float u = __shfl_up_sync(0xffffffffu, s, o); if (lane >= o) s += u; }
        if (lane == 31) wsum[warp] = s;
        __syncthreads();
        if (warp == 0 && lane < 16) {
            float y = wsum[lane];
            #pragma unroll
            for (int o = 1; o < 16; o <<= 1) { float u = __shfl_up_sync(0xffffu, y, o); if (lane >= o) y += u; }
            wsum[lane] = y;
        }
        __syncthreads();
        float off = (warp ? wsum[warp-1] : 0.f) + (s - tot);
        #pragma unroll
        for (int e = 0; e < 8; e++) s_pre[t0+e] = off + v[e];
    }
    __syncthreads();
    {
        int rb = NA - 8 - t0;
        int4 iva = *(const int4*)&g_sidx[h*NA + rb];
        int4 ivb = *(const int4*)&g_sidx[h*NA + rb + 4];
        float4 wa = *(const float4*)&g_wA[h*NA + rb];
        float4 wb = *(const float4*)&g_wA[h*NA + rb + 4];
        float xs[8] = { xrow[iva.x], xrow[iva.y], xrow[iva.z], xrow[iva.w],
                        xrow[ivb.x], xrow[ivb.y], xrow[ivb.z], xrow[ivb.w] };
        float ws[8] = { wa.x, wa.y, wa.z, wa.w, wb.x, wb.y, wb.z, wb.w };
        float u[8];
        float run = ws[7]*xs[7];  u[0] = run;
        #pragma unroll
        for (int e = 1; e < 8; e++) { run += ws[7-e]*xs[7-e]; u[e] = run; }
        float tot = run, s = tot;
        #pragma unroll
        for (int o = 1; o < 32; o <<= 1) { float uu = __shfl_up_sync(0xffffffffu, s, o); if (lane >= o) s += uu; }
        if (lane == 31) wsum[warp] = s;
        __syncthreads();
        if (warp == 0 && lane < 16) {
            float y = wsum[lane];
            #pragma unroll
            for (int o = 1; o < 16; o <<= 1) { float uu = __shfl_up_sync(0xffffu, y, o); if (lane >= o) y += uu; }
            wsum[lane] = y;
        }
        __syncthreads();
        float off = (warp ? wsum[warp-1] : 0.f) + (s - tot);
        #pragma unroll
        for (int e = 0; e < 8; e++) s_suf[rb + 7 - e] = off + u[e];
    }
    __syncthreads();

    float bv = bias[c];
    float mn = 1e30f, mx = -1e30f;
    #pragma unroll
    for (int l = 0; l < 8; l++) {
        int n = tid + l*512;
        int k = g_kcount[h*NA + n];
        float r = g_rn[h*NA + n];
        float invd = g_invd[h*NA + n];
        float Av = (k < NA) ? s_suf[k]     : 0.f;
        float Bv = (k > 0)  ? s_pre[k - 1] : 0.f;
        float val = (r*Av + Bv) * invd + bv;
        if (do_elu) val = (val > 0.f) ? val : expm1f(val);
        mn = fminf(mn, val); mx = fmaxf(mx, val);
        outT[(size_t)c*NA + n] = val;
    }
    if (do_mm) {
        __shared__ float smn[512], smx[512];
        smn[tid] = mn; smx[tid] = mx; __syncthreads();
        for (int s = 256; s > 0; s >>= 1) {
            if (tid < s) {
                smn[tid] = fminf(smn[tid], smn[tid+s]);
                smx[tid] = fmaxf(smx[tid], smx[tid+s]);
            }
            __syncthreads();
        }
        if (tid == 0) { g_pmin[c] = smn[0]; g_pmax[c] = smx[0]; }
    }
}

// ---------------- fused policy + value head (+ loss write) ----------------
__global__ void __launch_bounds__(256)
policyk(const float* __restrict__ A0, const float* __restrict__ A1T,
        const float* __restrict__ Wa, const float* __restrict__ ba,
        const float* __restrict__ Wv, const float* __restrict__ bv,
        float* __restrict__ out_logp, float* __restrict__ out_value,
        float* __restrict__ out_loss)
{
    if (blockIdx.x == 0 && threadIdx.x == 0) out_loss[0] = g_loss;
    __shared__ float As[16][68];
    __shared__ float Bs[16][68];
    __shared__ float Ss[64][65];
    int tid = threadIdx.x;
    int tx = tid % 16, ty = tid / 16;
    int row0 = blockIdx.x * 64;
    float acc[4][4] = {};
    float vacc = 0.f;

    for (int k0 = 0; k0 < 512; k0 += 16) {
        if (k0 < 256) {
            int lin = tid * 4;
            int m = lin >> 4, kk = lin & 15;
            float4 v = *(const float4*)&A0[(size_t)(row0+m)*256 + k0 + kk];
            As[kk+0][m] = v.x; As[kk+1][m] = v.y; As[kk+2][m] = v.z; As[kk+3][m] = v.w;
        } else {
            int lin = tid * 4;
            int kk = lin >> 6, m4 = lin & 63;
            float4 v = *(const float4*)&A1T[(size_t)(k0-256+kk)*NA + row0 + m4];
            *(float4*)&As[kk][m4] = v;
        }
        {
            int lin = tid * 4;
            int kk = lin >> 6, n = lin & 63;
            *(float4*)&Bs[kk][n] = *(const float4*)&Wa[(size_t)(k0+kk)*64 + n];
        }
        __syncthreads();
        #pragma unroll
        for (int kk = 0; kk < 16; kk++) {
            float a[4], bb[4];
            #pragma unroll
            for (int i = 0; i < 4; i++) a[i] = As[kk][ty*4+i];
            #pragma unroll
            for (int j = 0; j < 4; j++) bb[j] = Bs[kk][tx*4+j];
            #pragma unroll
            for (int i = 0; i < 4; i++)
                #pragma unroll
                for (int j = 0; j < 4; j++)
                    acc[i][j] = fmaf(a[i], bb[j], acc[i][j]);
        }
        if (tid < 64) {
            #pragma unroll
            for (int kk = 0; kk < 16; kk++)
                vacc = fmaf(As[kk][tid], Wv[k0+kk], vacc);
        }
        __syncthreads();
    }
    if (tid < 64) out_value[row0 + tid] = vacc + bv[0];

    #pragma unroll
    for (int i = 0; i < 4; i++)
        #pragma unroll
        for (int j = 0; j < 4; j++)
            Ss[ty*4+i][tx*4+j] = acc[i][j] + ba[tx*4+j];
    __syncthreads();

    int row = tid >> 2, quad = tid & 3;
    float m = -1e30f;
    #pragma unroll
    for (int c = 0; c < 16; c++) m = fmaxf(m, Ss[row][quad*16 + c]);
    m = fmaxf(m, __shfl_xor_sync(0xffffffffu, m, 1));
    m = fmaxf(m, __shfl_xor_sync(0xffffffffu, m, 2));
    float s = 0.f;
    #pragma unroll
    for (int c = 0; c < 16; c++) s += expf(Ss[row][quad*16 + c] - m);
    s += __shfl_xor_sync(0xffffffffu, s, 1);
    s += __shfl_xor_sync(0xffffffffu, s, 2);
    float lse = m + logf(s);
    #pragma unroll
    for (int c = 0; c < 16; c++)
        out_logp[(size_t)(row0+row)*64 + quad*16 + c] = Ss[row][quad*16 + c] - lse;
}

// ---------------- host ----------------
extern "C" void kernel_launch(void* const* d_in, const int* in_sizes, int n_in,
                              void* d_out, int out_size)
{
    const float* obs  = (const float*)d_in[0];
    const float* h0   = (const float*)d_in[1];
    const float* c0   = (const float*)d_in[2];
    const float* Wobs = (const float*)d_in[3];
    const float* bobs = (const float*)d_in[4];
    const float* Wih  = (const float*)d_in[5];
    const float* Whh  = (const float*)d_in[6];
    const float* bih  = (const float*)d_in[7];
    const float* bhh  = (const float*)d_in[8];
    const float* W1   = (const float*)d_in[9];
    const float* ai1  = (const float*)d_in[10];
    const float* aj1  = (const float*)d_in[11];
    const float* b1   = (const float*)d_in[12];
    const float* W2   = (const float*)d_in[13];
    const float* ai2  = (const float*)d_in[14];
    const float* aj2  = (const float*)d_in[15];
    const float* b2   = (const float*)d_in[16];
    const float* Wv   = (const float*)d_in[17];
    const float* bv   = (const float*)d_in[18];
    const float* Wa   = (const float*)d_in[19];
    const float* ba   = (const float*)d_in[20];

    float* out       = (float*)d_out;
    float* out_logp  = out;
    float* out_value = out + NA*ACT;
    float* out_h     = out_value + NA;
    float* out_c     = out_h + NA*HD;
    float* out_loss  = out_c + NA*HD;

    float *p_hWT, *p_commT, *p_bsum;
    __nv_bfloat16 *p_Ah, *p_Al, *p_A2h, *p_A2l;
    __nv_bfloat16 *p_B0h, *p_B0l, *p_Bgh, *p_Bgl, *p_B1h, *p_B1l, *p_B2h, *p_B2l;
    cudaGetSymbolAddress((void**)&p_hWT,    g_hWT);
    cudaGetSymbolAddress((void**)&p_commT,  g_commT);
    cudaGetSymbolAddress((void**)&p_bsum,   g_bsum);
    cudaGetSymbolAddress((void**)&p_Ah,     g_Ah);
    cudaGetSymbolAddress((void**)&p_Al,     g_Al);
    cudaGetSymbolAddress((void**)&p_A2h,    g_A2h);
    cudaGetSymbolAddress((void**)&p_A2l,    g_A2l);
    cudaGetSymbolAddress((void**)&p_B0h,    g_B0h);
    cudaGetSymbolAddress((void**)&p_B0l,    g_B0l);
    cudaGetSymbolAddress((void**)&p_Bgh,    g_Bgh);
    cudaGetSymbolAddress((void**)&p_Bgl,    g_Bgl);
    cudaGetSymbolAddress((void**)&p_B1h,    g_B1h);
    cudaGetSymbolAddress((void**)&p_B1l,    g_B1l);
    cudaGetSymbolAddress((void**)&p_B2h,    g_B2h);
    cudaGetSymbolAddress((void**)&p_B2l,    g_B2l);

    const int SM128 = TG_SMEM_BYTES(128);
    const int SM64  = TG_SMEM_BYTES(64);
    const int SMSORT = NA * 16;
    cudaFuncSetAttribute((const void*)tgemm<128>, cudaFuncAttributeMaxDynamicSharedMemorySize, SM128);
    cudaFuncSetAttribute((const void*)tgemm<64>,  cudaFuncAttributeMaxDynamicSharedMemorySize, SM64);
    cudaFuncSetAttribute((const void*)sortk,      cudaFuncAttributeMaxDynamicSharedMemorySize, SMSORT);

    // 1. prep
    wprep<<<WQ8/256, 256>>>(obs, h0, Wobs, Wih, Whh, W1, W2, bih, bhh, bobs);
    // 2. weight-product GEMM -> Bg cols 0..255 (split output)
    tgemm<64><<<dim3(2, 16), 256, SM64>>>(p_A2h, p_A2l, p_B0h, p_B0l, nullptr,
                                          p_Bgh, p_Bgl, 512,
                                          nullptr, nullptr, nullptr, 0,
                                          nullptr, nullptr, nullptr, 256, 256);
    // 3. gates GEMM ([obs|h0] @ Bg^T) + fused LSTM -> out_h, out_c, minmax[256]
    tgemm<128><<<dim3(8, 32), 256, SM128>>>(p_Ah, p_Al, p_Bgh, p_Bgl, p_bsum,
                                            nullptr, nullptr, 0,
                                            nullptr, nullptr, nullptr, 0,
                                            c0, out_h, out_c, 1024, 512);
    // 4. quant #1 -> splits into A2 (row-major [n][256])
    quantA<<<256, 256>>>(out_h, p_A2h, p_A2l, 256);
    // 5. GAT1 projection -> hWT + fused ci/cj
    tgemm<64><<<dim3(2, 64), 256, SM64>>>(p_A2h, p_A2l, p_B1h, p_B1l, nullptr,
                                          nullptr, nullptr, 0,
                                          p_hWT, ai1, aj1, 64,
                                          nullptr, nullptr, nullptr, 256, 256);
    // 6-7. GAT1 attention
    sortk<<<4, 1024, SMSORT>>>();
    scomb<<<256, 512>>>(b1, p_commT, 64, 1, 1);
    // 8. quant #2 (transposed input)
    quantT<<<dim3(NA/128, 8), dim3(32, 8)>>>(p_commT, p_A2h, p_A2l, 256);
    // 9. GAT2 projection
    tgemm<64><<<dim3(2, 64), 256, SM64>>>(p_A2h, p_A2l, p_B2h, p_B2l, nullptr,
                                          nullptr, nullptr, 0,
                                          p_hWT, ai2, aj2, 256,
                                          nullptr, nullptr, nullptr, 256, 256);
    // 10-11. GAT2 attention
    sortk<<<1, 1024, SMSORT>>>();
    scomb<<<256, 512>>>(b2, p_commT, 256, 0, 0);
    // 12. fused policy + value heads + loss
    policyk<<<NA/64, 256>>>(out_h, p_commT, Wa, ba, Wv, bv, out_logp, out_value, out_loss);
}

// round 14
// speedup vs baseline: 1.0497x; 1.0008x over previous
#include <cuda_runtime.h>
#include <cuda_bf16.h>
#include <math.h>
#include <stdint.h>

#define NA   4096
#define HD   256
#define HG   256
#define ACT  64
#define MMB  1024

// ---------------- device scratch ----------------
__device__ float g_hWT[HG*NA];
__device__ float g_commT[HG*NA];
__device__ float g_bsum[4*HD];
__device__ __nv_bfloat16 g_Ah[NA*512];
__device__ __nv_bfloat16 g_Al[NA*512];
__device__ __nv_bfloat16 g_A2h[NA*256];
__device__ __nv_bfloat16 g_A2l[NA*256];
__device__ __nv_bfloat16 g_B0h[256*256], g_B0l[256*256];
__device__ __nv_bfloat16 g_Bgh[1024*512], g_Bgl[1024*512];
__device__ __nv_bfloat16 g_B1h[256*256], g_B1l[256*256];
__device__ __nv_bfloat16 g_B2h[256*256], g_B2l[256*256];
__device__ float g_ci[4*NA];
__device__ float g_cj[4*NA];
__device__ int   g_kcount[4*NA];
__device__ int   g_sidx[4*NA];
__device__ float g_wA[4*NA];
__device__ float g_wB[4*NA];
__device__ float g_rn[4*NA];
__device__ float g_invd[4*NA];
__device__ float g_pmin[MMB];
__device__ float g_pmax[MMB];
__device__ float g_loss;

__device__ __forceinline__ void bf16split(float x, __nv_bfloat16* hi, __nv_bfloat16* lo) {
    __nv_bfloat16 h = __float2bfloat16(x);
    *hi = h;
    *lo = __float2bfloat16(x - __bfloat162float(h));
}
__device__ __forceinline__ float fsig(float x) { return 1.f / (1.f + __expf(-x)); }
__device__ __forceinline__ float ftanh(float x) {
    float ax = fabsf(x);
    float e = __expf(-2.f * ax);
    float t = (1.f - e) / (1.f + e);
    return copysignf(t, x);
}
// split 4 consecutive values -> 8B stores
__device__ __forceinline__ void split4(const float* v, __nv_bfloat16* hi, __nv_bfloat16* lo) {
    __nv_bfloat16 h[4], l[4];
    #pragma unroll
    for (int e = 0; e < 4; e++) bf16split(v[e], &h[e], &l[e]);
    *(uint2*)hi = *(uint2*)h;
    *(uint2*)lo = *(uint2*)l;
}

// ---------------- fused prep (vectorized: 4 elems/thread) --------------------
// vec4 region boundaries (in float4 units)
#define WV0 (NA*64)                 // obs
#define WV1 (WV0 + NA*64)           // h0 -> Ah cols 256..511
#define WV2 (WV1 + 16384)           // Wobs raw
#define WV3 (WV2 + 65536)           // Wih perm -> A2
#define WV4 (WV3 + 65536)           // Whh perm -> Bg cols 256..511
#define WV5 (WV4 + 16384)           // W1^T
#define WV6 (WV5 + 16384)           // W2^T
#define WV7 (WV6 + 4096)            // zero ci/cj (float4)
#define WVTOT (WV7 + 32768)         // bsum warp dots (scalar threads)
__global__ void wprep(const float* __restrict__ obs, const float* __restrict__ h0,
                      const float* __restrict__ Wobs,
                      const float* __restrict__ Wih, const float* __restrict__ Whh,
                      const float* __restrict__ W1, const float* __restrict__ W2,
                      const float* __restrict__ bih, const float* __restrict__ bhh,
                      const float* __restrict__ bobs)
{
    int idx = blockIdx.x*256 + threadIdx.x;
    if (idx == 0) g_loss = 0.f;
    if (idx < WV0) {
        int j = idx * 4;                     // n*256 + k
        int n = j >> 8, k = j & 255;
        int d = n*512 + k;
        float4 v = *(const float4*)(obs + j);
        split4(&v.x, &g_Ah[d], &g_Al[d]);
    } else if (idx < WV1) {
        int j = (idx - WV0) * 4;
        int n = j >> 8, k = j & 255;
        int d = n*512 + 256 + k;
        float4 v = *(const float4*)(h0 + j);
        split4(&v.x, &g_Ah[d], &g_Al[d]);
    } else if (idx < WV2) {
        int j = (idx - WV1) * 4;
        float4 v = *(const float4*)(Wobs + j);
        split4(&v.x, &g_B0h[j], &g_B0l[j]);
    } else if (idx < WV3) {
        int j = (idx - WV2) * 4;
        int r = j >> 8, k = j & 255;
        int G = (r >> 3) & 3;
        int u = ((r >> 5) << 3) | (r & 7);
        float4 v = *(const float4*)(Wih + (G*256 + u)*256 + k);
        split4(&v.x, &g_A2h[j], &g_A2l[j]);
    } else if (idx < WV4) {
        int j = (idx - WV3) * 4;
        int r = j >> 8, k = j & 255;
        int G = (r >> 3) & 3;
        int u = ((r >> 5) << 3) | (r & 7);
        int d = r*512 + 256 + k;
        float4 v = *(const float4*)(Whh + (G*256 + u)*256 + k);
        split4(&v.x, &g_Bgh[d], &g_Bgl[d]);
    } else if (idx < WV5) {
        int j = (idx - WV4) * 4;
        int n = j >> 8, k = j & 255;
        float vv[4];
        #pragma unroll
        for (int e = 0; e < 4; e++) vv[e] = W1[(k+e)*256 + n];
        split4(vv, &g_B1h[j], &g_B1l[j]);
    } else if (idx < WV6) {
        int j = (idx - WV5) * 4;
        int n = j >> 8, k = j & 255;
        float vv[4];
        #pragma unroll
        for (int e = 0; e < 4; e++) vv[e] = W2[(k+e)*256 + n];
        split4(vv, &g_B2h[j], &g_B2l[j]);
    } else if (idx < WV7) {
        int j = (idx - WV6);
        float4 z = make_float4(0.f, 0.f, 0.f, 0.f);
        ((float4*)g_ci)[j] = z;
        ((float4*)g_cj)[j] = z;
    } else if (idx < WVTOT) {
        int t = idx - WV7;
        int r = t >> 5, lane = t & 31;
        int G = (r >> 3) & 3;
        int u = ((r >> 5) << 3) | (r & 7);
        int orow = G*256 + u;
        float s = 0.f;
        #pragma unroll
        for (int k = lane; k < 256; k += 32)
            s = fmaf(bobs[k], Wih[orow*256 + k], s);
        for (int o = 16; o > 0; o >>= 1) s += __shfl_down_sync(0xffffffffu, s, o);
        if (lane == 0) g_bsum[r] = s + bih[orow] + bhh[orow];
    }
}

// ---------------- mma.sync helpers ----------------
__device__ __forceinline__ uint32_t cvta_sm(const void* p) {
    uint32_t a;
    asm("{ .reg .u64 t; cvta.to.shared.u64 t, %1; cvt.u32.u64 %0, t; }" : "=r"(a) : "l"(p));
    return a;
}
__device__ __forceinline__ void ldm_x4(uint32_t (&d)[4], uint32_t addr) {
    asm volatile("ldmatrix.sync.aligned.m8n8.x4.shared.b16 {%0,%1,%2,%3}, [%4];"
        : "=r"(d[0]), "=r"(d[1]), "=r"(d[2]), "=r"(d[3]) : "r"(addr));
}
__device__ __forceinline__ void mma16816(float (&c)[4], const uint32_t (&a)[4],
                                         uint32_t b0, uint32_t b1) {
    asm volatile("mma.sync.aligned.m16n8k16.row.col.f32.bf16.bf16.f32 "
        "{%0,%1,%2,%3},{%4,%5,%6,%7},{%8,%9},{%0,%1,%2,%3};"
        : "+f"(c[0]), "+f"(c[1]), "+f"(c[2]), "+f"(c[3])
        : "r"(a[0]), "r"(a[1]), "r"(a[2]), "r"(a[3]), "r"(b0), "r"(b1));
}

// ---------------- split-bf16 tensor GEMM, cp.async 3-stage pipeline ----------
#define TG_STRIDE 40
#define TG_STAGE_ELE(BM)   (2*(BM)*TG_STRIDE + 2*128*TG_STRIDE)
#define TG_SMEM_BYTES(BM)  (3 * TG_STAGE_ELE(BM) * 2)

template<int BM>
__global__ void __launch_bounds__(256, BM == 64 ? 2 : 1)
tgemm(const __nv_bfloat16* __restrict__ Ah, const __nv_bfloat16* __restrict__ Al,
      const __nv_bfloat16* __restrict__ Bh, const __nv_bfloat16* __restrict__ Bl,
      const float* __restrict__ bias,
      __nv_bfloat16* __restrict__ Shi, __nv_bfloat16* __restrict__ Slo, int ldS,
      float* __restrict__ hwT, const float* __restrict__ aivec,
      const float* __restrict__ ajvec, int Gh,
      const float* __restrict__ c0v, float* __restrict__ hOut, float* __restrict__ cOut,
      int N, int K)
{
    constexpr int A_ELE = BM * TG_STRIDE;
    constexpr int B_ELE = 128 * TG_STRIDE;
    constexpr int STAGE = 2*A_ELE + 2*B_ELE;
    static_assert(STAGE == TG_STAGE_ELE(BM), "stage size mismatch");
    constexpr int NWM  = BM / 32;
    constexpr int WN   = 128 / (8 / NWM);
    constexpr int NB16 = WN / 16;
    constexpr int NB   = WN / 8;
    constexpr int A_U4 = BM * 4;
    constexpr int B_U4 = 512;
    constexpr int TOT_U4 = 2*A_U4 + 2*B_U4;

    extern __shared__ __nv_bfloat16 sm[];
    int tid = threadIdx.x, lane = tid & 31, wid = tid >> 5;
    int col0 = blockIdx.x * 128, row0 = blockIdx.y * BM;
    int wm = (wid % NWM) * 32, wn = (wid / NWM) * WN;
    uint32_t sb = cvta_sm(sm);

    float acc[2][NB][4] = {};

    auto issue = [&](int stage, int k0) {
        uint32_t stb = sb + (uint32_t)stage * STAGE * 2;
        #pragma unroll
        for (int l = 0; l < TOT_U4/256; l++) {
            int i = tid + l * 256;
            const __nv_bfloat16* src;
            int r, c8;
            uint32_t soff;
            if (i < 2*A_U4) {
                int a = i / A_U4, j = i % A_U4;
                r = j >> 2; c8 = j & 3;
                src = (a ? Al : Ah) + (size_t)(row0 + r) * K;
                soff = (uint32_t)a * A_ELE;
            } else {
                int i2 = i - 2*A_U4;
                int a = i2 / B_U4, j = i2 % B_U4;
                r = j >> 2; c8 = j & 3;
                src = (a ? Bl : Bh) + (size_t)(col0 + r) * K;
                soff = 2*A_ELE + (uint32_t)a * B_ELE;
            }
            uint32_t dst = stb + (soff + r * TG_STRIDE + c8 * 8) * 2;
            const __nv_bfloat16* g = src + k0 + c8 * 8;
            asm volatile("cp.async.cg.shared.global [%0], [%1], 16;" :: "r"(dst), "l"(g));
        }
        asm volatile("cp.async.commit_group;" ::: "memory");
    };

    auto compute = [&](int stage) {
        uint32_t stb = sb + (uint32_t)stage * STAGE * 2;
        uint32_t bA_h = stb, bA_l = stb + A_ELE*2;
        uint32_t bB_h = stb + 2*A_ELE*2, bB_l = stb + (2*A_ELE + B_ELE)*2;
        #pragma unroll
        for (int kk = 0; kk < 32; kk += 16) {
            uint32_t ah[2][4], al[2][4];
            #pragma unroll
            for (int mb = 0; mb < 2; mb++) {
                int r = wm + mb * 16 + (lane & 15);
                int c = kk + (lane >> 4) * 8;
                uint32_t off = (uint32_t)(r * TG_STRIDE + c) * 2;
                ldm_x4(ah[mb], bA_h + off);
                ldm_x4(al[mb], bA_l + off);
            }
            #pragma unroll
            for (int nb = 0; nb < NB16; nb++) {
                int r = wn + nb * 16 + ((lane >> 4) << 3) + (lane & 7);
                int c = kk + ((lane >> 3) & 1) * 8;
                uint32_t off = (uint32_t)(r * TG_STRIDE + c) * 2;
                uint32_t bh[4], bl[4];
                ldm_x4(bh, bB_h + off);
                ldm_x4(bl, bB_l + off);
                #pragma unroll
                for (int mb = 0; mb < 2; mb++) {
                    mma16816(acc[mb][2*nb+0], ah[mb], bh[0], bh[1]);
                    mma16816(acc[mb][2*nb+1], ah[mb], bh[2], bh[3]);
                    mma16816(acc[mb][2*nb+0], ah[mb], bl[0], bl[1]);
                    mma16816(acc[mb][2*nb+1], ah[mb], bl[2], bl[3]);
                    mma16816(acc[mb][2*nb+0], al[mb], bh[0], bh[1]);
                    mma16816(acc[mb][2*nb+1], al[mb], bh[2], bh[3]);
                }
            }
        }
    };

    int nch = K >> 5;
    issue(0, 0);
    if (nch > 1) issue(1, 32);
    for (int ck = 0; ck < nch; ck++) {
        if (ck + 2 < nch) {
            issue((ck + 2) % 3, (ck + 2) << 5);
            asm volatile("cp.async.wait_group 2;" ::: "memory");
        } else if (ck + 1 < nch) {
            asm volatile("cp.async.wait_group 1;" ::: "memory");
        } else {
            asm volatile("cp.async.wait_group 0;" ::: "memory");
        }
        __syncthreads();
        compute(ck % 3);
        __syncthreads();
    }

    int g = lane >> 2, tg = lane & 3;

    if constexpr (BM == 128) {
        if (c0v) {
            float mn = 1e30f, mx = -1e30f;
            #pragma unroll
            for (int mb = 0; mb < 2; mb++) {
                #pragma unroll
                for (int ug = 0; ug < 2; ug++) {
                    int cb = col0 + wn + ug*32;
                    int u0 = ((cb >> 5) << 3) + 2*tg;
                    float iv[4], fv[4], gv[4], ov[4];
                    #pragma unroll
                    for (int e = 0; e < 4; e++) {
                        int co = 2*tg + (e & 1);
                        iv[e] = acc[mb][ug*4+0][e] + bias[cb + 0  + co];
                        fv[e] = acc[mb][ug*4+1][e] + bias[cb + 8  + co];
                        gv[e] = acc[mb][ug*4+2][e] + bias[cb + 16 + co];
                        ov[e] = acc[mb][ug*4+3][e] + bias[cb + 24 + co];
                    }
                    #pragma unroll
                    for (int half = 0; half < 2; half++) {
                        int row = row0 + wm + mb*16 + g + half*8;
                        float2 cc = *(const float2*)(c0v + (size_t)row*256 + u0);
                        float cin[2] = {cc.x, cc.y};
                        float hh[2], c2[2];
                        #pragma unroll
                        for (int e2 = 0; e2 < 2; e2++) {
                            int e = half*2 + e2;
                            float si = fsig(iv[e]);
                            float sf = fsig(fv[e]);
                            float so = fsig(ov[e]);
                            c2[e2] = sf * cin[e2] + si * ftanh(gv[e]);
                            hh[e2] = so * ftanh(c2[e2]);
                            mn = fminf(mn, hh[e2]); mx = fmaxf(mx, hh[e2]);
                        }
                        *(float2*)(hOut + (size_t)row*256 + u0) = make_float2(hh[0], hh[1]);
                        *(float2*)(cOut + (size_t)row*256 + u0) = make_float2(c2[0], c2[1]);
                    }
                }
            }
            __shared__ float smn[256], smx[256];
            smn[tid] = mn; smx[tid] = mx; __syncthreads();
            for (int s = 128; s > 0; s >>= 1) {
                if (tid < s) {
                    smn[tid] = fminf(smn[tid], smn[tid+s]);
                    smx[tid] = fmaxf(smx[tid], smx[tid+s]);
                }
                __syncthreads();
            }
            if (tid == 0) {
                int bid = blockIdx.y * gridDim.x + blockIdx.x;
                g_pmin[bid] = smn[0]; g_pmax[bid] = smx[0];
            }
            return;
        }
    }

    float cia[2][2] = {}, cja[2][2] = {};
    #pragma unroll
    for (int mb = 0; mb < 2; mb++) {
        #pragma unroll
        for (int n8 = 0; n8 < NB; n8++) {
            int row = row0 + wm + mb * 16 + g;
            int col = col0 + wn + n8 * 8 + 2 * tg;
            float b0 = bias ? bias[col]   : 0.f;
            float b1 = bias ? bias[col+1] : 0.f;
            float v00 = acc[mb][n8][0] + b0, v01 = acc[mb][n8][1] + b1;
            float v10 = acc[mb][n8][2] + b0, v11 = acc[mb][n8][3] + b1;
            if (Shi) {
                size_t d0 = (size_t)row * ldS + col;
                size_t d1 = (size_t)(row + 8) * ldS + col;
                bf16split(v00, &Shi[d0],   &Slo[d0]);
                bf16split(v01, &Shi[d0+1], &Slo[d0+1]);
                bf16split(v10, &Shi[d1],   &Slo[d1]);
                bf16split(v11, &Shi[d1+1], &Slo[d1+1]);
            }
            if (hwT) {
                hwT[(size_t)col*NA + row]         = v00;
                hwT[(size_t)(col+1)*NA + row]     = v01;
                hwT[(size_t)col*NA + row + 8]     = v10;
                hwT[(size_t)(col+1)*NA + row + 8] = v11;
            }
            if (aivec) {
                float a0 = aivec[col], a1 = aivec[col+1];
                float j0 = ajvec[col], j1 = ajvec[col+1];
                cia[mb][0] += v00*a0 + v01*a1;
                cia[mb][1] += v10*a0 + v11*a1;
                cja[mb][0] += v00*j0 + v01*j1;
                cja[mb][1] += v10*j0 + v11*j1;
            }
        }
    }
    if (aivec) {
        int hh = (col0 + wn) / Gh;
        #pragma unroll
        for (int mb = 0; mb < 2; mb++) {
            #pragma unroll
            for (int hf = 0; hf < 2; hf++) {
                float ci = cia[mb][hf], cj = cja[mb][hf];
                ci += __shfl_xor_sync(0xffffffffu, ci, 1);
                ci += __shfl_xor_sync(0xffffffffu, ci, 2);
                cj += __shfl_xor_sync(0xffffffffu, cj, 1);
                cj += __shfl_xor_sync(0xffffffffu, cj, 2);
                if (tg == 0) {
                    int row = row0 + wm + mb * 16 + g + hf * 8;
                    atomicAdd(&g_ci[hh*NA + row], ci);
                    atomicAdd(&g_cj[hh*NA + row], cj);
                }
            }
        }
    }
}

// ---------------- fake-quant A ----------------------
__global__ void quantA(const float* __restrict__ x,
                       __nv_bfloat16* __restrict__ hi, __nv_bfloat16* __restrict__ lo,
                       int npart)
{
    __shared__ float smn[256], smx[256];
    __shared__ float sparam[2];
    float mn = 1e30f, mx = -1e30f;
    for (int i = threadIdx.x; i < npart; i += 256) {
        mn = fminf(mn, g_pmin[i]); mx = fmaxf(mx, g_pmax[i]);
    }
    smn[threadIdx.x] = mn; smx[threadIdx.x] = mx; __syncthreads();
    for (int s = 128; s > 0; s >>= 1) {
        if (threadIdx.x < s) {
            smn[threadIdx.x] = fminf(smn[threadIdx.x], smn[threadIdx.x+s]);
            smx[threadIdx.x] = fmaxf(smx[threadIdx.x], smx[threadIdx.x+s]);
        }
        __syncthreads();
    }
    if (threadIdx.x == 0) {
        float a = smn[0], b = smx[0];
        if (a == b) { a -= 0.01f; b += 0.01f; }
        float scale = (b - a) / 255.f;
        sparam[0] = scale;
        sparam[1] = rintf(-a / scale);
    }
    __syncthreads();
    float scale = sparam[0], zp = sparam[1];

    float part = 0.f;
    #pragma unroll
    for (int l = 0; l < 4; l++) {
        int i = blockIdx.x*256 + threadIdx.x + l*65536;
        float4 t = ((const float4*)x)[i];
        float ts[4] = {t.x, t.y, t.z, t.w};
        float ds[4];
        #pragma unroll
        for (int q = 0; q < 4; q++) {
            float r = rintf(ts[q]/scale + zp);
            r = fminf(fmaxf(r, 0.f), 255.f);
            float d = (r - zp) * scale;
            ds[q] = d;
            part += __log2f(fmaf(510.f, fabsf(d), 1.f));
        }
        split4(ds, &hi[i*4], &lo[i*4]);
    }
    __shared__ float sd[256];
    sd[threadIdx.x] = part; __syncthreads();
    for (int s = 128; s > 0; s >>= 1) { if (threadIdx.x < s) sd[threadIdx.x] += sd[threadIdx.x+s]; __syncthreads(); }
    if (threadIdx.x == 0) atomicAdd(&g_loss, sd[0]);
}

// ---------------- fake-quant T ----------------------
__global__ void quantT(const float* __restrict__ inT,
                       __nv_bfloat16* __restrict__ hi, __nv_bfloat16* __restrict__ lo,
                       int npart)
{
    __shared__ float tile[32][33];
    __shared__ float smn[256], smx[256];
    __shared__ float sparam[2];
    int tx = threadIdx.x, ty = threadIdx.y;
    int tid = ty*32 + tx;

    float mn = (tid < npart) ? g_pmin[tid] : 1e30f;
    float mx = (tid < npart) ? g_pmax[tid] : -1e30f;
    smn[tid] = mn; smx[tid] = mx; __syncthreads();
    for (int s = 128; s > 0; s >>= 1) {
        if (tid < s) {
            smn[tid] = fminf(smn[tid], smn[tid+s]);
            smx[tid] = fmaxf(smx[tid], smx[tid+s]);
        }
        __syncthreads();
    }
    if (tid == 0) {
        float a = smn[0], b = smx[0];
        if (a == b) { a -= 0.01f; b += 0.01f; }
        float scale = (b - a) / 255.f;
        sparam[0] = scale;
        sparam[1] = rintf(-a / scale);
    }
    __syncthreads();
    float scale = sparam[0], zp = sparam[1];

    int c0 = blockIdx.y * 32;
    float part = 0.f;
    #pragma unroll 1
    for (int nt = 0; nt < 4; nt++) {
        int n0 = blockIdx.x * 128 + nt * 32;
        for (int cc = ty; cc < 32; cc += 8) {
            float t = inT[(size_t)(c0+cc)*NA + n0 + tx];
            float r = rintf(t/scale + zp);
            r = fminf(fmaxf(r, 0.f), 255.f);
            float d = (r - zp) * scale;
            tile[cc][tx] = d;
            part += __log2f(fmaf(510.f, fabsf(d), 1.f));
        }
        __syncthreads();
        for (int nn = ty; nn < 32; nn += 8) {
            float d = tile[tx][nn];
            size_t o = (size_t)(n0+nn)*256 + c0 + tx;
            bf16split(d, &hi[o], &lo[o]);
        }
        __syncthreads();
    }
    __shared__ float sd[256];
    sd[tid] = part; __syncthreads();
    for (int s = 128; s > 0; s >>= 1) { if (tid < s) sd[tid] += sd[tid+s]; __syncthreads(); }
    if (tid == 0) atomicAdd(&g_loss, sd[0]);
}

// ---------------- sortk ----------------
__global__ void __launch_bounds__(1024)
sortk()
{
    extern __shared__ char sms[];
    float* key = (float*)sms;
    int*   idx = (int*)(key + NA);
    float* sA  = (float*)(idx + NA);
    float* sB  = sA + NA;
    __shared__ float wsum[32];
    int h = blockIdx.x;
    int tid = threadIdx.x, lane = tid & 31, warp = tid >> 5;

    for (int i = tid; i < NA; i += 1024) { key[i] = g_cj[h*NA + i]; idx[i] = i; }
    __syncthreads();
    for (int k = 2; k <= NA; k <<= 1) {
        int j = k >> 1;
        for (; j >= 128; j >>= 1) {
            #pragma unroll 2
            for (int p = tid; p < NA/2; p += 1024) {
                int i = ((p & ~(j-1)) << 1) | (p & (j-1));
                int il = i | j;
                bool up = ((i & k) == 0);
                float a = key[i], b = key[il];
                if (up ? (a > b) : (a < b)) {
                    key[i] = b; key[il] = a;
                    int tmp = idx[i]; idx[i] = idx[il]; idx[il] = tmp;
                }
            }
            __syncthreads();
        }
        for (; j >= 1; j >>= 1) {
            #pragma unroll 2
            for (int q = lane; q < 64; q += 32) {
                int p = (warp << 6) | q;
                int i = ((p & ~(j-1)) << 1) | (p & (j-1));
                int il = i | j;
                bool up = ((i & k) == 0);
                float a = key[i], b = key[il];
                if (up ? (a > b) : (a < b)) {
                    key[i] = b; key[il] = a;
                    int tmp = idx[i]; idx[i] = idx[il]; idx[il] = tmp;
                }
            }
            __syncwarp();
        }
        __syncthreads();
    }
    float cm = key[NA-1];

    int t0 = tid * 4;
    float kw0 = key[t0], kw1 = key[t0+1], kw2 = key[t0+2], kw3 = key[t0+3];
    float wB0 = expf(0.2f*(kw0-cm)), wB1 = expf(0.2f*(kw1-cm));
    float wB2 = expf(0.2f*(kw2-cm)), wB3 = expf(0.2f*(kw3-cm));
    float wA0 = expf(kw0-cm), wA1 = expf(kw1-cm), wA2 = expf(kw2-cm), wA3 = expf(kw3-cm);
    *(int4*)&g_sidx[h*NA + t0] = make_int4(idx[t0], idx[t0+1], idx[t0+2], idx[t0+3]);
    *(float4*)&g_wA[h*NA + t0] = make_float4(wA0, wA1, wA2, wA3);
    *(float4*)&g_wB[h*NA + t0] = make_float4(wB0, wB1, wB2, wB3);

    {
        float v0 = wB0, v1 = v0+wB1, v2 = v1+wB2, v3 = v2+wB3;
        float tot = v3, s = tot;
        #pragma unroll
        for (int o = 1; o < 32; o <<= 1) { float u = __shfl_up_sync(0xffffffffu, s, o); if (lane >= o) s += u; }
        if (lane == 31) wsum[warp] = s;
        __syncthreads();
        if (warp == 0) {
            float y = wsum[lane];
            #pragma unroll
            for (int o = 1; o < 32; o <<= 1) { float u = __shfl_up_sync(0xffffffffu, y, o); if (lane >= o) y += u; }
            wsum[lane] = y;
        }
        __syncthreads();
        float off = (warp ? wsum[warp-1] : 0.f) + (s - tot);
        sB[t0] = off+v0; sB[t0+1] = off+v1; sB[t0+2] = off+v2; sB[t0+3] = off+v3;
    }
    __syncthreads();
    {
        int rb = NA - 4 - t0;
        float a0 = expf(key[rb]-cm),   a1 = expf(key[rb+1]-cm);
        float a2 = expf(key[rb+2]-cm), a3 = expf(key[rb+3]-cm);
        float u0 = a3, u1 = u0+a2, u2 = u1+a1, u3 = u2+a0;
        float tot = u3, s = tot;
        #pragma unroll
        for (int o = 1; o < 32; o <<= 1) { float u = __shfl_up_sync(0xffffffffu, s, o); if (lane >= o) s += u; }
        if (lane == 31) wsum[warp] = s;
        __syncthreads();
        if (warp == 0) {
            float y = wsum[lane];
            #pragma unroll
            for (int o = 1; o < 32; o <<= 1) { float u = __shfl_up_sync(0xffffffffu, y, o); if (lane >= o) y += u; }
            wsum[lane] = y;
        }
        __syncthreads();
        float off = (warp ? wsum[warp-1] : 0.f) + (s - tot);
        sA[rb] = off+u3; sA[rb+1] = off+u2; sA[rb+2] = off+u1; sA[rb+3] = off+u0;
    }
    __syncthreads();

    for (int l = 0; l < 4; l++) {
        int n = tid + l*1024;
        float cin = g_ci[h*NA + n];
        float t = -cin;
        int lo = 0, hi = NA;
        while (lo < hi) {
            int mid = (lo + hi) >> 1;
            if (key[mid] <= t) lo = mid + 1; else hi = mid;
        }
        float r = expf(0.8f * (cin + cm));
        float A = (lo < NA) ? sA[lo]     : 0.f;
        float B = (lo > 0)  ? sB[lo - 1] : 0.f;
        g_kcount[h*NA + n] = lo;
        g_rn[h*NA + n]     = r;
        g_invd[h*NA + n]   = 1.f / (r*A + B);
        g_ci[h*NA + n] = 0.f;
        g_cj[h*NA + n] = 0.f;
    }
}

// ---------------- scomb: x staged in smem, scans reuse it --------------------
__global__ void __launch_bounds__(512)
scomb(const float* __restrict__ bias, float* __restrict__ outT,
      int G, int do_elu, int do_mm)
{
    __shared__ float s_x[NA];
    __shared__ float s_pre[NA];
    __shared__ float s_suf[NA];
    __shared__ float wsum[16];
    int c = blockIdx.x;
    int h = c / G;
    int tid = threadIdx.x, lane = tid & 31, warp = tid >> 5;
    int t0 = tid * 8;
    const float* xrow = g_hWT + (size_t)c * NA;

    // stage x in sorted order (gather once)
    {
        int4 iva = *(const int4*)&g_sidx[h*NA + t0];
        int4 ivb = *(const int4*)&g_sidx[h*NA + t0 + 4];
        s_x[t0+0] = xrow[iva.x]; s_x[t0+1] = xrow[iva.y];
        s_x[t0+2] = xrow[iva.z]; s_x[t0+3] = xrow[iva.w];
        s_x[t0+4] = xrow[ivb.x]; s_x[t0+5] = xrow[ivb.y];
        s_x[t0+6] = xrow[ivb.z]; s_x[t0+7] = xrow[ivb.w];
    }
    __syncthreads();

    // prefix of wB*x
    {
        float4 wa = *(const float4*)&g_wB[h*NA + t0];
        float4 wb = *(const float4*)&g_wB[h*NA + t0 + 4];
        float v[8];
        float run = wa.x * s_x[t0+0];   v[0] = run;
        run += wa.y * s_x[t0+1];        v[1] = run;
        run += wa.z * s_x[t0+2];        v[2] = run;
        run += wa.w * s_x[t0+3];        v[3] = run;
        run += wb.x * s_x[t0+4];        v[4] = run;
        run += wb.y * s_x[t0+5];        v[5] = run;
        run += wb.z * s_x[t0+6];        v[6] = run;
        run += wb.w * s_x[t0+7];        v[7] = run;
        float tot = run, s = tot;
        #pragma unroll
        for (int o = 1; o < 32; o <<= 1) { float u = __shfl_up_sync(0xffffffffu, s, o); if (lane >= o) s += u; }
        if (lane == 31) wsum[warp] = s;
        __syncthreads();
        if (warp == 0 && lane < 16) {
            float y = wsum[lane];
            #pragma unroll
            for (int o = 1; o < 16; o <<= 1) { float u = __shfl_up_sync(0xffffu, y, o); if (lane >= o) y += u; }
            wsum[lane] = y;
        }
        __syncthreads();
        float off = (warp ? wsum[warp-1] : 0.f) + (s - tot);
        #pragma unroll
        for (int e = 0; e < 8; e++) s_pre[t0+e] = off + v[e];
    }
    __syncthreads();
    // suffix of wA*x (reversed prefix)
    {
        int rb = NA - 8 - t0;
        float4 wa = *(const float4*)&g_wA[h*NA + rb];
        float4 wb = *(const float4*)&g_wA[h*NA + rb + 4];
        float ws[8] = { wa.x, wa.y, wa.z, wa.w, wb.x, wb.y, wb.z, wb.w };
        float u[8];
        float run = ws[7]*s_x[rb+7];  u[0] = run;
        #pragma unroll
        for (int e = 1; e < 8; e++) { run += ws[7-e]*s_x[rb+7-e]; u[e] = run; }
        float tot = run, s = tot;
        #pragma unroll
        for (int o = 1; o < 32; o <<= 1) { float uu = __shfl_up_sync(0xffffffffu, s, o); if (lane >= o) s += uu; }
        if (lane == 31) wsum[warp] = s;
        __syncthreads();
        if (warp == 0 && lane < 16) {
            float y = wsum[lane];
            #pragma unroll
            for (int o = 1; o < 16; o <<= 1) { float uu = __shfl_up_sync(0xffffu, y, o); if (lane >= o) y += uu; }
            wsum[lane] = y;
        }
        __syncthreads();
        float off = (warp ? wsum[warp-1] : 0.f) + (s - tot);
        #pragma unroll
        for (int e = 0; e < 8; e++) s_suf[rb + 7 - e] = off + u[e];
    }
    __syncthreads();

    float bv = bias[c];
    float mn = 1e30f, mx = -1e30f;
    #pragma unroll
    for (int l = 0; l < 8; l++) {
        int n = tid + l*512;
        int k = g_kcount[h*NA + n];
        float r = g_rn[h*NA + n];
        float invd = g_invd[h*NA + n];
        float Av = (k < NA) ? s_suf[k]     : 0.f;
        float Bv = (k > 0)  ? s_pre[k - 1] : 0.f;
        float val = (r*Av + Bv) * invd + bv;
        if (do_elu) val = (val > 0.f) ? val : expm1f(val);
        mn = fminf(mn, val); mx = fmaxf(mx, val);
        outT[(size_t)c*NA + n] = val;
    }
    if (do_mm) {
        __shared__ float smn[512], smx[512];
        smn[tid] = mn; smx[tid] = mx; __syncthreads();
        for (int s = 256; s > 0; s >>= 1) {
            if (tid < s) {
                smn[tid] = fminf(smn[tid], smn[tid+s]);
                smx[tid] = fmaxf(smx[tid], smx[tid+s]);
            }
            __syncthreads();
        }
        if (tid == 0) { g_pmin[c] = smn[0]; g_pmax[c] = smx[0]; }
    }
}

// ---------------- fused policy + value head (+ loss write) ----------------
__global__ void __launch_bounds__(256)
policyk(const float* __restrict__ A0, const float* __restrict__ A1T,
        const float* __restrict__ Wa, const float* __restrict__ ba,
        const float* __restrict__ Wv, const float* __restrict__ bv,
        float* __restrict__ out_logp, float* __restrict__ out_value,
        float* __restrict__ out_loss)
{
    if (blockIdx.x == 0 && threadIdx.x == 0) out_loss[0] = g_loss;
    __shared__ float As[16][68];
    __shared__ float Bs[16][68];
    __shared__ float Ss[64][65];
    int tid = threadIdx.x;
    int tx = tid % 16, ty = tid / 16;
    int row0 = blockIdx.x * 64;
    float acc[4][4] = {};
    float vacc = 0.f;

    for (int k0 = 0; k0 < 512; k0 += 16) {
        if (k0 < 256) {
            int lin = tid * 4;
            int m = lin >> 4, kk = lin & 15;
            float4 v = *(const float4*)&A0[(size_t)(row0+m)*256 + k0 + kk];
            As[kk+0][m] = v.x; As[kk+1][m] = v.y; As[kk+2][m] = v.z; As[kk+3][m] = v.w;
        } else {
            int lin = tid * 4;
            int kk = lin >> 6, m4 = lin & 63;
            float4 v = *(const float4*)&A1T[(size_t)(k0-256+kk)*NA + row0 + m4];
            *(float4*)&As[kk][m4] = v;
        }
        {
            int lin = tid * 4;
            int kk = lin >> 6, n = lin & 63;
            *(float4*)&Bs[kk][n] = *(const float4*)&Wa[(size_t)(k0+kk)*64 + n];
        }
        __syncthreads();
        #pragma unroll
        for (int kk = 0; kk < 16; kk++) {
            float a[4], bb[4];
            #pragma unroll
            for (int i = 0; i < 4; i++) a[i] = As[kk][ty*4+i];
            #pragma unroll
            for (int j = 0; j < 4; j++) bb[j] = Bs[kk][tx*4+j];
            #pragma unroll
            for (int i = 0; i < 4; i++)
                #pragma unroll
                for (int j = 0; j < 4; j++)
                    acc[i][j] = fmaf(a[i], bb[j], acc[i][j]);
        }
        if (tid < 64) {
            #pragma unroll
            for (int kk = 0; kk < 16; kk++)
                vacc = fmaf(As[kk][tid], Wv[k0+kk], vacc);
        }
        __syncthreads();
    }
    if (tid < 64) out_value[row0 + tid] = vacc + bv[0];

    #pragma unroll
    for (int i = 0; i < 4; i++)
        #pragma unroll
        for (int j = 0; j < 4; j++)
            Ss[ty*4+i][tx*4+j] = acc[i][j] + ba[tx*4+j];
    __syncthreads();

    int row = tid >> 2, quad = tid & 3;
    float m = -1e30f;
    #pragma unroll
    for (int c = 0; c < 16; c++) m = fmaxf(m, Ss[row][quad*16 + c]);
    m = fmaxf(m, __shfl_xor_sync(0xffffffffu, m, 1));
    m = fmaxf(m, __shfl_xor_sync(0xffffffffu, m, 2));
    float s = 0.f;
    #pragma unroll
    for (int c = 0; c < 16; c++) s += expf(Ss[row][quad*16 + c] - m);
    s += __shfl_xor_sync(0xffffffffu, s, 1);
    s += __shfl_xor_sync(0xffffffffu, s, 2);
    float lse = m + logf(s);
    #pragma unroll
    for (int c = 0; c < 16; c++)
        out_logp[(size_t)(row0+row)*64 + quad*16 + c] = Ss[row][quad*16 + c] - lse;
}

// ---------------- host ----------------
extern "C" void kernel_launch(void* const* d_in, const int* in_sizes, int n_in,
                              void* d_out, int out_size)
{
    const float* obs  = (const float*)d_in[0];
    const float* h0   = (const float*)d_in[1];
    const float* c0   = (const float*)d_in[2];
    const float* Wobs = (const float*)d_in[3];
    const float* bobs = (const float*)d_in[4];
    const float* Wih  = (const float*)d_in[5];
    const float* Whh  = (const float*)d_in[6];
    const float* bih  = (const float*)d_in[7];
    const float* bhh  = (const float*)d_in[8];
    const float* W1   = (const float*)d_in[9];
    const float* ai1  = (const float*)d_in[10];
    const float* aj1  = (const float*)d_in[11];
    const float* b1   = (const float*)d_in[12];
    const float* W2   = (const float*)d_in[13];
    const float* ai2  = (const float*)d_in[14];
    const float* aj2  = (const float*)d_in[15];
    const float* b2   = (const float*)d_in[16];
    const float* Wv   = (const float*)d_in[17];
    const float* bv   = (const float*)d_in[18];
    const float* Wa   = (const float*)d_in[19];
    const float* ba   = (const float*)d_in[20];

    float* out       = (float*)d_out;
    float* out_logp  = out;
    float* out_value = out + NA*ACT;
    float* out_h     = out_value + NA;
    float* out_c     = out_h + NA*HD;
    float* out_loss  = out_c + NA*HD;

    float *p_hWT, *p_commT, *p_bsum;
    __nv_bfloat16 *p_Ah, *p_Al, *p_A2h, *p_A2l;
    __nv_bfloat16 *p_B0h, *p_B0l, *p_Bgh, *p_Bgl, *p_B1h, *p_B1l, *p_B2h, *p_B2l;
    cudaGetSymbolAddress((void**)&p_hWT,    g_hWT);
    cudaGetSymbolAddress((void**)&p_commT,  g_commT);
    cudaGetSymbolAddress((void**)&p_bsum,   g_bsum);
    cudaGetSymbolAddress((void**)&p_Ah,     g_Ah);
    cudaGetSymbolAddress((void**)&p_Al,     g_Al);
    cudaGetSymbolAddress((void**)&p_A2h,    g_A2h);
    cudaGetSymbolAddress((void**)&p_A2l,    g_A2l);
    cudaGetSymbolAddress((void**)&p_B0h,    g_B0h);
    cudaGetSymbolAddress((void**)&p_B0l,    g_B0l);
    cudaGetSymbolAddress((void**)&p_Bgh,    g_Bgh);
    cudaGetSymbolAddress((void**)&p_Bgl,    g_Bgl);
    cudaGetSymbolAddress((void**)&p_B1h,    g_B1h);
    cudaGetSymbolAddress((void**)&p_B1l,    g_B1l);
    cudaGetSymbolAddress((void**)&p_B2h,    g_B2h);
    cudaGetSymbolAddress((void**)&p_B2l,    g_B2l);

    const int SM128 = TG_SMEM_BYTES(128);
    const int SM64  = TG_SMEM_BYTES(64);
    const int SMSORT = NA * 16;
    cudaFuncSetAttribute((const void*)tgemm<128>, cudaFuncAttributeMaxDynamicSharedMemorySize, SM128);
    cudaFuncSetAttribute((const void*)tgemm<64>,  cudaFuncAttributeMaxDynamicSharedMemorySize, SM64);
    cudaFuncSetAttribute((const void*)sortk,      cudaFuncAttributeMaxDynamicSharedMemorySize, SMSORT);

    // 1. prep (vectorized)
    wprep<<<(WVTOT + 255)/256, 256>>>(obs, h0, Wobs, Wih, Whh, W1, W2, bih, bhh, bobs);
    // 2. weight-product GEMM -> Bg cols 0..255 (split output)
    tgemm<64><<<dim3(2, 16), 256, SM64>>>(p_A2h, p_A2l, p_B0h, p_B0l, nullptr,
                                          p_Bgh, p_Bgl, 512,
                                          nullptr, nullptr, nullptr, 0,
                                          nullptr, nullptr, nullptr, 256, 256);
    // 3. gates GEMM ([obs|h0] @ Bg^T) + fused LSTM -> out_h, out_c, minmax[256]
    tgemm<128><<<dim3(8, 32), 256, SM128>>>(p_Ah, p_Al, p_Bgh, p_Bgl, p_bsum,
                                            nullptr, nullptr, 0,
                                            nullptr, nullptr, nullptr, 0,
                                            c0, out_h, out_c, 1024, 512);
    // 4. quant #1 -> splits into A2
    quantA<<<256, 256>>>(out_h, p_A2h, p_A2l, 256);
    // 5. GAT1 projection -> hWT + fused ci/cj
    tgemm<64><<<dim3(2, 64), 256, SM64>>>(p_A2h, p_A2l, p_B1h, p_B1l, nullptr,
                                          nullptr, nullptr, 0,
                                          p_hWT, ai1, aj1, 64,
                                          nullptr, nullptr, nullptr, 256, 256);
    // 6-7. GAT1 attention
    sortk<<<4, 1024, SMSORT>>>();
    scomb<<<256, 512>>>(b1, p_commT, 64, 1, 1);
    // 8. quant #2 (transposed input)
    quantT<<<dim3(NA/128, 8), dim3(32, 8)>>>(p_commT, p_A2h, p_A2l, 256);
    // 9. GAT2 projection
    tgemm<64><<<dim3(2, 64), 256, SM64>>>(p_A2h, p_A2l, p_B2h, p_B2l, nullptr,
                                          nullptr, nullptr, 0,
                                          p_hWT, ai2, aj2, 256,
                                          nullptr, nullptr, nullptr, 256, 256);
    // 10-11. GAT2 attention
    sortk<<<1, 1024, SMSORT>>>();
    scomb<<<256, 512>>>(b2, p_commT, 256, 0, 0);
    // 12. fused policy + value heads + loss
    policyk<<<NA/64, 256>>>(out_h, p_commT, Wa, ba, Wv, bv, out_logp, out_value, out_loss);
}

// round 15
// speedup vs baseline: 1.0749x; 1.0241x over previous
#include <cuda_runtime.h>
#include <cuda_bf16.h>
#include <math.h>
#include <stdint.h>

#define NA   4096
#define HD   256
#define HG   256
#define ACT  64
#define MMB  1024

// ---------------- device scratch ----------------
__device__ float g_hWT[HG*NA];
__device__ float g_commT[HG*NA];
__device__ float g_bsum[4*HD];
__device__ __nv_bfloat16 g_Ah[NA*512];
__device__ __nv_bfloat16 g_Al[NA*512];
__device__ __nv_bfloat16 g_A2h[NA*256];
__device__ __nv_bfloat16 g_A2l[NA*256];
__device__ __nv_bfloat16 g_B0h[256*256], g_B0l[256*256];
__device__ __nv_bfloat16 g_Bgh[1024*512], g_Bgl[1024*512];
__device__ __nv_bfloat16 g_B1h[256*256], g_B1l[256*256];
__device__ __nv_bfloat16 g_B2h[256*256], g_B2l[256*256];
__device__ float g_ci[4*NA];
__device__ float g_cj[4*NA];
__device__ int   g_kcount[4*NA];
__device__ int   g_sidx[4*NA];
__device__ float g_wA[4*NA];
__device__ float g_wB[4*NA];
__device__ float g_rn[4*NA];
__device__ float g_invd[4*NA];
__device__ float g_pmin[MMB];
__device__ float g_pmax[MMB];
__device__ float g_loss;

__device__ __forceinline__ void bf16split(float x, __nv_bfloat16* hi, __nv_bfloat16* lo) {
    __nv_bfloat16 h = __float2bfloat16(x);
    *hi = h;
    *lo = __float2bfloat16(x - __bfloat162float(h));
}
__device__ __forceinline__ float fsig(float x) { return 1.f / (1.f + __expf(-x)); }
__device__ __forceinline__ float ftanh(float x) {
    float ax = fabsf(x);
    float e = __expf(-2.f * ax);
    float t = (1.f - e) / (1.f + e);
    return copysignf(t, x);
}
__device__ __forceinline__ void split4(const float* v, __nv_bfloat16* hi, __nv_bfloat16* lo) {
    __nv_bfloat16 h[4], l[4];
    #pragma unroll
    for (int e = 0; e < 4; e++) bf16split(v[e], &h[e], &l[e]);
    *(uint2*)hi = *(uint2*)h;
    *(uint2*)lo = *(uint2*)l;
}

// ---------------- fused prep (vectorized) ----------------
#define WV0 (NA*64)
#define WV1 (WV0 + NA*64)
#define WV2 (WV1 + 16384)
#define WV3 (WV2 + 65536)
#define WV4 (WV3 + 65536)
#define WV5 (WV4 + 16384)
#define WV6 (WV5 + 16384)
#define WV7 (WV6 + 4096)
#define WVTOT (WV7 + 32768)
__global__ void wprep(const float* __restrict__ obs, const float* __restrict__ h0,
                      const float* __restrict__ Wobs,
                      const float* __restrict__ Wih, const float* __restrict__ Whh,
                      const float* __restrict__ W1, const float* __restrict__ W2,
                      const float* __restrict__ bih, const float* __restrict__ bhh,
                      const float* __restrict__ bobs)
{
    int idx = blockIdx.x*256 + threadIdx.x;
    if (idx == 0) g_loss = 0.f;
    if (idx < WV0) {
        int j = idx * 4;
        int n = j >> 8, k = j & 255;
        int d = n*512 + k;
        float4 v = *(const float4*)(obs + j);
        split4(&v.x, &g_Ah[d], &g_Al[d]);
    } else if (idx < WV1) {
        int j = (idx - WV0) * 4;
        int n = j >> 8, k = j & 255;
        int d = n*512 + 256 + k;
        float4 v = *(const float4*)(h0 + j);
        split4(&v.x, &g_Ah[d], &g_Al[d]);
    } else if (idx < WV2) {
        int j = (idx - WV1) * 4;
        float4 v = *(const float4*)(Wobs + j);
        split4(&v.x, &g_B0h[j], &g_B0l[j]);
    } else if (idx < WV3) {
        int j = (idx - WV2) * 4;
        int r = j >> 8, k = j & 255;
        int G = (r >> 3) & 3;
        int u = ((r >> 5) << 3) | (r & 7);
        float4 v = *(const float4*)(Wih + (G*256 + u)*256 + k);
        split4(&v.x, &g_A2h[j], &g_A2l[j]);
    } else if (idx < WV4) {
        int j = (idx - WV3) * 4;
        int r = j >> 8, k = j & 255;
        int G = (r >> 3) & 3;
        int u = ((r >> 5) << 3) | (r & 7);
        int d = r*512 + 256 + k;
        float4 v = *(const float4*)(Whh + (G*256 + u)*256 + k);
        split4(&v.x, &g_Bgh[d], &g_Bgl[d]);
    } else if (idx < WV5) {
        int j = (idx - WV4) * 4;
        int n = j >> 8, k = j & 255;
        float vv[4];
        #pragma unroll
        for (int e = 0; e < 4; e++) vv[e] = W1[(k+e)*256 + n];
        split4(vv, &g_B1h[j], &g_B1l[j]);
    } else if (idx < WV6) {
        int j = (idx - WV5) * 4;
        int n = j >> 8, k = j & 255;
        float vv[4];
        #pragma unroll
        for (int e = 0; e < 4; e++) vv[e] = W2[(k+e)*256 + n];
        split4(vv, &g_B2h[j], &g_B2l[j]);
    } else if (idx < WV7) {
        int j = (idx - WV6);
        float4 z = make_float4(0.f, 0.f, 0.f, 0.f);
        ((float4*)g_ci)[j] = z;
        ((float4*)g_cj)[j] = z;
    } else if (idx < WVTOT) {
        int t = idx - WV7;
        int r = t >> 5, lane = t & 31;
        int G = (r >> 3) & 3;
        int u = ((r >> 5) << 3) | (r & 7);
        int orow = G*256 + u;
        float s = 0.f;
        #pragma unroll
        for (int k = lane; k < 256; k += 32)
            s = fmaf(bobs[k], Wih[orow*256 + k], s);
        for (int o = 16; o > 0; o >>= 1) s += __shfl_down_sync(0xffffffffu, s, o);
        if (lane == 0) g_bsum[r] = s + bih[orow] + bhh[orow];
    }
}

// ---------------- mma.sync helpers ----------------
__device__ __forceinline__ uint32_t cvta_sm(const void* p) {
    uint32_t a;
    asm("{ .reg .u64 t; cvta.to.shared.u64 t, %1; cvt.u32.u64 %0, t; }" : "=r"(a) : "l"(p));
    return a;
}
__device__ __forceinline__ void ldm_x4(uint32_t (&d)[4], uint32_t addr) {
    asm volatile("ldmatrix.sync.aligned.m8n8.x4.shared.b16 {%0,%1,%2,%3}, [%4];"
        : "=r"(d[0]), "=r"(d[1]), "=r"(d[2]), "=r"(d[3]) : "r"(addr));
}
__device__ __forceinline__ void mma16816(float (&c)[4], const uint32_t (&a)[4],
                                         uint32_t b0, uint32_t b1) {
    asm volatile("mma.sync.aligned.m16n8k16.row.col.f32.bf16.bf16.f32 "
        "{%0,%1,%2,%3},{%4,%5,%6,%7},{%8,%9},{%0,%1,%2,%3};"
        : "+f"(c[0]), "+f"(c[1]), "+f"(c[2]), "+f"(c[3])
        : "r"(a[0]), "r"(a[1]), "r"(a[2]), "r"(a[3]), "r"(b0), "r"(b1));
}

// ---------------- split-bf16 tensor GEMM (BM=64), cp.async 3-stage -----------
#define TG_STRIDE 40
#define TG_STAGE_ELE(BM)   (2*(BM)*TG_STRIDE + 2*128*TG_STRIDE)
#define TG_SMEM_BYTES(BM)  (3 * TG_STAGE_ELE(BM) * 2)

template<int BM>
__global__ void __launch_bounds__(256, 2)
tgemm(const __nv_bfloat16* __restrict__ Ah, const __nv_bfloat16* __restrict__ Al,
      const __nv_bfloat16* __restrict__ Bh, const __nv_bfloat16* __restrict__ Bl,
      const float* __restrict__ bias,
      __nv_bfloat16* __restrict__ Shi, __nv_bfloat16* __restrict__ Slo, int ldS,
      float* __restrict__ hwT, const float* __restrict__ aivec,
      const float* __restrict__ ajvec, int Gh,
      int N, int K)
{
    constexpr int A_ELE = BM * TG_STRIDE;
    constexpr int B_ELE = 128 * TG_STRIDE;
    constexpr int STAGE = 2*A_ELE + 2*B_ELE;
    constexpr int NWM  = BM / 32;
    constexpr int WN   = 128 / (8 / NWM);
    constexpr int NB16 = WN / 16;
    constexpr int NB   = WN / 8;
    constexpr int A_U4 = BM * 4;
    constexpr int B_U4 = 512;
    constexpr int TOT_U4 = 2*A_U4 + 2*B_U4;

    extern __shared__ __nv_bfloat16 sm[];
    int tid = threadIdx.x, lane = tid & 31, wid = tid >> 5;
    int col0 = blockIdx.x * 128, row0 = blockIdx.y * BM;
    int wm = (wid % NWM) * 32, wn = (wid / NWM) * WN;
    uint32_t sb = cvta_sm(sm);

    float acc[2][NB][4] = {};

    auto issue = [&](int stage, int k0) {
        uint32_t stb = sb + (uint32_t)stage * STAGE * 2;
        #pragma unroll
        for (int l = 0; l < TOT_U4/256; l++) {
            int i = tid + l * 256;
            const __nv_bfloat16* src;
            int r, c8;
            uint32_t soff;
            if (i < 2*A_U4) {
                int a = i / A_U4, j = i % A_U4;
                r = j >> 2; c8 = j & 3;
                src = (a ? Al : Ah) + (size_t)(row0 + r) * K;
                soff = (uint32_t)a * A_ELE;
            } else {
                int i2 = i - 2*A_U4;
                int a = i2 / B_U4, j = i2 % B_U4;
                r = j >> 2; c8 = j & 3;
                src = (a ? Bl : Bh) + (size_t)(col0 + r) * K;
                soff = 2*A_ELE + (uint32_t)a * B_ELE;
            }
            uint32_t dst = stb + (soff + r * TG_STRIDE + c8 * 8) * 2;
            const __nv_bfloat16* g = src + k0 + c8 * 8;
            asm volatile("cp.async.cg.shared.global [%0], [%1], 16;" :: "r"(dst), "l"(g));
        }
        asm volatile("cp.async.commit_group;" ::: "memory");
    };

    auto compute = [&](int stage) {
        uint32_t stb = sb + (uint32_t)stage * STAGE * 2;
        uint32_t bA_h = stb, bA_l = stb + A_ELE*2;
        uint32_t bB_h = stb + 2*A_ELE*2, bB_l = stb + (2*A_ELE + B_ELE)*2;
        #pragma unroll
        for (int kk = 0; kk < 32; kk += 16) {
            uint32_t ah[2][4], al[2][4];
            #pragma unroll
            for (int mb = 0; mb < 2; mb++) {
                int r = wm + mb * 16 + (lane & 15);
                int c = kk + (lane >> 4) * 8;
                uint32_t off = (uint32_t)(r * TG_STRIDE + c) * 2;
                ldm_x4(ah[mb], bA_h + off);
                ldm_x4(al[mb], bA_l + off);
            }
            #pragma unroll
            for (int nb = 0; nb < NB16; nb++) {
                int r = wn + nb * 16 + ((lane >> 4) << 3) + (lane & 7);
                int c = kk + ((lane >> 3) & 1) * 8;
                uint32_t off = (uint32_t)(r * TG_STRIDE + c) * 2;
                uint32_t bh[4], bl[4];
                ldm_x4(bh, bB_h + off);
                ldm_x4(bl, bB_l + off);
                #pragma unroll
                for (int mb = 0; mb < 2; mb++) {
                    mma16816(acc[mb][2*nb+0], ah[mb], bh[0], bh[1]);
                    mma16816(acc[mb][2*nb+1], ah[mb], bh[2], bh[3]);
                    mma16816(acc[mb][2*nb+0], ah[mb], bl[0], bl[1]);
                    mma16816(acc[mb][2*nb+1], ah[mb], bl[2], bl[3]);
                    mma16816(acc[mb][2*nb+0], al[mb], bh[0], bh[1]);
                    mma16816(acc[mb][2*nb+1], al[mb], bh[2], bh[3]);
                }
            }
        }
    };

    int nch = K >> 5;
    issue(0, 0);
    if (nch > 1) issue(1, 32);
    for (int ck = 0; ck < nch; ck++) {
        if (ck + 2 < nch) {
            issue((ck + 2) % 3, (ck + 2) << 5);
            asm volatile("cp.async.wait_group 2;" ::: "memory");
        } else if (ck + 1 < nch) {
            asm volatile("cp.async.wait_group 1;" ::: "memory");
        } else {
            asm volatile("cp.async.wait_group 0;" ::: "memory");
        }
        __syncthreads();
        compute(ck % 3);
        __syncthreads();
    }

    int g = lane >> 2, tg = lane & 3;

    float cia[2][2] = {}, cja[2][2] = {};
    #pragma unroll
    for (int mb = 0; mb < 2; mb++) {
        #pragma unroll
        for (int n8 = 0; n8 < NB; n8++) {
            int row = row0 + wm + mb * 16 + g;
            int col = col0 + wn + n8 * 8 + 2 * tg;
            float b0 = bias ? bias[col]   : 0.f;
            float b1 = bias ? bias[col+1] : 0.f;
            float v00 = acc[mb][n8][0] + b0, v01 = acc[mb][n8][1] + b1;
            float v10 = acc[mb][n8][2] + b0, v11 = acc[mb][n8][3] + b1;
            if (Shi) {
                size_t d0 = (size_t)row * ldS + col;
                size_t d1 = (size_t)(row + 8) * ldS + col;
                bf16split(v00, &Shi[d0],   &Slo[d0]);
                bf16split(v01, &Shi[d0+1], &Slo[d0+1]);
                bf16split(v10, &Shi[d1],   &Slo[d1]);
                bf16split(v11, &Shi[d1+1], &Slo[d1+1]);
            }
            if (hwT) {
                hwT[(size_t)col*NA + row]         = v00;
                hwT[(size_t)(col+1)*NA + row]     = v01;
                hwT[(size_t)col*NA + row + 8]     = v10;
                hwT[(size_t)(col+1)*NA + row + 8] = v11;
            }
            if (aivec) {
                float a0 = aivec[col], a1 = aivec[col+1];
                float j0 = ajvec[col], j1 = ajvec[col+1];
                cia[mb][0] += v00*a0 + v01*a1;
                cia[mb][1] += v10*a0 + v11*a1;
                cja[mb][0] += v00*j0 + v01*j1;
                cja[mb][1] += v10*j0 + v11*j1;
            }
        }
    }
    if (aivec) {
        int hh = (col0 + wn) / Gh;
        #pragma unroll
        for (int mb = 0; mb < 2; mb++) {
            #pragma unroll
            for (int hf = 0; hf < 2; hf++) {
                float ci = cia[mb][hf], cj = cja[mb][hf];
                ci += __shfl_xor_sync(0xffffffffu, ci, 1);
                ci += __shfl_xor_sync(0xffffffffu, ci, 2);
                cj += __shfl_xor_sync(0xffffffffu, cj, 1);
                cj += __shfl_xor_sync(0xffffffffu, cj, 2);
                if (tg == 0) {
                    int row = row0 + wm + mb * 16 + g + hf * 8;
                    atomicAdd(&g_ci[hh*NA + row], ci);
                    atomicAdd(&g_cj[hh*NA + row], cj);
                }
            }
        }
    }
}

// ---------------- gates GEMM: 128x256 tile, 64x64 warp tiles, fused LSTM -----
// grid (N/256, M/128) = (4, 32) = 128 CTAs (single wave). 2-stage cp.async.
#define GW_A_ELE (128*TG_STRIDE)           // 5120 per A array
#define GW_B_ELE (256*TG_STRIDE)           // 10240 per B array
#define GW_STAGE (2*GW_A_ELE + 2*GW_B_ELE) // 30720 elems
#define GW_SMEM  (2 * GW_STAGE * 2)        // 122880 B

__global__ void __launch_bounds__(256, 1)
gatesk(const __nv_bfloat16* __restrict__ Ah, const __nv_bfloat16* __restrict__ Al,
       const __nv_bfloat16* __restrict__ Bh, const __nv_bfloat16* __restrict__ Bl,
       const float* __restrict__ bias,
       const float* __restrict__ c0v, float* __restrict__ hOut, float* __restrict__ cOut,
       int K)
{
    extern __shared__ __nv_bfloat16 sm[];
    int tid = threadIdx.x, lane = tid & 31, wid = tid >> 5;
    int col0 = blockIdx.x * 256, row0 = blockIdx.y * 128;
    int wm = (wid & 1) * 64, wn = (wid >> 1) * 64;
    uint32_t sb = cvta_sm(sm);

    float acc[4][8][4] = {};

    auto issue = [&](int stage, int k0) {
        uint32_t stb = sb + (uint32_t)stage * GW_STAGE * 2;
        #pragma unroll
        for (int l = 0; l < 12; l++) {        // 3072 u4 total
            int i = tid + l * 256;
            const __nv_bfloat16* src;
            int r, c8;
            uint32_t soff;
            if (i < 1024) {
                int a = i >> 9, j = i & 511;
                r = j >> 2; c8 = j & 3;
                src = (a ? Al : Ah) + (size_t)(row0 + r) * K;
                soff = (uint32_t)a * GW_A_ELE;
            } else {
                int i2 = i - 1024;
                int a = i2 >> 10, j = i2 & 1023;
                r = j >> 2; c8 = j & 3;
                src = (a ? Bl : Bh) + (size_t)(col0 + r) * K;
                soff = 2*GW_A_ELE + (uint32_t)a * GW_B_ELE;
            }
            uint32_t dst = stb + (soff + r * TG_STRIDE + c8 * 8) * 2;
            const __nv_bfloat16* g = src + k0 + c8 * 8;
            asm volatile("cp.async.cg.shared.global [%0], [%1], 16;" :: "r"(dst), "l"(g));
        }
        asm volatile("cp.async.commit_group;" ::: "memory");
    };

    auto compute = [&](int stage) {
        uint32_t stb = sb + (uint32_t)stage * GW_STAGE * 2;
        uint32_t bA_h = stb, bA_l = stb + GW_A_ELE*2;
        uint32_t bB_h = stb + 2*GW_A_ELE*2, bB_l = stb + (2*GW_A_ELE + GW_B_ELE)*2;
        #pragma unroll
        for (int kk = 0; kk < 32; kk += 16) {
            uint32_t ah[4][4], al[4][4];
            #pragma unroll
            for (int mb = 0; mb < 4; mb++) {
                int r = wm + mb * 16 + (lane & 15);
                int c = kk + (lane >> 4) * 8;
                uint32_t off = (uint32_t)(r * TG_STRIDE + c) * 2;
                ldm_x4(ah[mb], bA_h + off);
                ldm_x4(al[mb], bA_l + off);
            }
            #pragma unroll
            for (int nb = 0; nb < 4; nb++) {
                int r = wn + nb * 16 + ((lane >> 4) << 3) + (lane & 7);
                int c = kk + ((lane >> 3) & 1) * 8;
                uint32_t off = (uint32_t)(r * TG_STRIDE + c) * 2;
                uint32_t bh[4], bl[4];
                ldm_x4(bh, bB_h + off);
                ldm_x4(bl, bB_l + off);
                #pragma unroll
                for (int mb = 0; mb < 4; mb++) {
                    mma16816(acc[mb][2*nb+0], ah[mb], bh[0], bh[1]);
                    mma16816(acc[mb][2*nb+1], ah[mb], bh[2], bh[3]);
                    mma16816(acc[mb][2*nb+0], ah[mb], bl[0], bl[1]);
                    mma16816(acc[mb][2*nb+1], ah[mb], bl[2], bl[3]);
                    mma16816(acc[mb][2*nb+0], al[mb], bh[0], bh[1]);
                    mma16816(acc[mb][2*nb+1], al[mb], bh[2], bh[3]);
                }
            }
        }
    };

    int nch = K >> 5;
    issue(0, 0);
    for (int ck = 0; ck < nch; ck++) {
        if (ck + 1 < nch) {
            issue((ck + 1) & 1, (ck + 1) << 5);
            asm volatile("cp.async.wait_group 1;" ::: "memory");
        } else {
            asm volatile("cp.async.wait_group 0;" ::: "memory");
        }
        __syncthreads();
        compute(ck & 1);
        __syncthreads();
    }

    int g = lane >> 2, tg = lane & 3;
    float mn = 1e30f, mx = -1e30f;
    #pragma unroll
    for (int mb = 0; mb < 4; mb++) {
        #pragma unroll
        for (int ug = 0; ug < 2; ug++) {
            int cb = col0 + wn + ug*32;
            int u0 = ((cb >> 5) << 3) + 2*tg;
            float iv[4], fv[4], gv[4], ov[4];
            #pragma unroll
            for (int e = 0; e < 4; e++) {
                int co = 2*tg + (e & 1);
                iv[e] = acc[mb][ug*4+0][e] + bias[cb + 0  + co];
                fv[e] = acc[mb][ug*4+1][e] + bias[cb + 8  + co];
                gv[e] = acc[mb][ug*4+2][e] + bias[cb + 16 + co];
                ov[e] = acc[mb][ug*4+3][e] + bias[cb + 24 + co];
            }
            #pragma unroll
            for (int half = 0; half < 2; half++) {
                int row = row0 + wm + mb*16 + g + half*8;
                float2 cc = *(const float2*)(c0v + (size_t)row*256 + u0);
                float cin[2] = {cc.x, cc.y};
                float hh[2], c2[2];
                #pragma unroll
                for (int e2 = 0; e2 < 2; e2++) {
                    int e = half*2 + e2;
                    float si = fsig(iv[e]);
                    float sf = fsig(fv[e]);
                    float so = fsig(ov[e]);
                    c2[e2] = sf * cin[e2] + si * ftanh(gv[e]);
                    hh[e2] = so * ftanh(c2[e2]);
                    mn = fminf(mn, hh[e2]); mx = fmaxf(mx, hh[e2]);
                }
                *(float2*)(hOut + (size_t)row*256 + u0) = make_float2(hh[0], hh[1]);
                *(float2*)(cOut + (size_t)row*256 + u0) = make_float2(c2[0], c2[1]);
            }
        }
    }
    __shared__ float smn[256], smx[256];
    smn[tid] = mn; smx[tid] = mx; __syncthreads();
    for (int s = 128; s > 0; s >>= 1) {
        if (tid < s) {
            smn[tid] = fminf(smn[tid], smn[tid+s]);
            smx[tid] = fmaxf(smx[tid], smx[tid+s]);
        }
        __syncthreads();
    }
    if (tid == 0) {
        int bid = blockIdx.y * gridDim.x + blockIdx.x;   // 0..127
        g_pmin[bid] = smn[0]; g_pmax[bid] = smx[0];
    }
}

// ---------------- fake-quant A ----------------------
__global__ void quantA(const float* __restrict__ x,
                       __nv_bfloat16* __restrict__ hi, __nv_bfloat16* __restrict__ lo,
                       int npart)
{
    __shared__ float smn[256], smx[256];
    __shared__ float sparam[2];
    float mn = 1e30f, mx = -1e30f;
    for (int i = threadIdx.x; i < npart; i += 256) {
        mn = fminf(mn, g_pmin[i]); mx = fmaxf(mx, g_pmax[i]);
    }
    smn[threadIdx.x] = mn; smx[threadIdx.x] = mx; __syncthreads();
    for (int s = 128; s > 0; s >>= 1) {
        if (threadIdx.x < s) {
            smn[threadIdx.x] = fminf(smn[threadIdx.x], smn[threadIdx.x+s]);
            smx[threadIdx.x] = fmaxf(smx[threadIdx.x], smx[threadIdx.x+s]);
        }
        __syncthreads();
    }
    if (threadIdx.x == 0) {
        float a = smn[0], b = smx[0];
        if (a == b) { a -= 0.01f; b += 0.01f; }
        float scale = (b - a) / 255.f;
        sparam[0] = scale;
        sparam[1] = rintf(-a / scale);
    }
    __syncthreads();
    float scale = sparam[0], zp = sparam[1];

    float part = 0.f;
    #pragma unroll
    for (int l = 0; l < 4; l++) {
        int i = blockIdx.x*256 + threadIdx.x + l*65536;
        float4 t = ((const float4*)x)[i];
        float ts[4] = {t.x, t.y, t.z, t.w};
        float ds[4];
        #pragma unroll
        for (int q = 0; q < 4; q++) {
            float r = rintf(ts[q]/scale + zp);
            r = fminf(fmaxf(r, 0.f), 255.f);
            float d = (r - zp) * scale;
            ds[q] = d;
            part += __log2f(fmaf(510.f, fabsf(d), 1.f));
        }
        split4(ds, &hi[i*4], &lo[i*4]);
    }
    __shared__ float sd[256];
    sd[threadIdx.x] = part; __syncthreads();
    for (int s = 128; s > 0; s >>= 1) { if (threadIdx.x < s) sd[threadIdx.x] += sd[threadIdx.x+s]; __syncthreads(); }
    if (threadIdx.x == 0) atomicAdd(&g_loss, sd[0]);
}

// ---------------- fake-quant T ----------------------
__global__ void quantT(const float* __restrict__ inT,
                       __nv_bfloat16* __restrict__ hi, __nv_bfloat16* __restrict__ lo,
                       int npart)
{
    __shared__ float tile[32][33];
    __shared__ float smn[256], smx[256];
    __shared__ float sparam[2];
    int tx = threadIdx.x, ty = threadIdx.y;
    int tid = ty*32 + tx;

    float mn = (tid < npart) ? g_pmin[tid] : 1e30f;
    float mx = (tid < npart) ? g_pmax[tid] : -1e30f;
    smn[tid] = mn; smx[tid] = mx; __syncthreads();
    for (int s = 128; s > 0; s >>= 1) {
        if (tid < s) {
            smn[tid] = fminf(smn[tid], smn[tid+s]);
            smx[tid] = fmaxf(smx[tid], smx[tid+s]);
        }
        __syncthreads();
    }
    if (tid == 0) {
        float a = smn[0], b = smx[0];
        if (a == b) { a -= 0.01f; b += 0.01f; }
        float scale = (b - a) / 255.f;
        sparam[0] = scale;
        sparam[1] = rintf(-a / scale);
    }
    __syncthreads();
    float scale = sparam[0], zp = sparam[1];

    int c0 = blockIdx.y * 32;
    float part = 0.f;
    #pragma unroll 1
    for (int nt = 0; nt < 4; nt++) {
        int n0 = blockIdx.x * 128 + nt * 32;
        for (int cc = ty; cc < 32; cc += 8) {
            float t = inT[(size_t)(c0+cc)*NA + n0 + tx];
            float r = rintf(t/scale + zp);
            r = fminf(fmaxf(r, 0.f), 255.f);
            float d = (r - zp) * scale;
            tile[cc][tx] = d;
            part += __log2f(fmaf(510.f, fabsf(d), 1.f));
        }
        __syncthreads();
        for (int nn = ty; nn < 32; nn += 8) {
            float d = tile[tx][nn];
            size_t o = (size_t)(n0+nn)*256 + c0 + tx;
            bf16split(d, &hi[o], &lo[o]);
        }
        __syncthreads();
    }
    __shared__ float sd[256];
    sd[tid] = part; __syncthreads();
    for (int s = 128; s > 0; s >>= 1) { if (tid < s) sd[tid] += sd[tid+s]; __syncthreads(); }
    if (tid == 0) atomicAdd(&g_loss, sd[0]);
}

// ---------------- sortk ----------------
__global__ void __launch_bounds__(1024)
sortk()
{
    extern __shared__ char sms[];
    float* key = (float*)sms;
    int*   idx = (int*)(key + NA);
    float* sA  = (float*)(idx + NA);
    float* sB  = sA + NA;
    __shared__ float wsum[32];
    int h = blockIdx.x;
    int tid = threadIdx.x, lane = tid & 31, warp = tid >> 5;

    for (int i = tid; i < NA; i += 1024) { key[i] = g_cj[h*NA + i]; idx[i] = i; }
    __syncthreads();
    for (int k = 2; k <= NA; k <<= 1) {
        int j = k >> 1;
        for (; j >= 128; j >>= 1) {
            #pragma unroll 2
            for (int p = tid; p < NA/2; p += 1024) {
                int i = ((p & ~(j-1)) << 1) | (p & (j-1));
                int il = i | j;
                bool up = ((i & k) == 0);
                float a = key[i], b = key[il];
                if (up ? (a > b) : (a < b)) {
                    key[i] = b; key[il] = a;
                    int tmp = idx[i]; idx[i] = idx[il]; idx[il] = tmp;
                }
            }
            __syncthreads();
        }
        for (; j >= 1; j >>= 1) {
            #pragma unroll 2
            for (int q = lane; q < 64; q += 32) {
                int p = (warp << 6) | q;
                int i = ((p & ~(j-1)) << 1) | (p & (j-1));
                int il = i | j;
                bool up = ((i & k) == 0);
                float a = key[i], b = key[il];
                if (up ? (a > b) : (a < b)) {
                    key[i] = b; key[il] = a;
                    int tmp = idx[i]; idx[i] = idx[il]; idx[il] = tmp;
                }
            }
            __syncwarp();
        }
        __syncthreads();
    }
    float cm = key[NA-1];

    int t0 = tid * 4;
    float kw0 = key[t0], kw1 = key[t0+1], kw2 = key[t0+2], kw3 = key[t0+3];
    float wB0 = expf(0.2f*(kw0-cm)), wB1 = expf(0.2f*(kw1-cm));
    float wB2 = expf(0.2f*(kw2-cm)), wB3 = expf(0.2f*(kw3-cm));
    float wA0 = expf(kw0-cm), wA1 = expf(kw1-cm), wA2 = expf(kw2-cm), wA3 = expf(kw3-cm);
    *(int4*)&g_sidx[h*NA + t0] = make_int4(idx[t0], idx[t0+1], idx[t0+2], idx[t0+3]);
    *(float4*)&g_wA[h*NA + t0] = make_float4(wA0, wA1, wA2, wA3);
    *(float4*)&g_wB[h*NA + t0] = make_float4(wB0, wB1, wB2, wB3);

    {
        float v0 = wB0, v1 = v0+wB1, v2 = v1+wB2, v3 = v2+wB3;
        float tot = v3, s = tot;
        #pragma unroll
        for (int o = 1; o < 32; o <<= 1) { float u = __shfl_up_sync(0xffffffffu, s, o); if (lane >= o) s += u; }
        if (lane == 31) wsum[warp] = s;
        __syncthreads();
        if (warp == 0) {
            float y = wsum[lane];
            #pragma unroll
            for (int o = 1; o < 32; o <<= 1) { float u = __shfl_up_sync(0xffffffffu, y, o); if (lane >= o) y += u; }
            wsum[lane] = y;
        }
        __syncthreads();
        float off = (warp ? wsum[warp-1] : 0.f) + (s - tot);
        sB[t0] = off+v0; sB[t0+1] = off+v1; sB[t0+2] = off+v2; sB[t0+3] = off+v3;
    }
    __syncthreads();
    {
        int rb = NA - 4 - t0;
        float a0 = expf(key[rb]-cm),   a1 = expf(key[rb+1]-cm);
        float a2 = expf(key[rb+2]-cm), a3 = expf(key[rb+3]-cm);
        float u0 = a3, u1 = u0+a2, u2 = u1+a1, u3 = u2+a0;
        float tot = u3, s = tot;
        #pragma unroll
        for (int o = 1; o < 32; o <<= 1) { float u = __shfl_up_sync(0xffffffffu, s, o); if (lane >= o) s += u; }
        if (lane == 31) wsum[warp] = s;
        __syncthreads();
        if (warp == 0) {
            float y = wsum[lane];
            #pragma unroll
            for (int o = 1; o < 32; o <<= 1) { float u = __shfl_up_sync(0xffffffffu, y, o); if (lane >= o) y += u; }
            wsum[lane] = y;
        }
        __syncthreads();
        float off = (warp ? wsum[warp-1] : 0.f) + (s - tot);
        sA[rb] = off+u3; sA[rb+1] = off+u2; sA[rb+2] = off+u1; sA[rb+3] = off+u0;
    }
    __syncthreads();

    for (int l = 0; l < 4; l++) {
        int n = tid + l*1024;
        float cin = g_ci[h*NA + n];
        float t = -cin;
        int lo = 0, hi = NA;
        while (lo < hi) {
            int mid = (lo + hi) >> 1;
            if (key[mid] <= t) lo = mid + 1; else hi = mid;
        }
        float r = expf(0.8f * (cin + cm));
        float A = (lo < NA) ? sA[lo]     : 0.f;
        float B = (lo > 0)  ? sB[lo - 1] : 0.f;
        g_kcount[h*NA + n] = lo;
        g_rn[h*NA + n]     = r;
        g_invd[h*NA + n]   = 1.f / (r*A + B);
        g_ci[h*NA + n] = 0.f;
        g_cj[h*NA + n] = 0.f;
    }
}

// ---------------- scomb ----------------
__global__ void __launch_bounds__(512)
scomb(const float* __restrict__ bias, float* __restrict__ outT,
      int G, int do_elu, int do_mm)
{
    __shared__ float s_x[NA];
    __shared__ float s_pre[NA];
    __shared__ float s_suf[NA];
    __shared__ float wsum[16];
    int c = blockIdx.x;
    int h = c / G;
    int tid = threadIdx.x, lane = tid & 31, warp = tid >> 5;
    int t0 = tid * 8;
    const float* xrow = g_hWT + (size_t)c * NA;

    {
        int4 iva = *(const int4*)&g_sidx[h*NA + t0];
        int4 ivb = *(const int4*)&g_sidx[h*NA + t0 + 4];
        s_x[t0+0] = xrow[iva.x]; s_x[t0+1] = xrow[iva.y];
        s_x[t0+2] = xrow[iva.z]; s_x[t0+3] = xrow[iva.w];
        s_x[t0+4] = xrow[ivb.x]; s_x[t0+5] = xrow[ivb.y];
        s_x[t0+6] = xrow[ivb.z]; s_x[t0+7] = xrow[ivb.w];
    }
    __syncthreads();

    {
        float4 wa = *(const float4*)&g_wB[h*NA + t0];
        float4 wb = *(const float4*)&g_wB[h*NA + t0 + 4];
        float v[8];
        float run = wa.x * s_x[t0+0];   v[0] = run;
        run += wa.y * s_x[t0+1];        v[1] = run;
        run += wa.z * s_x[t0+2];        v[2] = run;
        run += wa.w * s_x[t0+3];        v[3] = run;
        run += wb.x * s_x[t0+4];        v[4] = run;
        run += wb.y * s_x[t0+5];        v[5] = run;
        run += wb.z * s_x[t0+6];        v[6] = run;
        run += wb.w * s_x[t0+7];        v[7] = run;
        float tot = run, s = tot;
        #pragma unroll
        for (int o = 1; o < 32; o <<= 1) { float u = __shfl_up_sync(0xffffffffu, s, o); if (lane >= o) s += u; }
        if (lane == 31) wsum[warp] = s;
        __syncthreads();
        if (warp == 0 && lane < 16) {
            float y = wsum[lane];
            #pragma unroll
            for (int o = 1; o < 16; o <<= 1) { float u = __shfl_up_sync(0xffffu, y, o); if (lane >= o) y += u; }
            wsum[lane] = y;
        }
        __syncthreads();
        float off = (warp ? wsum[warp-1] : 0.f) + (s - tot);
        #pragma unroll
        for (int e = 0; e < 8; e++) s_pre[t0+e] = off + v[e];
    }
    __syncthreads();
    {
        int rb = NA - 8 - t0;
        float4 wa = *(const float4*)&g_wA[h*NA + rb];
        float4 wb = *(const float4*)&g_wA[h*NA + rb + 4];
        float ws[8] = { wa.x, wa.y, wa.z, wa.w, wb.x, wb.y, wb.z, wb.w };
        float u[8];
        float run = ws[7]*s_x[rb+7];  u[0] = run;
        #pragma unroll
        for (int e = 1; e < 8; e++) { run += ws[7-e]*s_x[rb+7-e]; u[e] = run; }
        float tot = run, s = tot;
        #pragma unroll
        for (int o = 1; o < 32; o <<= 1) { float uu = __shfl_up_sync(0xffffffffu, s, o); if (lane >= o) s += uu; }
        if (lane == 31) wsum[warp] = s;
        __syncthreads();
        if (warp == 0 && lane < 16) {
            float y = wsum[lane];
            #pragma unroll
            for (int o = 1; o < 16; o <<= 1) { float uu = __shfl_up_sync(0xffffu, y, o); if (lane >= o) y += uu; }
            wsum[lane] = y;
        }
        __syncthreads();
        float off = (warp ? wsum[warp-1] : 0.f) + (s - tot);
        #pragma unroll
        for (int e = 0; e < 8; e++) s_suf[rb + 7 - e] = off + u[e];
    }
    __syncthreads();

    float bv = bias[c];
    float mn = 1e30f, mx = -1e30f;
    #pragma unroll
    for (int l = 0; l < 8; l++) {
        int n = tid + l*512;
        int k = g_kcount[h*NA + n];
        float r = g_rn[h*NA + n];
        float invd = g_invd[h*NA + n];
        float Av = (k < NA) ? s_suf[k]     : 0.f;
        float Bv = (k > 0)  ? s_pre[k - 1] : 0.f;
        float val = (r*Av + Bv) * invd + bv;
        if (do_elu) val = (val > 0.f) ? val : expm1f(val);
        mn = fminf(mn, val); mx = fmaxf(mx, val);
        outT[(size_t)c*NA + n] = val;
    }
    if (do_mm) {
        __shared__ float smn[512], smx[512];
        smn[tid] = mn; smx[tid] = mx; __syncthreads();
        for (int s = 256; s > 0; s >>= 1) {
            if (tid < s) {
                smn[tid] = fminf(smn[tid], smn[tid+s]);
                smx[tid] = fmaxf(smx[tid], smx[tid+s]);
            }
            __syncthreads();
        }
        if (tid == 0) { g_pmin[c] = smn[0]; g_pmax[c] = smx[0]; }
    }
}

// ---------------- fused policy + value head (+ loss write) ----------------
__global__ void __launch_bounds__(256)
policyk(const float* __restrict__ A0, const float* __restrict__ A1T,
        const float* __restrict__ Wa, const float* __restrict__ ba,
        const float* __restrict__ Wv, const float* __restrict__ bv,
        float* __restrict__ out_logp, float* __restrict__ out_value,
        float* __restrict__ out_loss)
{
    if (blockIdx.x == 0 && threadIdx.x == 0) out_loss[0] = g_loss;
    __shared__ float As[16][68];
    __shared__ float Bs[16][68];
    __shared__ float Ss[64][65];
    int tid = threadIdx.x;
    int tx = tid % 16, ty = tid / 16;
    int row0 = blockIdx.x * 64;
    float acc[4][4] = {};
    float vacc = 0.f;

    for (int k0 = 0; k0 < 512; k0 += 16) {
        if (k0 < 256) {
            int lin = tid * 4;
            int m = lin >> 4, kk = lin & 15;
            float4 v = *(const float4*)&A0[(size_t)(row0+m)*256 + k0 + kk];
            As[kk+0][m] = v.x; As[kk+1][m] = v.y; As[kk+2][m] = v.z; As[kk+3][m] = v.w;
        } else {
            int lin = tid * 4;
            int kk = lin >> 6, m4 = lin & 63;
            float4 v = *(const float4*)&A1T[(size_t)(k0-256+kk)*NA + row0 + m4];
            *(float4*)&As[kk][m4] = v;
        }
        {
            int lin = tid * 4;
            int kk = lin >> 6, n = lin & 63;
            *(float4*)&Bs[kk][n] = *(const float4*)&Wa[(size_t)(k0+kk)*64 + n];
        }
        __syncthreads();
        #pragma unroll
        for (int kk = 0; kk < 16; kk++) {
            float a[4], bb[4];
            #pragma unroll
            for (int i = 0; i < 4; i++) a[i] = As[kk][ty*4+i];
            #pragma unroll
            for (int j = 0; j < 4; j++) bb[j] = Bs[kk][tx*4+j];
            #pragma unroll
            for (int i = 0; i < 4; i++)
                #pragma unroll
                for (int j = 0; j < 4; j++)
                    acc[i][j] = fmaf(a[i], bb[j], acc[i][j]);
        }
        if (tid < 64) {
            #pragma unroll
            for (int kk = 0; kk < 16; kk++)
                vacc = fmaf(As[kk][tid], Wv[k0+kk], vacc);
        }
        __syncthreads();
    }
    if (tid < 64) out_value[row0 + tid] = vacc + bv[0];

    #pragma unroll
    for (int i = 0; i < 4; i++)
        #pragma unroll
        for (int j = 0; j < 4; j++)
            Ss[ty*4+i][tx*4+j] = acc[i][j] + ba[tx*4+j];
    __syncthreads();

    int row = tid >> 2, quad = tid & 3;
    float m = -1e30f;
    #pragma unroll
    for (int c = 0; c < 16; c++) m = fmaxf(m, Ss[row][quad*16 + c]);
    m = fmaxf(m, __shfl_xor_sync(0xffffffffu, m, 1));
    m = fmaxf(m, __shfl_xor_sync(0xffffffffu, m, 2));
    float s = 0.f;
    #pragma unroll
    for (int c = 0; c < 16; c++) s += expf(Ss[row][quad*16 + c] - m);
    s += __shfl_xor_sync(0xffffffffu, s, 1);
    s += __shfl_xor_sync(0xffffffffu, s, 2);
    float lse = m + logf(s);
    #pragma unroll
    for (int c = 0; c < 16; c++)
        out_logp[(size_t)(row0+row)*64 + quad*16 + c] = Ss[row][quad*16 + c] - lse;
}

// ---------------- host ----------------
extern "C" void kernel_launch(void* const* d_in, const int* in_sizes, int n_in,
                              void* d_out, int out_size)
{
    const float* obs  = (const float*)d_in[0];
    const float* h0   = (const float*)d_in[1];
    const float* c0   = (const float*)d_in[2];
    const float* Wobs = (const float*)d_in[3];
    const float* bobs = (const float*)d_in[4];
    const float* Wih  = (const float*)d_in[5];
    const float* Whh  = (const float*)d_in[6];
    const float* bih  = (const float*)d_in[7];
    const float* bhh  = (const float*)d_in[8];
    const float* W1   = (const float*)d_in[9];
    const float* ai1  = (const float*)d_in[10];
    const float* aj1  = (const float*)d_in[11];
    const float* b1   = (const float*)d_in[12];
    const float* W2   = (const float*)d_in[13];
    const float* ai2  = (const float*)d_in[14];
    const float* aj2  = (const float*)d_in[15];
    const float* b2   = (const float*)d_in[16];
    const float* Wv   = (const float*)d_in[17];
    const float* bv   = (const float*)d_in[18];
    const float* Wa   = (const float*)d_in[19];
    const float* ba   = (const float*)d_in[20];

    float* out       = (float*)d_out;
    float* out_logp  = out;
    float* out_value = out + NA*ACT;
    float* out_h     = out_value + NA;
    float* out_c     = out_h + NA*HD;
    float* out_loss  = out_c + NA*HD;

    float *p_hWT, *p_commT, *p_bsum;
    __nv_bfloat16 *p_Ah, *p_Al, *p_A2h, *p_A2l;
    __nv_bfloat16 *p_B0h, *p_B0l, *p_Bgh, *p_Bgl, *p_B1h, *p_B1l, *p_B2h, *p_B2l;
    cudaGetSymbolAddress((void**)&p_hWT,    g_hWT);
    cudaGetSymbolAddress((void**)&p_commT,  g_commT);
    cudaGetSymbolAddress((void**)&p_bsum,   g_bsum);
    cudaGetSymbolAddress((void**)&p_Ah,     g_Ah);
    cudaGetSymbolAddress((void**)&p_Al,     g_Al);
    cudaGetSymbolAddress((void**)&p_A2h,    g_A2h);
    cudaGetSymbolAddress((void**)&p_A2l,    g_A2l);
    cudaGetSymbolAddress((void**)&p_B0h,    g_B0h);
    cudaGetSymbolAddress((void**)&p_B0l,    g_B0l);
    cudaGetSymbolAddress((void**)&p_Bgh,    g_Bgh);
    cudaGetSymbolAddress((void**)&p_Bgl,    g_Bgl);
    cudaGetSymbolAddress((void**)&p_B1h,    g_B1h);
    cudaGetSymbolAddress((void**)&p_B1l,    g_B1l);
    cudaGetSymbolAddress((void**)&p_B2h,    g_B2h);
    cudaGetSymbolAddress((void**)&p_B2l,    g_B2l);

    const int SM64  = TG_SMEM_BYTES(64);
    const int SMSORT = NA * 16;
    cudaFuncSetAttribute((const void*)tgemm<64>, cudaFuncAttributeMaxDynamicSharedMemorySize, SM64);
    cudaFuncSetAttribute((const void*)gatesk,    cudaFuncAttributeMaxDynamicSharedMemorySize, GW_SMEM);
    cudaFuncSetAttribute((const void*)sortk,     cudaFuncAttributeMaxDynamicSharedMemorySize, SMSORT);

    // 1. prep
    wprep<<<(WVTOT + 255)/256, 256>>>(obs, h0, Wobs, Wih, Whh, W1, W2, bih, bhh, bobs);
    // 2. weight-product GEMM -> Bg cols 0..255 (split output)
    tgemm<64><<<dim3(2, 16), 256, SM64>>>(p_A2h, p_A2l, p_B0h, p_B0l, nullptr,
                                          p_Bgh, p_Bgl, 512,
                                          nullptr, nullptr, nullptr, 0, 256, 256);
    // 3. gates GEMM (128x256 tile, single wave) + fused LSTM -> out_h, out_c, minmax[128]
    gatesk<<<dim3(4, 32), 256, GW_SMEM>>>(p_Ah, p_Al, p_Bgh, p_Bgl, p_bsum,
                                          c0, out_h, out_c, 512);
    // 4. quant #1 -> splits into A2
    quantA<<<256, 256>>>(out_h, p_A2h, p_A2l, 128);
    // 5. GAT1 projection -> hWT + fused ci/cj
    tgemm<64><<<dim3(2, 64), 256, SM64>>>(p_A2h, p_A2l, p_B1h, p_B1l, nullptr,
                                          nullptr, nullptr, 0,
                                          p_hWT, ai1, aj1, 64, 256, 256);
    // 6-7. GAT1 attention
    sortk<<<4, 1024, SMSORT>>>();
    scomb<<<256, 512>>>(b1, p_commT, 64, 1, 1);
    // 8. quant #2 (transposed input)
    quantT<<<dim3(NA/128, 8), dim3(32, 8)>>>(p_commT, p_A2h, p_A2l, 256);
    // 9. GAT2 projection
    tgemm<64><<<dim3(2, 64), 256, SM64>>>(p_A2h, p_A2l, p_B2h, p_B2l, nullptr,
                                          nullptr, nullptr, 0,
                                          p_hWT, ai2, aj2, 256, 256, 256);
    // 10-11. GAT2 attention
    sortk<<<1, 1024, SMSORT>>>();
    scomb<<<256, 512>>>(b2, p_commT, 256, 0, 0);
    // 12. fused policy + value heads + loss
    policyk<<<NA/64, 256>>>(out_h, p_commT, Wa, ba, Wv, bv, out_logp, out_value, out_loss);
}

// round 16
// speedup vs baseline: 1.0899x; 1.0139x over previous
#include <cuda_runtime.h>
#include <cuda_bf16.h>
#include <math.h>
#include <stdint.h>

#define NA   4096
#define HD   256
#define HG   256
#define ACT  64
#define MMB  1024

// ---------------- device scratch ----------------
__device__ float g_hWT[HG*NA];
__device__ float g_commT[HG*NA];
__device__ float g_bsum[4*HD];
__device__ __nv_bfloat16 g_Ah[NA*512];
__device__ __nv_bfloat16 g_Al[NA*512];
__device__ __nv_bfloat16 g_A2h[NA*256];      // quantized q = r - zp (exact bf16)
__device__ __nv_bfloat16 g_A2l[NA*256];      // wgemm A lo
__device__ __nv_bfloat16 g_B0h[256*256], g_B0l[256*256];
__device__ __nv_bfloat16 g_Bgh[1024*512], g_Bgl[1024*512];
__device__ __nv_bfloat16 g_B1h[256*256], g_B1l[256*256];
__device__ __nv_bfloat16 g_B2h[256*256], g_B2l[256*256];
__device__ float g_ci[4*NA];
__device__ float g_cj[4*NA];
__device__ int   g_kcount[4*NA];
__device__ int   g_sidx[4*NA];
__device__ float g_wA[4*NA];
__device__ float g_wB[4*NA];
__device__ float g_rn[4*NA];
__device__ float g_invd[4*NA];
__device__ float g_pmin[MMB];
__device__ float g_pmax[MMB];
__device__ float g_qscale;
__device__ float g_loss;

__device__ __forceinline__ void bf16split(float x, __nv_bfloat16* hi, __nv_bfloat16* lo) {
    __nv_bfloat16 h = __float2bfloat16(x);
    *hi = h;
    *lo = __float2bfloat16(x - __bfloat162float(h));
}
__device__ __forceinline__ float fsig(float x) { return 1.f / (1.f + __expf(-x)); }
__device__ __forceinline__ float ftanh(float x) {
    float ax = fabsf(x);
    float e = __expf(-2.f * ax);
    float t = (1.f - e) / (1.f + e);
    return copysignf(t, x);
}
__device__ __forceinline__ void split4(const float* v, __nv_bfloat16* hi, __nv_bfloat16* lo) {
    __nv_bfloat16 h[4], l[4];
    #pragma unroll
    for (int e = 0; e < 4; e++) bf16split(v[e], &h[e], &l[e]);
    *(uint2*)hi = *(uint2*)h;
    *(uint2*)lo = *(uint2*)l;
}

// ---------------- fused prep (vectorized) ----------------
#define WV0 (NA*64)
#define WV1 (WV0 + NA*64)
#define WV2 (WV1 + 16384)
#define WV3 (WV2 + 65536)
#define WV4 (WV3 + 65536)
#define WV5 (WV4 + 16384)
#define WV6 (WV5 + 16384)
#define WV7 (WV6 + 4096)
#define WVTOT (WV7 + 32768)
__global__ void wprep(const float* __restrict__ obs, const float* __restrict__ h0,
                      const float* __restrict__ Wobs,
                      const float* __restrict__ Wih, const float* __restrict__ Whh,
                      const float* __restrict__ W1, const float* __restrict__ W2,
                      const float* __restrict__ bih, const float* __restrict__ bhh,
                      const float* __restrict__ bobs)
{
    int idx = blockIdx.x*256 + threadIdx.x;
    if (idx == 0) g_loss = 0.f;
    if (idx < WV0) {
        int j = idx * 4;
        int n = j >> 8, k = j & 255;
        int d = n*512 + k;
        float4 v = *(const float4*)(obs + j);
        split4(&v.x, &g_Ah[d], &g_Al[d]);
    } else if (idx < WV1) {
        int j = (idx - WV0) * 4;
        int n = j >> 8, k = j & 255;
        int d = n*512 + 256 + k;
        float4 v = *(const float4*)(h0 + j);
        split4(&v.x, &g_Ah[d], &g_Al[d]);
    } else if (idx < WV2) {
        int j = (idx - WV1) * 4;
        float4 v = *(const float4*)(Wobs + j);
        split4(&v.x, &g_B0h[j], &g_B0l[j]);
    } else if (idx < WV3) {
        int j = (idx - WV2) * 4;
        int r = j >> 8, k = j & 255;
        int G = (r >> 3) & 3;
        int u = ((r >> 5) << 3) | (r & 7);
        float4 v = *(const float4*)(Wih + (G*256 + u)*256 + k);
        split4(&v.x, &g_A2h[j], &g_A2l[j]);
    } else if (idx < WV4) {
        int j = (idx - WV3) * 4;
        int r = j >> 8, k = j & 255;
        int G = (r >> 3) & 3;
        int u = ((r >> 5) << 3) | (r & 7);
        int d = r*512 + 256 + k;
        float4 v = *(const float4*)(Whh + (G*256 + u)*256 + k);
        split4(&v.x, &g_Bgh[d], &g_Bgl[d]);
    } else if (idx < WV5) {
        int j = (idx - WV4) * 4;
        int n = j >> 8, k = j & 255;
        float vv[4];
        #pragma unroll
        for (int e = 0; e < 4; e++) vv[e] = W1[(k+e)*256 + n];
        split4(vv, &g_B1h[j], &g_B1l[j]);
    } else if (idx < WV6) {
        int j = (idx - WV5) * 4;
        int n = j >> 8, k = j & 255;
        float vv[4];
        #pragma unroll
        for (int e = 0; e < 4; e++) vv[e] = W2[(k+e)*256 + n];
        split4(vv, &g_B2h[j], &g_B2l[j]);
    } else if (idx < WV7) {
        int j = (idx - WV6);
        float4 z = make_float4(0.f, 0.f, 0.f, 0.f);
        ((float4*)g_ci)[j] = z;
        ((float4*)g_cj)[j] = z;
    } else if (idx < WVTOT) {
        int t = idx - WV7;
        int r = t >> 5, lane = t & 31;
        int G = (r >> 3) & 3;
        int u = ((r >> 5) << 3) | (r & 7);
        int orow = G*256 + u;
        float s = 0.f;
        #pragma unroll
        for (int k = lane; k < 256; k += 32)
            s = fmaf(bobs[k], Wih[orow*256 + k], s);
        for (int o = 16; o > 0; o >>= 1) s += __shfl_down_sync(0xffffffffu, s, o);
        if (lane == 0) g_bsum[r] = s + bih[orow] + bhh[orow];
    }
}

// ---------------- mma.sync helpers ----------------
__device__ __forceinline__ uint32_t cvta_sm(const void* p) {
    uint32_t a;
    asm("{ .reg .u64 t; cvta.to.shared.u64 t, %1; cvt.u32.u64 %0, t; }" : "=r"(a) : "l"(p));
    return a;
}
__device__ __forceinline__ void ldm_x4(uint32_t (&d)[4], uint32_t addr) {
    asm volatile("ldmatrix.sync.aligned.m8n8.x4.shared.b16 {%0,%1,%2,%3}, [%4];"
        : "=r"(d[0]), "=r"(d[1]), "=r"(d[2]), "=r"(d[3]) : "r"(addr));
}
__device__ __forceinline__ void mma16816(float (&c)[4], const uint32_t (&a)[4],
                                         uint32_t b0, uint32_t b1) {
    asm volatile("mma.sync.aligned.m16n8k16.row.col.f32.bf16.bf16.f32 "
        "{%0,%1,%2,%3},{%4,%5,%6,%7},{%8,%9},{%0,%1,%2,%3};"
        : "+f"(c[0]), "+f"(c[1]), "+f"(c[2]), "+f"(c[3])
        : "r"(a[0]), "r"(a[1]), "r"(a[2]), "r"(a[3]), "r"(b0), "r"(b1));
}

// ---------------- split-bf16 tensor GEMM (BM=64), cp.async 3-stage -----------
// AONE: A is a single exact bf16 array (quantized path) -> 2 MMA passes,
//       epilogue scaled by *ascale.
#define TG_STRIDE 40
#define TG_STAGE_ELE(BM)   (2*(BM)*TG_STRIDE + 2*128*TG_STRIDE)
#define TG_SMEM_BYTES(BM)  (3 * TG_STAGE_ELE(BM) * 2)

template<int BM, bool AONE>
__global__ void __launch_bounds__(256, 2)
tgemm(const __nv_bfloat16* __restrict__ Ah, const __nv_bfloat16* __restrict__ Al,
      const __nv_bfloat16* __restrict__ Bh, const __nv_bfloat16* __restrict__ Bl,
      const float* __restrict__ bias, const float* __restrict__ ascale,
      __nv_bfloat16* __restrict__ Shi, __nv_bfloat16* __restrict__ Slo, int ldS,
      float* __restrict__ hwT, const float* __restrict__ aivec,
      const float* __restrict__ ajvec, int Gh,
      int N, int K)
{
    constexpr int A_ELE = BM * TG_STRIDE;
    constexpr int B_ELE = 128 * TG_STRIDE;
    constexpr int STAGE = 2*A_ELE + 2*B_ELE;    // layout identical for both modes
    constexpr int NWM  = BM / 32;
    constexpr int WN   = 128 / (8 / NWM);
    constexpr int NB16 = WN / 16;
    constexpr int NB   = WN / 8;
    constexpr int A_U4 = BM * 4;
    constexpr int B_U4 = 512;
    constexpr int NAA  = AONE ? 1 : 2;
    constexpr int TOT_U4 = NAA*A_U4 + 2*B_U4;

    extern __shared__ __nv_bfloat16 sm[];
    int tid = threadIdx.x, lane = tid & 31, wid = tid >> 5;
    int col0 = blockIdx.x * 128, row0 = blockIdx.y * BM;
    int wm = (wid % NWM) * 32, wn = (wid / NWM) * WN;
    uint32_t sb = cvta_sm(sm);

    float acc[2][NB][4] = {};

    auto issue = [&](int stage, int k0) {
        uint32_t stb = sb + (uint32_t)stage * STAGE * 2;
        #pragma unroll
        for (int l = 0; l < TOT_U4/256; l++) {
            int i = tid + l * 256;
            const __nv_bfloat16* src;
            int r, c8;
            uint32_t soff;
            if (i < NAA*A_U4) {
                int a = i / A_U4, j = i % A_U4;
                r = j >> 2; c8 = j & 3;
                src = (a ? Al : Ah) + (size_t)(row0 + r) * K;
                soff = (uint32_t)a * A_ELE;
            } else {
                int i2 = i - NAA*A_U4;
                int a = i2 / B_U4, j = i2 % B_U4;
                r = j >> 2; c8 = j & 3;
                src = (a ? Bl : Bh) + (size_t)(col0 + r) * K;
                soff = 2*A_ELE + (uint32_t)a * B_ELE;
            }
            uint32_t dst = stb + (soff + r * TG_STRIDE + c8 * 8) * 2;
            const __nv_bfloat16* g = src + k0 + c8 * 8;
            asm volatile("cp.async.cg.shared.global [%0], [%1], 16;" :: "r"(dst), "l"(g));
        }
        asm volatile("cp.async.commit_group;" ::: "memory");
    };

    auto compute = [&](int stage) {
        uint32_t stb = sb + (uint32_t)stage * STAGE * 2;
        uint32_t bA_h = stb, bA_l = stb + A_ELE*2;
        uint32_t bB_h = stb + 2*A_ELE*2, bB_l = stb + (2*A_ELE + B_ELE)*2;
        #pragma unroll
        for (int kk = 0; kk < 32; kk += 16) {
            uint32_t ah[2][4], al[2][4];
            #pragma unroll
            for (int mb = 0; mb < 2; mb++) {
                int r = wm + mb * 16 + (lane & 15);
                int c = kk + (lane >> 4) * 8;
                uint32_t off = (uint32_t)(r * TG_STRIDE + c) * 2;
                ldm_x4(ah[mb], bA_h + off);
                if constexpr (!AONE) ldm_x4(al[mb], bA_l + off);
            }
            #pragma unroll
            for (int nb = 0; nb < NB16; nb++) {
                int r = wn + nb * 16 + ((lane >> 4) << 3) + (lane & 7);
                int c = kk + ((lane >> 3) & 1) * 8;
                uint32_t off = (uint32_t)(r * TG_STRIDE + c) * 2;
                uint32_t bh[4], bl[4];
                ldm_x4(bh, bB_h + off);
                ldm_x4(bl, bB_l + off);
                #pragma unroll
                for (int mb = 0; mb < 2; mb++) {
                    mma16816(acc[mb][2*nb+0], ah[mb], bh[0], bh[1]);
                    mma16816(acc[mb][2*nb+1], ah[mb], bh[2], bh[3]);
                    mma16816(acc[mb][2*nb+0], ah[mb], bl[0], bl[1]);
                    mma16816(acc[mb][2*nb+1], ah[mb], bl[2], bl[3]);
                    if constexpr (!AONE) {
                        mma16816(acc[mb][2*nb+0], al[mb], bh[0], bh[1]);
                        mma16816(acc[mb][2*nb+1], al[mb], bh[2], bh[3]);
                    }
                }
            }
        }
    };

    int nch = K >> 5;
    issue(0, 0);
    if (nch > 1) issue(1, 32);
    for (int ck = 0; ck < nch; ck++) {
        if (ck + 2 < nch) {
            issue((ck + 2) % 3, (ck + 2) << 5);
            asm volatile("cp.async.wait_group 2;" ::: "memory");
        } else if (ck + 1 < nch) {
            asm volatile("cp.async.wait_group 1;" ::: "memory");
        } else {
            asm volatile("cp.async.wait_group 0;" ::: "memory");
        }
        __syncthreads();
        compute(ck % 3);
        __syncthreads();
    }

    int g = lane >> 2, tg = lane & 3;
    float s = ascale ? *ascale : 1.f;

    float cia[2][2] = {}, cja[2][2] = {};
    #pragma unroll
    for (int mb = 0; mb < 2; mb++) {
        #pragma unroll
        for (int n8 = 0; n8 < NB; n8++) {
            int row = row0 + wm + mb * 16 + g;
            int col = col0 + wn + n8 * 8 + 2 * tg;
            float b0 = bias ? bias[col]   : 0.f;
            float b1 = bias ? bias[col+1] : 0.f;
            float v00 = acc[mb][n8][0] * s + b0, v01 = acc[mb][n8][1] * s + b1;
            float v10 = acc[mb][n8][2] * s + b0, v11 = acc[mb][n8][3] * s + b1;
            if (Shi) {
                size_t d0 = (size_t)row * ldS + col;
                size_t d1 = (size_t)(row + 8) * ldS + col;
                bf16split(v00, &Shi[d0],   &Slo[d0]);
                bf16split(v01, &Shi[d0+1], &Slo[d0+1]);
                bf16split(v10, &Shi[d1],   &Slo[d1]);
                bf16split(v11, &Shi[d1+1], &Slo[d1+1]);
            }
            if (hwT) {
                hwT[(size_t)col*NA + row]         = v00;
                hwT[(size_t)(col+1)*NA + row]     = v01;
                hwT[(size_t)col*NA + row + 8]     = v10;
                hwT[(size_t)(col+1)*NA + row + 8] = v11;
            }
            if (aivec) {
                float a0 = aivec[col], a1 = aivec[col+1];
                float j0 = ajvec[col], j1 = ajvec[col+1];
                cia[mb][0] += v00*a0 + v01*a1;
                cia[mb][1] += v10*a0 + v11*a1;
                cja[mb][0] += v00*j0 + v01*j1;
                cja[mb][1] += v10*j0 + v11*j1;
            }
        }
    }
    if (aivec) {
        int hh = (col0 + wn) / Gh;
        #pragma unroll
        for (int mb = 0; mb < 2; mb++) {
            #pragma unroll
            for (int hf = 0; hf < 2; hf++) {
                float ci = cia[mb][hf], cj = cja[mb][hf];
                ci += __shfl_xor_sync(0xffffffffu, ci, 1);
                ci += __shfl_xor_sync(0xffffffffu, ci, 2);
                cj += __shfl_xor_sync(0xffffffffu, cj, 1);
                cj += __shfl_xor_sync(0xffffffffu, cj, 2);
                if (tg == 0) {
                    int row = row0 + wm + mb * 16 + g + hf * 8;
                    atomicAdd(&g_ci[hh*NA + row], ci);
                    atomicAdd(&g_cj[hh*NA + row], cj);
                }
            }
        }
    }
}

// ---------------- gates GEMM: 128x256 tile, 64x64 warp tiles, fused LSTM -----
#define GW_A_ELE (128*TG_STRIDE)
#define GW_B_ELE (256*TG_STRIDE)
#define GW_STAGE (2*GW_A_ELE + 2*GW_B_ELE)
#define GW_SMEM  (2 * GW_STAGE * 2)

__global__ void __launch_bounds__(256, 1)
gatesk(const __nv_bfloat16* __restrict__ Ah, const __nv_bfloat16* __restrict__ Al,
       const __nv_bfloat16* __restrict__ Bh, const __nv_bfloat16* __restrict__ Bl,
       const float* __restrict__ bias,
       const float* __restrict__ c0v, float* __restrict__ hOut, float* __restrict__ cOut,
       int K)
{
    extern __shared__ __nv_bfloat16 sm[];
    int tid = threadIdx.x, lane = tid & 31, wid = tid >> 5;
    int col0 = blockIdx.x * 256, row0 = blockIdx.y * 128;
    int wm = (wid & 1) * 64, wn = (wid >> 1) * 64;
    uint32_t sb = cvta_sm(sm);

    float acc[4][8][4] = {};

    auto issue = [&](int stage, int k0) {
        uint32_t stb = sb + (uint32_t)stage * GW_STAGE * 2;
        #pragma unroll
        for (int l = 0; l < 12; l++) {
            int i = tid + l * 256;
            const __nv_bfloat16* src;
            int r, c8;
            uint32_t soff;
            if (i < 1024) {
                int a = i >> 9, j = i & 511;
                r = j >> 2; c8 = j & 3;
                src = (a ? Al : Ah) + (size_t)(row0 + r) * K;
                soff = (uint32_t)a * GW_A_ELE;
            } else {
                int i2 = i - 1024;
                int a = i2 >> 10, j = i2 & 1023;
                r = j >> 2; c8 = j & 3;
                src = (a ? Bl : Bh) + (size_t)(col0 + r) * K;
                soff = 2*GW_A_ELE + (uint32_t)a * GW_B_ELE;
            }
            uint32_t dst = stb + (soff + r * TG_STRIDE + c8 * 8) * 2;
            const __nv_bfloat16* g = src + k0 + c8 * 8;
            asm volatile("cp.async.cg.shared.global [%0], [%1], 16;" :: "r"(dst), "l"(g));
        }
        asm volatile("cp.async.commit_group;" ::: "memory");
    };

    auto compute = [&](int stage) {
        uint32_t stb = sb + (uint32_t)stage * GW_STAGE * 2;
        uint32_t bA_h = stb, bA_l = stb + GW_A_ELE*2;
        uint32_t bB_h = stb + 2*GW_A_ELE*2, bB_l = stb + (2*GW_A_ELE + GW_B_ELE)*2;
        #pragma unroll
        for (int kk = 0; kk < 32; kk += 16) {
            uint32_t ah[4][4], al[4][4];
            #pragma unroll
            for (int mb = 0; mb < 4; mb++) {
                int r = wm + mb * 16 + (lane & 15);
                int c = kk + (lane >> 4) * 8;
                uint32_t off = (uint32_t)(r * TG_STRIDE + c) * 2;
                ldm_x4(ah[mb], bA_h + off);
                ldm_x4(al[mb], bA_l + off);
            }
            #pragma unroll
            for (int nb = 0; nb < 4; nb++) {
                int r = wn + nb * 16 + ((lane >> 4) << 3) + (lane & 7);
                int c = kk + ((lane >> 3) & 1) * 8;
                uint32_t off = (uint32_t)(r * TG_STRIDE + c) * 2;
                uint32_t bh[4], bl[4];
                ldm_x4(bh, bB_h + off);
                ldm_x4(bl, bB_l + off);
                #pragma unroll
                for (int mb = 0; mb < 4; mb++) {
                    mma16816(acc[mb][2*nb+0], ah[mb], bh[0], bh[1]);
                    mma16816(acc[mb][2*nb+1], ah[mb], bh[2], bh[3]);
                    mma16816(acc[mb][2*nb+0], ah[mb], bl[0], bl[1]);
                    mma16816(acc[mb][2*nb+1], ah[mb], bl[2], bl[3]);
                    mma16816(acc[mb][2*nb+0], al[mb], bh[0], bh[1]);
                    mma16816(acc[mb][2*nb+1], al[mb], bh[2], bh[3]);
                }
            }
        }
    };

    int nch = K >> 5;
    issue(0, 0);
    for (int ck = 0; ck < nch; ck++) {
        if (ck + 1 < nch) {
            issue((ck + 1) & 1, (ck + 1) << 5);
            asm volatile("cp.async.wait_group 1;" ::: "memory");
        } else {
            asm volatile("cp.async.wait_group 0;" ::: "memory");
        }
        __syncthreads();
        compute(ck & 1);
        __syncthreads();
    }

    int g = lane >> 2, tg = lane & 3;
    float mn = 1e30f, mx = -1e30f;
    #pragma unroll
    for (int mb = 0; mb < 4; mb++) {
        #pragma unroll
        for (int ug = 0; ug < 2; ug++) {
            int cb = col0 + wn + ug*32;
            int u0 = ((cb >> 5) << 3) + 2*tg;
            float iv[4], fv[4], gv[4], ov[4];
            #pragma unroll
            for (int e = 0; e < 4; e++) {
                int co = 2*tg + (e & 1);
                iv[e] = acc[mb][ug*4+0][e] + bias[cb + 0  + co];
                fv[e] = acc[mb][ug*4+1][e] + bias[cb + 8  + co];
                gv[e] = acc[mb][ug*4+2][e] + bias[cb + 16 + co];
                ov[e] = acc[mb][ug*4+3][e] + bias[cb + 24 + co];
            }
            #pragma unroll
            for (int half = 0; half < 2; half++) {
                int row = row0 + wm + mb*16 + g + half*8;
                float2 cc = *(const float2*)(c0v + (size_t)row*256 + u0);
                float cin[2] = {cc.x, cc.y};
                float hh[2], c2[2];
                #pragma unroll
                for (int e2 = 0; e2 < 2; e2++) {
                    int e = half*2 + e2;
                    float si = fsig(iv[e]);
                    float sf = fsig(fv[e]);
                    float so = fsig(ov[e]);
                    c2[e2] = sf * cin[e2] + si * ftanh(gv[e]);
                    hh[e2] = so * ftanh(c2[e2]);
                    mn = fminf(mn, hh[e2]); mx = fmaxf(mx, hh[e2]);
                }
                *(float2*)(hOut + (size_t)row*256 + u0) = make_float2(hh[0], hh[1]);
                *(float2*)(cOut + (size_t)row*256 + u0) = make_float2(c2[0], c2[1]);
            }
        }
    }
    __shared__ float smn[256], smx[256];
    smn[tid] = mn; smx[tid] = mx; __syncthreads();
    for (int s = 128; s > 0; s >>= 1) {
        if (tid < s) {
            smn[tid] = fminf(smn[tid], smn[tid+s]);
            smx[tid] = fmaxf(smx[tid], smx[tid+s]);
        }
        __syncthreads();
    }
    if (tid == 0) {
        int bid = blockIdx.y * gridDim.x + blockIdx.x;
        g_pmin[bid] = smn[0]; g_pmax[bid] = smx[0];
    }
}

// ---------------- fake-quant A: emits exact q = r - zp (single bf16) ---------
__global__ void quantA(const float* __restrict__ x,
                       __nv_bfloat16* __restrict__ q, int npart)
{
    __shared__ float smn[256], smx[256];
    __shared__ float sparam[2];
    float mn = 1e30f, mx = -1e30f;
    for (int i = threadIdx.x; i < npart; i += 256) {
        mn = fminf(mn, g_pmin[i]); mx = fmaxf(mx, g_pmax[i]);
    }
    smn[threadIdx.x] = mn; smx[threadIdx.x] = mx; __syncthreads();
    for (int s = 128; s > 0; s >>= 1) {
        if (threadIdx.x < s) {
            smn[threadIdx.x] = fminf(smn[threadIdx.x], smn[threadIdx.x+s]);
            smx[threadIdx.x] = fmaxf(smx[threadIdx.x], smx[threadIdx.x+s]);
        }
        __syncthreads();
    }
    if (threadIdx.x == 0) {
        float a = smn[0], b = smx[0];
        if (a == b) { a -= 0.01f; b += 0.01f; }
        float scale = (b - a) / 255.f;
        sparam[0] = scale;
        sparam[1] = rintf(-a / scale);
        if (blockIdx.x == 0) g_qscale = scale;
    }
    __syncthreads();
    float scale = sparam[0], zp = sparam[1];

    float part = 0.f;
    #pragma unroll
    for (int l = 0; l < 4; l++) {
        int i = blockIdx.x*256 + threadIdx.x + l*65536;
        float4 t = ((const float4*)x)[i];
        float ts[4] = {t.x, t.y, t.z, t.w};
        __nv_bfloat16 qs[4];
        #pragma unroll
        for (int e = 0; e < 4; e++) {
            float r = rintf(ts[e]/scale + zp);
            r = fminf(fmaxf(r, 0.f), 255.f);
            float qv = r - zp;
            qs[e] = __float2bfloat16(qv);     // exact (|q| <= 255)
            part += __log2f(fmaf(510.f, fabsf(qv * scale), 1.f));
        }
        *(uint2*)(q + i*4) = *(uint2*)qs;
    }
    __shared__ float sd[256];
    sd[threadIdx.x] = part; __syncthreads();
    for (int s = 128; s > 0; s >>= 1) { if (threadIdx.x < s) sd[threadIdx.x] += sd[threadIdx.x+s]; __syncthreads(); }
    if (threadIdx.x == 0) atomicAdd(&g_loss, sd[0]);
}

// ---------------- fake-quant T: emits exact q (transposed input) -------------
__global__ void quantT(const float* __restrict__ inT,
                       __nv_bfloat16* __restrict__ q, int npart)
{
    __shared__ float tile[32][33];
    __shared__ float smn[256], smx[256];
    __shared__ float sparam[2];
    int tx = threadIdx.x, ty = threadIdx.y;
    int tid = ty*32 + tx;

    float mn = (tid < npart) ? g_pmin[tid] : 1e30f;
    float mx = (tid < npart) ? g_pmax[tid] : -1e30f;
    smn[tid] = mn; smx[tid] = mx; __syncthreads();
    for (int s = 128; s > 0; s >>= 1) {
        if (tid < s) {
            smn[tid] = fminf(smn[tid], smn[tid+s]);
            smx[tid] = fmaxf(smx[tid], smx[tid+s]);
        }
        __syncthreads();
    }
    if (tid == 0) {
        float a = smn[0], b = smx[0];
        if (a == b) { a -= 0.01f; b += 0.01f; }
        float scale = (b - a) / 255.f;
        sparam[0] = scale;
        sparam[1] = rintf(-a / scale);
        if (blockIdx.x == 0 && blockIdx.y == 0) g_qscale = scale;
    }
    __syncthreads();
    float scale = sparam[0], zp = sparam[1];

    int c0 = blockIdx.y * 32;
    float part = 0.f;
    #pragma unroll 1
    for (int nt = 0; nt < 4; nt++) {
        int n0 = blockIdx.x * 128 + nt * 32;
        for (int cc = ty; cc < 32; cc += 8) {
            float t = inT[(size_t)(c0+cc)*NA + n0 + tx];
            float r = rintf(t/scale + zp);
            r = fminf(fmaxf(r, 0.f), 255.f);
            float qv = r - zp;
            tile[cc][tx] = qv;
            part += __log2f(fmaf(510.f, fabsf(qv * scale), 1.f));
        }
        __syncthreads();
        for (int nn = ty; nn < 32; nn += 8) {
            q[(size_t)(n0+nn)*256 + c0 + tx] = __float2bfloat16(tile[tx][nn]);
        }
        __syncthreads();
    }
    __shared__ float sd[256];
    sd[tid] = part; __syncthreads();
    for (int s = 128; s > 0; s >>= 1) { if (tid < s) sd[tid] += sd[tid+s]; __syncthreads(); }
    if (tid == 0) atomicAdd(&g_loss, sd[0]);
}

// ---------------- sortk ----------------
__global__ void __launch_bounds__(1024)
sortk()
{
    extern __shared__ char sms[];
    float* key = (float*)sms;
    int*   idx = (int*)(key + NA);
    float* sA  = (float*)(idx + NA);
    float* sB  = sA + NA;
    __shared__ float wsum[32];
    int h = blockIdx.x;
    int tid = threadIdx.x, lane = tid & 31, warp = tid >> 5;

    for (int i = tid; i < NA; i += 1024) { key[i] = g_cj[h*NA + i]; idx[i] = i; }
    __syncthreads();
    for (int k = 2; k <= NA; k <<= 1) {
        int j = k >> 1;
        for (; j >= 128; j >>= 1) {
            #pragma unroll 2
            for (int p = tid; p < NA/2; p += 1024) {
                int i = ((p & ~(j-1)) << 1) | (p & (j-1));
                int il = i | j;
                bool up = ((i & k) == 0);
                float a = key[i], b = key[il];
                if (up ? (a > b) : (a < b)) {
                    key[i] = b; key[il] = a;
                    int tmp = idx[i]; idx[i] = idx[il]; idx[il] = tmp;
                }
            }
            __syncthreads();
        }
        for (; j >= 1; j >>= 1) {
            #pragma unroll 2
            for (int q = lane; q < 64; q += 32) {
                int p = (warp << 6) | q;
                int i = ((p & ~(j-1)) << 1) | (p & (j-1));
                int il = i | j;
                bool up = ((i & k) == 0);
                float a = key[i], b = key[il];
                if (up ? (a > b) : (a < b)) {
                    key[i] = b; key[il] = a;
                    int tmp = idx[i]; idx[i] = idx[il]; idx[il] = tmp;
                }
            }
            __syncwarp();
        }
        __syncthreads();
    }
    float cm = key[NA-1];

    int t0 = tid * 4;
    float kw0 = key[t0], kw1 = key[t0+1], kw2 = key[t0+2], kw3 = key[t0+3];
    float wB0 = expf(0.2f*(kw0-cm)), wB1 = expf(0.2f*(kw1-cm));
    float wB2 = expf(0.2f*(kw2-cm)), wB3 = expf(0.2f*(kw3-cm));
    float wA0 = expf(kw0-cm), wA1 = expf(kw1-cm), wA2 = expf(kw2-cm), wA3 = expf(kw3-cm);
    *(int4*)&g_sidx[h*NA + t0] = make_int4(idx[t0], idx[t0+1], idx[t0+2], idx[t0+3]);
    *(float4*)&g_wA[h*NA + t0] = make_float4(wA0, wA1, wA2, wA3);
    *(float4*)&g_wB[h*NA + t0] = make_float4(wB0, wB1, wB2, wB3);

    {
        float v0 = wB0, v1 = v0+wB1, v2 = v1+wB2, v3 = v2+wB3;
        float tot = v3, s = tot;
        #pragma unroll
        for (int o = 1; o < 32; o <<= 1) { float u = __shfl_up_sync(0xffffffffu, s, o); if (lane >= o) s += u; }
        if (lane == 31) wsum[warp] = s;
        __syncthreads();
        if (warp == 0) {
            float y = wsum[lane];
            #pragma unroll
            for (int o = 1; o < 32; o <<= 1) { float u = __shfl_up_sync(0xffffffffu, y, o); if (lane >= o) y += u; }
            wsum[lane] = y;
        }
        __syncthreads();
        float off = (warp ? wsum[warp-1] : 0.f) + (s - tot);
        sB[t0] = off+v0; sB[t0+1] = off+v1; sB[t0+2] = off+v2; sB[t0+3] = off+v3;
    }
    __syncthreads();
    {
        int rb = NA - 4 - t0;
        float a0 = expf(key[rb]-cm),   a1 = expf(key[rb+1]-cm);
        float a2 = expf(key[rb+2]-cm), a3 = expf(key[rb+3]-cm);
        float u0 = a3, u1 = u0+a2, u2 = u1+a1, u3 = u2+a0;
        float tot = u3, s = tot;
        #pragma unroll
        for (int o = 1; o < 32; o <<= 1) { float u = __shfl_up_sync(0xffffffffu, s, o); if (lane >= o) s += u; }
        if (lane == 31) wsum[warp] = s;
        __syncthreads();
        if (warp == 0) {
            float y = wsum[lane];
            #pragma unroll
            for (int o = 1; o < 32; o <<= 1) { float u = __shfl_up_sync(0xffffffffu, y, o); if (lane >= o) y += u; }
            wsum[lane] = y;
        }
        __syncthreads();
        float off = (warp ? wsum[warp-1] : 0.f) + (s - tot);
        sA[rb] = off+u3; sA[rb+1] = off+u2; sA[rb+2] = off+u1; sA[rb+3] = off+u0;
    }
    __syncthreads();

    for (int l = 0; l < 4; l++) {
        int n = tid + l*1024;
        float cin = g_ci[h*NA + n];
        float t = -cin;
        int lo = 0, hi = NA;
        while (lo < hi) {
            int mid = (lo + hi) >> 1;
            if (key[mid] <= t) lo = mid + 1; else hi = mid;
        }
        float r = expf(0.8f * (cin + cm));
        float A = (lo < NA) ? sA[lo]     : 0.f;
        float B = (lo > 0)  ? sB[lo - 1] : 0.f;
        g_kcount[h*NA + n] = lo;
        g_rn[h*NA + n]     = r;
        g_invd[h*NA + n]   = 1.f / (r*A + B);
        g_ci[h*NA + n] = 0.f;
        g_cj[h*NA + n] = 0.f;
    }
}

// ---------------- scomb ----------------
__global__ void __launch_bounds__(512)
scomb(const float* __restrict__ bias, float* __restrict__ outT,
      int G, int do_elu, int do_mm)
{
    __shared__ float s_x[NA];
    __shared__ float s_pre[NA];
    __shared__ float s_suf[NA];
    __shared__ float wsum[16];
    int c = blockIdx.x;
    int h = c / G;
    int tid = threadIdx.x, lane = tid & 31, warp = tid >> 5;
    int t0 = tid * 8;
    const float* xrow = g_hWT + (size_t)c * NA;

    {
        int4 iva = *(const int4*)&g_sidx[h*NA + t0];
        int4 ivb = *(const int4*)&g_sidx[h*NA + t0 + 4];
        s_x[t0+0] = xrow[iva.x]; s_x[t0+1] = xrow[iva.y];
        s_x[t0+2] = xrow[iva.z]; s_x[t0+3] = xrow[iva.w];
        s_x[t0+4] = xrow[ivb.x]; s_x[t0+5] = xrow[ivb.y];
        s_x[t0+6] = xrow[ivb.z]; s_x[t0+7] = xrow[ivb.w];
    }
    __syncthreads();

    {
        float4 wa = *(const float4*)&g_wB[h*NA + t0];
        float4 wb = *(const float4*)&g_wB[h*NA + t0 + 4];
        float v[8];
        float run = wa.x * s_x[t0+0];   v[0] = run;
        run += wa.y * s_x[t0+1];        v[1] = run;
        run += wa.z * s_x[t0+2];        v[2] = run;
        run += wa.w * s_x[t0+3];        v[3] = run;
        run += wb.x * s_x[t0+4];        v[4] = run;
        run += wb.y * s_x[t0+5];        v[5] = run;
        run += wb.z * s_x[t0+6];        v[6] = run;
        run += wb.w * s_x[t0+7];        v[7] = run;
        float tot = run, s = tot;
        #pragma unroll
        for (int o = 1; o < 32; o <<= 1) { float u = __shfl_up_sync(0xffffffffu, s, o); if (lane >= o) s += u; }
        if (lane == 31) wsum[warp] = s;
        __syncthreads();
        if (warp == 0 && lane < 16) {
            float y = wsum[lane];
            #pragma unroll
            for (int o = 1; o < 16; o <<= 1) { float u = __shfl_up_sync(0xffffu, y, o); if (lane >= o) y += u; }
            wsum[lane] = y;
        }
        __syncthreads();
        float off = (warp ? wsum[warp-1] : 0.f) + (s - tot);
        #pragma unroll
        for (int e = 0; e < 8; e++) s_pre[t0+e] = off + v[e];
    }
    __syncthreads();
    {
        int rb = NA - 8 - t0;
        float4 wa = *(const float4*)&g_wA[h*NA + rb];
        float4 wb = *(const float4*)&g_wA[h*NA + rb + 4];
        float ws[8] = { wa.x, wa.y, wa.z, wa.w, wb.x, wb.y, wb.z, wb.w };
        float u[8];
        float run = ws[7]*s_x[rb+7];  u[0] = run;
        #pragma unroll
        for (int e = 1; e < 8; e++) { run += ws[7-e]*s_x[rb+7-e]; u[e] = run; }
        float tot = run, s = tot;
        #pragma unroll
        for (int o = 1; o < 32; o <<= 1) { float uu = __shfl_up_sync(0xffffffffu, s, o); if (lane >= o) s += uu; }
        if (lane == 31) wsum[warp] = s;
        __syncthreads();
        if (warp == 0 && lane < 16) {
            float y = wsum[lane];
            #pragma unroll
            for (int o = 1; o < 16; o <<= 1) { float uu = __shfl_up_sync(0xffffu, y, o); if (lane >= o) y += uu; }
            wsum[lane] = y;
        }
        __syncthreads();
        float off = (warp ? wsum[warp-1] : 0.f) + (s - tot);
        #pragma unroll
        for (int e = 0; e < 8; e++) s_suf[rb + 7 - e] = off + u[e];
    }
    __syncthreads();

    float bv = bias[c];
    float mn = 1e30f, mx = -1e30f;
    #pragma unroll
    for (int l = 0; l < 8; l++) {
        int n = tid + l*512;
        int k = g_kcount[h*NA + n];
        float r = g_rn[h*NA + n];
        float invd = g_invd[h*NA + n];
        float Av = (k < NA) ? s_suf[k]     : 0.f;
        float Bv = (k > 0)  ? s_pre[k - 1] : 0.f;
        float val = (r*Av + Bv) * invd + bv;
        if (do_elu) val = (val > 0.f) ? val : expm1f(val);
        mn = fminf(mn, val); mx = fmaxf(mx, val);
        outT[(size_t)c*NA + n] = val;
    }
    if (do_mm) {
        __shared__ float smn[512], smx[512];
        smn[tid] = mn; smx[tid] = mx; __syncthreads();
        for (int s = 256; s > 0; s >>= 1) {
            if (tid < s) {
                smn[tid] = fminf(smn[tid], smn[tid+s]);
                smx[tid] = fmaxf(smx[tid], smx[tid+s]);
            }
            __syncthreads();
        }
        if (tid == 0) { g_pmin[c] = smn[0]; g_pmax[c] = smx[0]; }
    }
}

// ---------------- fused policy + value head (+ loss write) ----------------
__global__ void __launch_bounds__(256)
policyk(const float* __restrict__ A0, const float* __restrict__ A1T,
        const float* __restrict__ Wa, const float* __restrict__ ba,
        const float* __restrict__ Wv, const float* __restrict__ bv,
        float* __restrict__ out_logp, float* __restrict__ out_value,
        float* __restrict__ out_loss)
{
    if (blockIdx.x == 0 && threadIdx.x == 0) out_loss[0] = g_loss;
    __shared__ float As[16][68];
    __shared__ float Bs[16][68];
    __shared__ float Ss[64][65];
    int tid = threadIdx.x;
    int tx = tid % 16, ty = tid / 16;
    int row0 = blockIdx.x * 64;
    float acc[4][4] = {};
    float vacc = 0.f;

    for (int k0 = 0; k0 < 512; k0 += 16) {
        if (k0 < 256) {
            int lin = tid * 4;
            int m = lin >> 4, kk = lin & 15;
            float4 v = *(const float4*)&A0[(size_t)(row0+m)*256 + k0 + kk];
            As[kk+0][m] = v.x; As[kk+1][m] = v.y; As[kk+2][m] = v.z; As[kk+3][m] = v.w;
        } else {
            int lin = tid * 4;
            int kk = lin >> 6, m4 = lin & 63;
            float4 v = *(const float4*)&A1T[(size_t)(k0-256+kk)*NA + row0 + m4];
            *(float4*)&As[kk][m4] = v;
        }
        {
            int lin = tid * 4;
            int kk = lin >> 6, n = lin & 63;
            *(float4*)&Bs[kk][n] = *(const float4*)&Wa[(size_t)(k0+kk)*64 + n];
        }
        __syncthreads();
        #pragma unroll
        for (int kk = 0; kk < 16; kk++) {
            float a[4], bb[4];
            #pragma unroll
            for (int i = 0; i < 4; i++) a[i] = As[kk][ty*4+i];
            #pragma unroll
            for (int j = 0; j < 4; j++) bb[j] = Bs[kk][tx*4+j];
            #pragma unroll
            for (int i = 0; i < 4; i++)
                #pragma unroll
                for (int j = 0; j < 4; j++)
                    acc[i][j] = fmaf(a[i], bb[j], acc[i][j]);
        }
        if (tid < 64) {
            #pragma unroll
            for (int kk = 0; kk < 16; kk++)
                vacc = fmaf(As[kk][tid], Wv[k0+kk], vacc);
        }
        __syncthreads();
    }
    if (tid < 64) out_value[row0 + tid] = vacc + bv[0];

    #pragma unroll
    for (int i = 0; i < 4; i++)
        #pragma unroll
        for (int j = 0; j < 4; j++)
            Ss[ty*4+i][tx*4+j] = acc[i][j] + ba[tx*4+j];
    __syncthreads();

    int row = tid >> 2, quad = tid & 3;
    float m = -1e30f;
    #pragma unroll
    for (int c = 0; c < 16; c++) m = fmaxf(m, Ss[row][quad*16 + c]);
    m = fmaxf(m, __shfl_xor_sync(0xffffffffu, m, 1));
    m = fmaxf(m, __shfl_xor_sync(0xffffffffu, m, 2));
    float s = 0.f;
    #pragma unroll
    for (int c = 0; c < 16; c++) s += expf(Ss[row][quad*16 + c] - m);
    s += __shfl_xor_sync(0xffffffffu, s, 1);
    s += __shfl_xor_sync(0xffffffffu, s, 2);
    float lse = m + logf(s);
    #pragma unroll
    for (int c = 0; c < 16; c++)
        out_logp[(size_t)(row0+row)*64 + quad*16 + c] = Ss[row][quad*16 + c] - lse;
}

// ---------------- host ----------------
extern "C" void kernel_launch(void* const* d_in, const int* in_sizes, int n_in,
                              void* d_out, int out_size)
{
    const float* obs  = (const float*)d_in[0];
    const float* h0   = (const float*)d_in[1];
    const float* c0   = (const float*)d_in[2];
    const float* Wobs = (const float*)d_in[3];
    const float* bobs = (const float*)d_in[4];
    const float* Wih  = (const float*)d_in[5];
    const float* Whh  = (const float*)d_in[6];
    const float* bih  = (const float*)d_in[7];
    const float* bhh  = (const float*)d_in[8];
    const float* W1   = (const float*)d_in[9];
    const float* ai1  = (const float*)d_in[10];
    const float* aj1  = (const float*)d_in[11];
    const float* b1   = (const float*)d_in[12];
    const float* W2   = (const float*)d_in[13];
    const float* ai2  = (const float*)d_in[14];
    const float* aj2  = (const float*)d_in[15];
    const float* b2   = (const float*)d_in[16];
    const float* Wv   = (const float*)d_in[17];
    const float* bv   = (const float*)d_in[18];
    const float* Wa   = (const float*)d_in[19];
    const float* ba   = (const float*)d_in[20];

    float* out       = (float*)d_out;
    float* out_logp  = out;
    float* out_value = out + NA*ACT;
    float* out_h     = out_value + NA;
    float* out_c     = out_h + NA*HD;
    float* out_loss  = out_c + NA*HD;

    float *p_hWT, *p_commT, *p_bsum, *p_qscale;
    __nv_bfloat16 *p_Ah, *p_Al, *p_A2h, *p_A2l;
    __nv_bfloat16 *p_B0h, *p_B0l, *p_Bgh, *p_Bgl, *p_B1h, *p_B1l, *p_B2h, *p_B2l;
    cudaGetSymbolAddress((void**)&p_hWT,    g_hWT);
    cudaGetSymbolAddress((void**)&p_commT,  g_commT);
    cudaGetSymbolAddress((void**)&p_bsum,   g_bsum);
    cudaGetSymbolAddress((void**)&p_qscale, g_qscale);
    cudaGetSymbolAddress((void**)&p_Ah,     g_Ah);
    cudaGetSymbolAddress((void**)&p_Al,     g_Al);
    cudaGetSymbolAddress((void**)&p_A2h,    g_A2h);
    cudaGetSymbolAddress((void**)&p_A2l,    g_A2l);
    cudaGetSymbolAddress((void**)&p_B0h,    g_B0h);
    cudaGetSymbolAddress((void**)&p_B0l,    g_B0l);
    cudaGetSymbolAddress((void**)&p_Bgh,    g_Bgh);
    cudaGetSymbolAddress((void**)&p_Bgl,    g_Bgl);
    cudaGetSymbolAddress((void**)&p_B1h,    g_B1h);
    cudaGetSymbolAddress((void**)&p_B1l,    g_B1l);
    cudaGetSymbolAddress((void**)&p_B2h,    g_B2h);
    cudaGetSymbolAddress((void**)&p_B2l,    g_B2l);

    const int SM64  = TG_SMEM_BYTES(64);
    const int SMSORT = NA * 16;
    cudaFuncSetAttribute((const void*)tgemm<64,false>, cudaFuncAttributeMaxDynamicSharedMemorySize, SM64);
    cudaFuncSetAttribute((const void*)tgemm<64,true>,  cudaFuncAttributeMaxDynamicSharedMemorySize, SM64);
    cudaFuncSetAttribute((const void*)gatesk,          cudaFuncAttributeMaxDynamicSharedMemorySize, GW_SMEM);
    cudaFuncSetAttribute((const void*)sortk,           cudaFuncAttributeMaxDynamicSharedMemorySize, SMSORT);

    // 1. prep
    wprep<<<(WVTOT + 255)/256, 256>>>(obs, h0, Wobs, Wih, Whh, W1, W2, bih, bhh, bobs);
    // 2. weight-product GEMM -> Bg cols 0..255 (split output, 3-pass)
    tgemm<64,false><<<dim3(2, 16), 256, SM64>>>(p_A2h, p_A2l, p_B0h, p_B0l, nullptr, nullptr,
                                                p_Bgh, p_Bgl, 512,
                                                nullptr, nullptr, nullptr, 0, 256, 256);
    // 3. gates GEMM (128x256 tile, single wave) + fused LSTM
    gatesk<<<dim3(4, 32), 256, GW_SMEM>>>(p_Ah, p_Al, p_Bgh, p_Bgl, p_bsum,
                                          c0, out_h, out_c, 512);
    // 4. quant #1 -> exact q into A2h + g_qscale
    quantA<<<256, 256>>>(out_h, p_A2h, 128);
    // 5. GAT1 projection (2-pass, scaled epilogue) -> hWT + fused ci/cj
    tgemm<64,true><<<dim3(2, 64), 256, SM64>>>(p_A2h, nullptr, p_B1h, p_B1l, nullptr, p_qscale,
                                               nullptr, nullptr, 0,
                                               p_hWT, ai1, aj1, 64, 256, 256);
    // 6-7. GAT1 attention
    sortk<<<4, 1024, SMSORT>>>();
    scomb<<<256, 512>>>(b1, p_commT, 64, 1, 1);
    // 8. quant #2 (transposed input) -> exact q + g_qscale
    quantT<<<dim3(NA/128, 8), dim3(32, 8)>>>(p_commT, p_A2h, 256);
    // 9. GAT2 projection (2-pass, scaled epilogue)
    tgemm<64,true><<<dim3(2, 64), 256, SM64>>>(p_A2h, nullptr, p_B2h, p_B2l, nullptr, p_qscale,
                                               nullptr, nullptr, 0,
                                               p_hWT, ai2, aj2, 256, 256, 256);
    // 10-11. GAT2 attention
    sortk<<<1, 1024, SMSORT>>>();
    scomb<<<256, 512>>>(b2, p_commT, 256, 0, 0);
    // 12. fused policy + value heads + loss
    policyk<<<NA/64, 256>>>(out_h, p_commT, Wa, ba, Wv, bv, out_logp, out_value, out_loss);
}

// round 17
// speedup vs baseline: 1.1172x; 1.0250x over previous
#include <cuda_runtime.h>
#include <cuda_bf16.h>
#include <math.h>
#include <stdint.h>

#define NA   4096
#define HD   256
#define HG   256
#define ACT  64
#define MMB  1024

// ---------------- device scratch ----------------
__device__ float g_hWT[HG*NA];
__device__ float g_commT[HG*NA];
__device__ float g_bsum[4*HD];
__device__ __nv_bfloat16 g_Ah[NA*512];
__device__ __nv_bfloat16 g_Al[NA*512];
__device__ __nv_bfloat16 g_A2h[NA*256];      // quantized q = r - zp (exact bf16)
__device__ __nv_bfloat16 g_A2l[NA*256];      // wgemm A lo
__device__ __nv_bfloat16 g_B0h[256*256], g_B0l[256*256];
__device__ __nv_bfloat16 g_Bgh[1024*512], g_Bgl[1024*512];
__device__ __nv_bfloat16 g_B1h[256*256], g_B1l[256*256];
__device__ __nv_bfloat16 g_B2h[256*256], g_B2l[256*256];
__device__ float g_ci[4*NA];
__device__ float g_cj[4*NA];
__device__ int   g_kcount[4*NA];
__device__ int   g_sidx[4*NA];
__device__ float g_wA[4*NA];
__device__ float g_wB[4*NA];
__device__ float g_rn[4*NA];
__device__ float g_invd[4*NA];
__device__ float g_pmin[MMB];
__device__ float g_pmax[MMB];
__device__ float g_qscale;
__device__ float g_loss;

__device__ __forceinline__ void bf16split(float x, __nv_bfloat16* hi, __nv_bfloat16* lo) {
    __nv_bfloat16 h = __float2bfloat16(x);
    *hi = h;
    *lo = __float2bfloat16(x - __bfloat162float(h));
}
__device__ __forceinline__ float fsig(float x) { return 1.f / (1.f + __expf(-x)); }
__device__ __forceinline__ float ftanh(float x) {
    float ax = fabsf(x);
    float e = __expf(-2.f * ax);
    float t = (1.f - e) / (1.f + e);
    return copysignf(t, x);
}
__device__ __forceinline__ void split4(const float* v, __nv_bfloat16* hi, __nv_bfloat16* lo) {
    __nv_bfloat16 h[4], l[4];
    #pragma unroll
    for (int e = 0; e < 4; e++) bf16split(v[e], &h[e], &l[e]);
    *(uint2*)hi = *(uint2*)h;
    *(uint2*)lo = *(uint2*)l;
}

// ---------------- fused prep (vectorized) ----------------
#define WV0 (NA*64)
#define WV1 (WV0 + NA*64)
#define WV2 (WV1 + 16384)
#define WV3 (WV2 + 65536)
#define WV4 (WV3 + 65536)
#define WV5 (WV4 + 16384)
#define WV6 (WV5 + 16384)
#define WV7 (WV6 + 4096)
#define WVTOT (WV7 + 32768)
__global__ void wprep(const float* __restrict__ obs, const float* __restrict__ h0,
                      const float* __restrict__ Wobs,
                      const float* __restrict__ Wih, const float* __restrict__ Whh,
                      const float* __restrict__ W1, const float* __restrict__ W2,
                      const float* __restrict__ bih, const float* __restrict__ bhh,
                      const float* __restrict__ bobs)
{
    int idx = blockIdx.x*256 + threadIdx.x;
    if (idx == 0) g_loss = 0.f;
    if (idx < WV0) {
        int j = idx * 4;
        int n = j >> 8, k = j & 255;
        int d = n*512 + k;
        float4 v = *(const float4*)(obs + j);
        split4(&v.x, &g_Ah[d], &g_Al[d]);
    } else if (idx < WV1) {
        int j = (idx - WV0) * 4;
        int n = j >> 8, k = j & 255;
        int d = n*512 + 256 + k;
        float4 v = *(const float4*)(h0 + j);
        split4(&v.x, &g_Ah[d], &g_Al[d]);
    } else if (idx < WV2) {
        int j = (idx - WV1) * 4;
        float4 v = *(const float4*)(Wobs + j);
        split4(&v.x, &g_B0h[j], &g_B0l[j]);
    } else if (idx < WV3) {
        int j = (idx - WV2) * 4;
        int r = j >> 8, k = j & 255;
        int G = (r >> 3) & 3;
        int u = ((r >> 5) << 3) | (r & 7);
        float4 v = *(const float4*)(Wih + (G*256 + u)*256 + k);
        split4(&v.x, &g_A2h[j], &g_A2l[j]);
    } else if (idx < WV4) {
        int j = (idx - WV3) * 4;
        int r = j >> 8, k = j & 255;
        int G = (r >> 3) & 3;
        int u = ((r >> 5) << 3) | (r & 7);
        int d = r*512 + 256 + k;
        float4 v = *(const float4*)(Whh + (G*256 + u)*256 + k);
        split4(&v.x, &g_Bgh[d], &g_Bgl[d]);
    } else if (idx < WV5) {
        int j = (idx - WV4) * 4;
        int n = j >> 8, k = j & 255;
        float vv[4];
        #pragma unroll
        for (int e = 0; e < 4; e++) vv[e] = W1[(k+e)*256 + n];
        split4(vv, &g_B1h[j], &g_B1l[j]);
    } else if (idx < WV6) {
        int j = (idx - WV5) * 4;
        int n = j >> 8, k = j & 255;
        float vv[4];
        #pragma unroll
        for (int e = 0; e < 4; e++) vv[e] = W2[(k+e)*256 + n];
        split4(vv, &g_B2h[j], &g_B2l[j]);
    } else if (idx < WV7) {
        int j = (idx - WV6);
        float4 z = make_float4(0.f, 0.f, 0.f, 0.f);
        ((float4*)g_ci)[j] = z;
        ((float4*)g_cj)[j] = z;
    } else if (idx < WVTOT) {
        int t = idx - WV7;
        int r = t >> 5, lane = t & 31;
        int G = (r >> 3) & 3;
        int u = ((r >> 5) << 3) | (r & 7);
        int orow = G*256 + u;
        float s = 0.f;
        #pragma unroll
        for (int k = lane; k < 256; k += 32)
            s = fmaf(bobs[k], Wih[orow*256 + k], s);
        for (int o = 16; o > 0; o >>= 1) s += __shfl_down_sync(0xffffffffu, s, o);
        if (lane == 0) g_bsum[r] = s + bih[orow] + bhh[orow];
    }
}

// ---------------- mma.sync helpers ----------------
__device__ __forceinline__ uint32_t cvta_sm(const void* p) {
    uint32_t a;
    asm("{ .reg .u64 t; cvta.to.shared.u64 t, %1; cvt.u32.u64 %0, t; }" : "=r"(a) : "l"(p));
    return a;
}
__device__ __forceinline__ void ldm_x4(uint32_t (&d)[4], uint32_t addr) {
    asm volatile("ldmatrix.sync.aligned.m8n8.x4.shared.b16 {%0,%1,%2,%3}, [%4];"
        : "=r"(d[0]), "=r"(d[1]), "=r"(d[2]), "=r"(d[3]) : "r"(addr));
}
__device__ __forceinline__ void mma16816(float (&c)[4], const uint32_t (&a)[4],
                                         uint32_t b0, uint32_t b1) {
    asm volatile("mma.sync.aligned.m16n8k16.row.col.f32.bf16.bf16.f32 "
        "{%0,%1,%2,%3},{%4,%5,%6,%7},{%8,%9},{%0,%1,%2,%3};"
        : "+f"(c[0]), "+f"(c[1]), "+f"(c[2]), "+f"(c[3])
        : "r"(a[0]), "r"(a[1]), "r"(a[2]), "r"(a[3]), "r"(b0), "r"(b1));
}

// ---------------- split-bf16 tensor GEMM (BM=64), cp.async 3-stage -----------
#define TG_STRIDE 40
#define TG_STAGE_ELE(BM)   (2*(BM)*TG_STRIDE + 2*128*TG_STRIDE)
#define TG_SMEM_BYTES(BM)  (3 * TG_STAGE_ELE(BM) * 2)

template<int BM, bool AONE>
__global__ void __launch_bounds__(256, 2)
tgemm(const __nv_bfloat16* __restrict__ Ah, const __nv_bfloat16* __restrict__ Al,
      const __nv_bfloat16* __restrict__ Bh, const __nv_bfloat16* __restrict__ Bl,
      const float* __restrict__ bias, const float* __restrict__ ascale,
      __nv_bfloat16* __restrict__ Shi, __nv_bfloat16* __restrict__ Slo, int ldS,
      float* __restrict__ hwT, const float* __restrict__ aivec,
      const float* __restrict__ ajvec, int Gh,
      int N, int K)
{
    constexpr int A_ELE = BM * TG_STRIDE;
    constexpr int B_ELE = 128 * TG_STRIDE;
    constexpr int STAGE = 2*A_ELE + 2*B_ELE;
    constexpr int NWM  = BM / 32;
    constexpr int WN   = 128 / (8 / NWM);
    constexpr int NB16 = WN / 16;
    constexpr int NB   = WN / 8;
    constexpr int A_U4 = BM * 4;
    constexpr int B_U4 = 512;
    constexpr int NAA  = AONE ? 1 : 2;
    constexpr int TOT_U4 = NAA*A_U4 + 2*B_U4;

    extern __shared__ __nv_bfloat16 sm[];
    int tid = threadIdx.x, lane = tid & 31, wid = tid >> 5;
    int col0 = blockIdx.x * 128, row0 = blockIdx.y * BM;
    int wm = (wid % NWM) * 32, wn = (wid / NWM) * WN;
    uint32_t sb = cvta_sm(sm);

    float acc[2][NB][4] = {};

    auto issue = [&](int stage, int k0) {
        uint32_t stb = sb + (uint32_t)stage * STAGE * 2;
        #pragma unroll
        for (int l = 0; l < TOT_U4/256; l++) {
            int i = tid + l * 256;
            const __nv_bfloat16* src;
            int r, c8;
            uint32_t soff;
            if (i < NAA*A_U4) {
                int a = i / A_U4, j = i % A_U4;
                r = j >> 2; c8 = j & 3;
                src = (a ? Al : Ah) + (size_t)(row0 + r) * K;
                soff = (uint32_t)a * A_ELE;
            } else {
                int i2 = i - NAA*A_U4;
                int a = i2 / B_U4, j = i2 % B_U4;
                r = j >> 2; c8 = j & 3;
                src = (a ? Bl : Bh) + (size_t)(col0 + r) * K;
                soff = 2*A_ELE + (uint32_t)a * B_ELE;
            }
            uint32_t dst = stb + (soff + r * TG_STRIDE + c8 * 8) * 2;
            const __nv_bfloat16* g = src + k0 + c8 * 8;
            asm volatile("cp.async.cg.shared.global [%0], [%1], 16;" :: "r"(dst), "l"(g));
        }
        asm volatile("cp.async.commit_group;" ::: "memory");
    };

    auto compute = [&](int stage) {
        uint32_t stb = sb + (uint32_t)stage * STAGE * 2;
        uint32_t bA_h = stb, bA_l = stb + A_ELE*2;
        uint32_t bB_h = stb + 2*A_ELE*2, bB_l = stb + (2*A_ELE + B_ELE)*2;
        #pragma unroll
        for (int kk = 0; kk < 32; kk += 16) {
            uint32_t ah[2][4], al[2][4];
            #pragma unroll
            for (int mb = 0; mb < 2; mb++) {
                int r = wm + mb * 16 + (lane & 15);
                int c = kk + (lane >> 4) * 8;
                uint32_t off = (uint32_t)(r * TG_STRIDE + c) * 2;
                ldm_x4(ah[mb], bA_h + off);
                if constexpr (!AONE) ldm_x4(al[mb], bA_l + off);
            }
            #pragma unroll
            for (int nb = 0; nb < NB16; nb++) {
                int r = wn + nb * 16 + ((lane >> 4) << 3) + (lane & 7);
                int c = kk + ((lane >> 3) & 1) * 8;
                uint32_t off = (uint32_t)(r * TG_STRIDE + c) * 2;
                uint32_t bh[4], bl[4];
                ldm_x4(bh, bB_h + off);
                ldm_x4(bl, bB_l + off);
                #pragma unroll
                for (int mb = 0; mb < 2; mb++) {
                    mma16816(acc[mb][2*nb+0], ah[mb], bh[0], bh[1]);
                    mma16816(acc[mb][2*nb+1], ah[mb], bh[2], bh[3]);
                    mma16816(acc[mb][2*nb+0], ah[mb], bl[0], bl[1]);
                    mma16816(acc[mb][2*nb+1], ah[mb], bl[2], bl[3]);
                    if constexpr (!AONE) {
                        mma16816(acc[mb][2*nb+0], al[mb], bh[0], bh[1]);
                        mma16816(acc[mb][2*nb+1], al[mb], bh[2], bh[3]);
                    }
                }
            }
        }
    };

    int nch = K >> 5;
    issue(0, 0);
    if (nch > 1) issue(1, 32);
    for (int ck = 0; ck < nch; ck++) {
        if (ck + 2 < nch) {
            issue((ck + 2) % 3, (ck + 2) << 5);
            asm volatile("cp.async.wait_group 2;" ::: "memory");
        } else if (ck + 1 < nch) {
            asm volatile("cp.async.wait_group 1;" ::: "memory");
        } else {
            asm volatile("cp.async.wait_group 0;" ::: "memory");
        }
        __syncthreads();
        compute(ck % 3);
        __syncthreads();
    }

    int g = lane >> 2, tg = lane & 3;
    float s = ascale ? *ascale : 1.f;

    float cia[2][2] = {}, cja[2][2] = {};
    #pragma unroll
    for (int mb = 0; mb < 2; mb++) {
        #pragma unroll
        for (int n8 = 0; n8 < NB; n8++) {
            int row = row0 + wm + mb * 16 + g;
            int col = col0 + wn + n8 * 8 + 2 * tg;
            float b0 = bias ? bias[col]   : 0.f;
            float b1 = bias ? bias[col+1] : 0.f;
            float v00 = acc[mb][n8][0] * s + b0, v01 = acc[mb][n8][1] * s + b1;
            float v10 = acc[mb][n8][2] * s + b0, v11 = acc[mb][n8][3] * s + b1;
            if (Shi) {
                size_t d0 = (size_t)row * ldS + col;
                size_t d1 = (size_t)(row + 8) * ldS + col;
                bf16split(v00, &Shi[d0],   &Slo[d0]);
                bf16split(v01, &Shi[d0+1], &Slo[d0+1]);
                bf16split(v10, &Shi[d1],   &Slo[d1]);
                bf16split(v11, &Shi[d1+1], &Slo[d1+1]);
            }
            if (hwT) {
                hwT[(size_t)col*NA + row]         = v00;
                hwT[(size_t)(col+1)*NA + row]     = v01;
                hwT[(size_t)col*NA + row + 8]     = v10;
                hwT[(size_t)(col+1)*NA + row + 8] = v11;
            }
            if (aivec) {
                float a0 = aivec[col], a1 = aivec[col+1];
                float j0 = ajvec[col], j1 = ajvec[col+1];
                cia[mb][0] += v00*a0 + v01*a1;
                cia[mb][1] += v10*a0 + v11*a1;
                cja[mb][0] += v00*j0 + v01*j1;
                cja[mb][1] += v10*j0 + v11*j1;
            }
        }
    }
    if (aivec) {
        int hh = (col0 + wn) / Gh;
        #pragma unroll
        for (int mb = 0; mb < 2; mb++) {
            #pragma unroll
            for (int hf = 0; hf < 2; hf++) {
                float ci = cia[mb][hf], cj = cja[mb][hf];
                ci += __shfl_xor_sync(0xffffffffu, ci, 1);
                ci += __shfl_xor_sync(0xffffffffu, ci, 2);
                cj += __shfl_xor_sync(0xffffffffu, cj, 1);
                cj += __shfl_xor_sync(0xffffffffu, cj, 2);
                if (tg == 0) {
                    int row = row0 + wm + mb * 16 + g + hf * 8;
                    atomicAdd(&g_ci[hh*NA + row], ci);
                    atomicAdd(&g_cj[hh*NA + row], cj);
                }
            }
        }
    }
}

// ---------------- gates GEMM: 128x256 tile, 64x64 warp tiles, fused LSTM -----
#define GW_A_ELE (128*TG_STRIDE)
#define GW_B_ELE (256*TG_STRIDE)
#define GW_STAGE (2*GW_A_ELE + 2*GW_B_ELE)
#define GW_SMEM  (2 * GW_STAGE * 2)

__global__ void __launch_bounds__(256, 1)
gatesk(const __nv_bfloat16* __restrict__ Ah, const __nv_bfloat16* __restrict__ Al,
       const __nv_bfloat16* __restrict__ Bh, const __nv_bfloat16* __restrict__ Bl,
       const float* __restrict__ bias,
       const float* __restrict__ c0v, float* __restrict__ hOut, float* __restrict__ cOut,
       int K)
{
    extern __shared__ __nv_bfloat16 sm[];
    int tid = threadIdx.x, lane = tid & 31, wid = tid >> 5;
    int col0 = blockIdx.x * 256, row0 = blockIdx.y * 128;
    int wm = (wid & 1) * 64, wn = (wid >> 1) * 64;
    uint32_t sb = cvta_sm(sm);

    float acc[4][8][4] = {};

    auto issue = [&](int stage, int k0) {
        uint32_t stb = sb + (uint32_t)stage * GW_STAGE * 2;
        #pragma unroll
        for (int l = 0; l < 12; l++) {
            int i = tid + l * 256;
            const __nv_bfloat16* src;
            int r, c8;
            uint32_t soff;
            if (i < 1024) {
                int a = i >> 9, j = i & 511;
                r = j >> 2; c8 = j & 3;
                src = (a ? Al : Ah) + (size_t)(row0 + r) * K;
                soff = (uint32_t)a * GW_A_ELE;
            } else {
                int i2 = i - 1024;
                int a = i2 >> 10, j = i2 & 1023;
                r = j >> 2; c8 = j & 3;
                src = (a ? Bl : Bh) + (size_t)(col0 + r) * K;
                soff = 2*GW_A_ELE + (uint32_t)a * GW_B_ELE;
            }
            uint32_t dst = stb + (soff + r * TG_STRIDE + c8 * 8) * 2;
            const __nv_bfloat16* g = src + k0 + c8 * 8;
            asm volatile("cp.async.cg.shared.global [%0], [%1], 16;" :: "r"(dst), "l"(g));
        }
        asm volatile("cp.async.commit_group;" ::: "memory");
    };

    auto compute = [&](int stage) {
        uint32_t stb = sb + (uint32_t)stage * GW_STAGE * 2;
        uint32_t bA_h = stb, bA_l = stb + GW_A_ELE*2;
        uint32_t bB_h = stb + 2*GW_A_ELE*2, bB_l = stb + (2*GW_A_ELE + GW_B_ELE)*2;
        #pragma unroll
        for (int kk = 0; kk < 32; kk += 16) {
            uint32_t ah[4][4], al[4][4];
            #pragma unroll
            for (int mb = 0; mb < 4; mb++) {
                int r = wm + mb * 16 + (lane & 15);
                int c = kk + (lane >> 4) * 8;
                uint32_t off = (uint32_t)(r * TG_STRIDE + c) * 2;
                ldm_x4(ah[mb], bA_h + off);
                ldm_x4(al[mb], bA_l + off);
            }
            #pragma unroll
            for (int nb = 0; nb < 4; nb++) {
                int r = wn + nb * 16 + ((lane >> 4) << 3) + (lane & 7);
                int c = kk + ((lane >> 3) & 1) * 8;
                uint32_t off = (uint32_t)(r * TG_STRIDE + c) * 2;
                uint32_t bh[4], bl[4];
                ldm_x4(bh, bB_h + off);
                ldm_x4(bl, bB_l + off);
                #pragma unroll
                for (int mb = 0; mb < 4; mb++) {
                    mma16816(acc[mb][2*nb+0], ah[mb], bh[0], bh[1]);
                    mma16816(acc[mb][2*nb+1], ah[mb], bh[2], bh[3]);
                    mma16816(acc[mb][2*nb+0], ah[mb], bl[0], bl[1]);
                    mma16816(acc[mb][2*nb+1], ah[mb], bl[2], bl[3]);
                    mma16816(acc[mb][2*nb+0], al[mb], bh[0], bh[1]);
                    mma16816(acc[mb][2*nb+1], al[mb], bh[2], bh[3]);
                }
            }
        }
    };

    int nch = K >> 5;
    issue(0, 0);
    for (int ck = 0; ck < nch; ck++) {
        if (ck + 1 < nch) {
            issue((ck + 1) & 1, (ck + 1) << 5);
            asm volatile("cp.async.wait_group 1;" ::: "memory");
        } else {
            asm volatile("cp.async.wait_group 0;" ::: "memory");
        }
        __syncthreads();
        compute(ck & 1);
        __syncthreads();
    }

    int g = lane >> 2, tg = lane & 3;
    float mn = 1e30f, mx = -1e30f;
    #pragma unroll
    for (int mb = 0; mb < 4; mb++) {
        #pragma unroll
        for (int ug = 0; ug < 2; ug++) {
            int cb = col0 + wn + ug*32;
            int u0 = ((cb >> 5) << 3) + 2*tg;
            float iv[4], fv[4], gv[4], ov[4];
            #pragma unroll
            for (int e = 0; e < 4; e++) {
                int co = 2*tg + (e & 1);
                iv[e] = acc[mb][ug*4+0][e] + bias[cb + 0  + co];
                fv[e] = acc[mb][ug*4+1][e] + bias[cb + 8  + co];
                gv[e] = acc[mb][ug*4+2][e] + bias[cb + 16 + co];
                ov[e] = acc[mb][ug*4+3][e] + bias[cb + 24 + co];
            }
            #pragma unroll
            for (int half = 0; half < 2; half++) {
                int row = row0 + wm + mb*16 + g + half*8;
                float2 cc = *(const float2*)(c0v + (size_t)row*256 + u0);
                float cin[2] = {cc.x, cc.y};
                float hh[2], c2[2];
                #pragma unroll
                for (int e2 = 0; e2 < 2; e2++) {
                    int e = half*2 + e2;
                    float si = fsig(iv[e]);
                    float sf = fsig(fv[e]);
                    float so = fsig(ov[e]);
                    c2[e2] = sf * cin[e2] + si * ftanh(gv[e]);
                    hh[e2] = so * ftanh(c2[e2]);
                    mn = fminf(mn, hh[e2]); mx = fmaxf(mx, hh[e2]);
                }
                *(float2*)(hOut + (size_t)row*256 + u0) = make_float2(hh[0], hh[1]);
                *(float2*)(cOut + (size_t)row*256 + u0) = make_float2(c2[0], c2[1]);
            }
        }
    }
    __shared__ float smn[256], smx[256];
    smn[tid] = mn; smx[tid] = mx; __syncthreads();
    for (int s = 128; s > 0; s >>= 1) {
        if (tid < s) {
            smn[tid] = fminf(smn[tid], smn[tid+s]);
            smx[tid] = fmaxf(smx[tid], smx[tid+s]);
        }
        __syncthreads();
    }
    if (tid == 0) {
        int bid = blockIdx.y * gridDim.x + blockIdx.x;
        g_pmin[bid] = smn[0]; g_pmax[bid] = smx[0];
    }
}

// ---------------- fake-quant A: emits exact q = r - zp (single bf16) ---------
__global__ void quantA(const float* __restrict__ x,
                       __nv_bfloat16* __restrict__ q, int npart)
{
    __shared__ float smn[256], smx[256];
    __shared__ float sparam[2];
    float mn = 1e30f, mx = -1e30f;
    for (int i = threadIdx.x; i < npart; i += 256) {
        mn = fminf(mn, g_pmin[i]); mx = fmaxf(mx, g_pmax[i]);
    }
    smn[threadIdx.x] = mn; smx[threadIdx.x] = mx; __syncthreads();
    for (int s = 128; s > 0; s >>= 1) {
        if (threadIdx.x < s) {
            smn[threadIdx.x] = fminf(smn[threadIdx.x], smn[threadIdx.x+s]);
            smx[threadIdx.x] = fmaxf(smx[threadIdx.x], smx[threadIdx.x+s]);
        }
        __syncthreads();
    }
    if (threadIdx.x == 0) {
        float a = smn[0], b = smx[0];
        if (a == b) { a -= 0.01f; b += 0.01f; }
        float scale = (b - a) / 255.f;
        sparam[0] = scale;
        sparam[1] = rintf(-a / scale);
        if (blockIdx.x == 0) g_qscale = scale;
    }
    __syncthreads();
    float scale = sparam[0], zp = sparam[1];

    float part = 0.f;
    #pragma unroll
    for (int l = 0; l < 4; l++) {
        int i = blockIdx.x*256 + threadIdx.x + l*65536;
        float4 t = ((const float4*)x)[i];
        float ts[4] = {t.x, t.y, t.z, t.w};
        __nv_bfloat16 qs[4];
        #pragma unroll
        for (int e = 0; e < 4; e++) {
            float r = rintf(ts[e]/scale + zp);
            r = fminf(fmaxf(r, 0.f), 255.f);
            float qv = r - zp;
            qs[e] = __float2bfloat16(qv);
            part += __log2f(fmaf(510.f, fabsf(qv * scale), 1.f));
        }
        *(uint2*)(q + i*4) = *(uint2*)qs;
    }
    __shared__ float sd[256];
    sd[threadIdx.x] = part; __syncthreads();
    for (int s = 128; s > 0; s >>= 1) { if (threadIdx.x < s) sd[threadIdx.x] += sd[threadIdx.x+s]; __syncthreads(); }
    if (threadIdx.x == 0) atomicAdd(&g_loss, sd[0]);
}

// ---------------- fake-quant T: emits exact q (transposed input) -------------
__global__ void quantT(const float* __restrict__ inT,
                       __nv_bfloat16* __restrict__ q, int npart)
{
    __shared__ float tile[32][33];
    __shared__ float smn[256], smx[256];
    __shared__ float sparam[2];
    int tx = threadIdx.x, ty = threadIdx.y;
    int tid = ty*32 + tx;

    float mn = (tid < npart) ? g_pmin[tid] : 1e30f;
    float mx = (tid < npart) ? g_pmax[tid] : -1e30f;
    smn[tid] = mn; smx[tid] = mx; __syncthreads();
    for (int s = 128; s > 0; s >>= 1) {
        if (tid < s) {
            smn[tid] = fminf(smn[tid], smn[tid+s]);
            smx[tid] = fmaxf(smx[tid], smx[tid+s]);
        }
        __syncthreads();
    }
    if (tid == 0) {
        float a = smn[0], b = smx[0];
        if (a == b) { a -= 0.01f; b += 0.01f; }
        float scale = (b - a) / 255.f;
        sparam[0] = scale;
        sparam[1] = rintf(-a / scale);
        if (blockIdx.x == 0 && blockIdx.y == 0) g_qscale = scale;
    }
    __syncthreads();
    float scale = sparam[0], zp = sparam[1];

    int c0 = blockIdx.y * 32;
    float part = 0.f;
    #pragma unroll 1
    for (int nt = 0; nt < 4; nt++) {
        int n0 = blockIdx.x * 128 + nt * 32;
        for (int cc = ty; cc < 32; cc += 8) {
            float t = inT[(size_t)(c0+cc)*NA + n0 + tx];
            float r = rintf(t/scale + zp);
            r = fminf(fmaxf(r, 0.f), 255.f);
            float qv = r - zp;
            tile[cc][tx] = qv;
            part += __log2f(fmaf(510.f, fabsf(qv * scale), 1.f));
        }
        __syncthreads();
        for (int nn = ty; nn < 32; nn += 8) {
            q[(size_t)(n0+nn)*256 + c0 + tx] = __float2bfloat16(tile[tx][nn]);
        }
        __syncthreads();
    }
    __shared__ float sd[256];
    sd[tid] = part; __syncthreads();
    for (int s = 128; s > 0; s >>= 1) { if (tid < s) sd[tid] += sd[tid+s]; __syncthreads(); }
    if (tid == 0) atomicAdd(&g_loss, sd[0]);
}

// ---------------- sortk ----------------
__global__ void __launch_bounds__(1024)
sortk()
{
    extern __shared__ char sms[];
    float* key = (float*)sms;
    int*   idx = (int*)(key + NA);
    float* sA  = (float*)(idx + NA);
    float* sB  = sA + NA;
    __shared__ float wsum[32];
    int h = blockIdx.x;
    int tid = threadIdx.x, lane = tid & 31, warp = tid >> 5;

    for (int i = tid; i < NA; i += 1024) { key[i] = g_cj[h*NA + i]; idx[i] = i; }
    __syncthreads();
    for (int k = 2; k <= NA; k <<= 1) {
        int j = k >> 1;
        for (; j >= 128; j >>= 1) {
            #pragma unroll 2
            for (int p = tid; p < NA/2; p += 1024) {
                int i = ((p & ~(j-1)) << 1) | (p & (j-1));
                int il = i | j;
                bool up = ((i & k) == 0);
                float a = key[i], b = key[il];
                if (up ? (a > b) : (a < b)) {
                    key[i] = b; key[il] = a;
                    int tmp = idx[i]; idx[i] = idx[il]; idx[il] = tmp;
                }
            }
            __syncthreads();
        }
        for (; j >= 1; j >>= 1) {
            #pragma unroll 2
            for (int q = lane; q < 64; q += 32) {
                int p = (warp << 6) | q;
                int i = ((p & ~(j-1)) << 1) | (p & (j-1));
                int il = i | j;
                bool up = ((i & k) == 0);
                float a = key[i], b = key[il];
                if (up ? (a > b) : (a < b)) {
                    key[i] = b; key[il] = a;
                    int tmp = idx[i]; idx[i] = idx[il]; idx[il] = tmp;
                }
            }
            __syncwarp();
        }
        __syncthreads();
    }
    float cm = key[NA-1];

    int t0 = tid * 4;
    float kw0 = key[t0], kw1 = key[t0+1], kw2 = key[t0+2], kw3 = key[t0+3];
    float wB0 = expf(0.2f*(kw0-cm)), wB1 = expf(0.2f*(kw1-cm));
    float wB2 = expf(0.2f*(kw2-cm)), wB3 = expf(0.2f*(kw3-cm));
    float wA0 = expf(kw0-cm), wA1 = expf(kw1-cm), wA2 = expf(kw2-cm), wA3 = expf(kw3-cm);
    *(int4*)&g_sidx[h*NA + t0] = make_int4(idx[t0], idx[t0+1], idx[t0+2], idx[t0+3]);
    *(float4*)&g_wA[h*NA + t0] = make_float4(wA0, wA1, wA2, wA3);
    *(float4*)&g_wB[h*NA + t0] = make_float4(wB0, wB1, wB2, wB3);

    {
        float v0 = wB0, v1 = v0+wB1, v2 = v1+wB2, v3 = v2+wB3;
        float tot = v3, s = tot;
        #pragma unroll
        for (int o = 1; o < 32; o <<= 1) { float u = __shfl_up_sync(0xffffffffu, s, o); if (lane >= o) s += u; }
        if (lane == 31) wsum[warp] = s;
        __syncthreads();
        if (warp == 0) {
            float y = wsum[lane];
            #pragma unroll
            for (int o = 1; o < 32; o <<= 1) { float u = __shfl_up_sync(0xffffffffu, y, o); if (lane >= o) y += u; }
            wsum[lane] = y;
        }
        __syncthreads();
        float off = (warp ? wsum[warp-1] : 0.f) + (s - tot);
        sB[t0] = off+v0; sB[t0+1] = off+v1; sB[t0+2] = off+v2; sB[t0+3] = off+v3;
    }
    __syncthreads();
    {
        int rb = NA - 4 - t0;
        float a0 = expf(key[rb]-cm),   a1 = expf(key[rb+1]-cm);
        float a2 = expf(key[rb+2]-cm), a3 = expf(key[rb+3]-cm);
        float u0 = a3, u1 = u0+a2, u2 = u1+a1, u3 = u2+a0;
        float tot = u3, s = tot;
        #pragma unroll
        for (int o = 1; o < 32; o <<= 1) { float u = __shfl_up_sync(0xffffffffu, s, o); if (lane >= o) s += u; }
        if (lane == 31) wsum[warp] = s;
        __syncthreads();
        if (warp == 0) {
            float y = wsum[lane];
            #pragma unroll
            for (int o = 1; o < 32; o <<= 1) { float u = __shfl_up_sync(0xffffffffu, y, o); if (lane >= o) y += u; }
            wsum[lane] = y;
        }
        __syncthreads();
        float off = (warp ? wsum[warp-1] : 0.f) + (s - tot);
        sA[rb] = off+u3; sA[rb+1] = off+u2; sA[rb+2] = off+u1; sA[rb+3] = off+u0;
    }
    __syncthreads();

    for (int l = 0; l < 4; l++) {
        int n = tid + l*1024;
        float cin = g_ci[h*NA + n];
        float t = -cin;
        int lo = 0, hi = NA;
        while (lo < hi) {
            int mid = (lo + hi) >> 1;
            if (key[mid] <= t) lo = mid + 1; else hi = mid;
        }
        float r = expf(0.8f * (cin + cm));
        float A = (lo < NA) ? sA[lo]     : 0.f;
        float B = (lo > 0)  ? sB[lo - 1] : 0.f;
        g_kcount[h*NA + n] = lo;
        g_rn[h*NA + n]     = r;
        g_invd[h*NA + n]   = 1.f / (r*A + B);
        g_ci[h*NA + n] = 0.f;
        g_cj[h*NA + n] = 0.f;
    }
}

// ---------------- scomb: 2 columns per block (shared perm/meta) --------------
// grid 128, 512 threads, dynamic smem: s_x0,s_x1,s_pre,s_suf = 4*NA floats.
__global__ void __launch_bounds__(512)
scomb(const float* __restrict__ bias, float* __restrict__ outT,
      int G, int do_elu, int do_mm)
{
    extern __shared__ float smsf[];
    float* s_x0  = smsf;
    float* s_x1  = smsf + NA;
    float* s_pre = smsf + 2*NA;
    float* s_suf = smsf + 3*NA;
    __shared__ float wsum[16];
    int cbase = blockIdx.x * 2;
    int h = cbase / G;
    int tid = threadIdx.x, lane = tid & 31, warp = tid >> 5;
    int t0 = tid * 8;
    const float* xrow0 = g_hWT + (size_t)cbase * NA;
    const float* xrow1 = xrow0 + NA;

    // gather both columns with one sidx load
    {
        int4 iva = *(const int4*)&g_sidx[h*NA + t0];
        int4 ivb = *(const int4*)&g_sidx[h*NA + t0 + 4];
        int ix[8] = { iva.x, iva.y, iva.z, iva.w, ivb.x, ivb.y, ivb.z, ivb.w };
        #pragma unroll
        for (int e = 0; e < 8; e++) {
            s_x0[t0+e] = xrow0[ix[e]];
            s_x1[t0+e] = xrow1[ix[e]];
        }
    }
    __syncthreads();

    float mn = 1e30f, mx = -1e30f;
    #pragma unroll 1
    for (int cc = 0; cc < 2; cc++) {
        const float* sx = cc ? s_x1 : s_x0;
        int c = cbase + cc;
        // prefix of wB*x
        {
            float4 wa = *(const float4*)&g_wB[h*NA + t0];
            float4 wb = *(const float4*)&g_wB[h*NA + t0 + 4];
            float v[8];
            float run = wa.x * sx[t0+0];   v[0] = run;
            run += wa.y * sx[t0+1];        v[1] = run;
            run += wa.z * sx[t0+2];        v[2] = run;
            run += wa.w * sx[t0+3];        v[3] = run;
            run += wb.x * sx[t0+4];        v[4] = run;
            run += wb.y * sx[t0+5];        v[5] = run;
            run += wb.z * sx[t0+6];        v[6] = run;
            run += wb.w * sx[t0+7];        v[7] = run;
            float tot = run, s = tot;
            #pragma unroll
            for (int o = 1; o < 32; o <<= 1) { float u = __shfl_up_sync(0xffffffffu, s, o); if (lane >= o) s += u; }
            if (lane == 31) wsum[warp] = s;
            __syncthreads();
            if (warp == 0 && lane < 16) {
                float y = wsum[lane];
                #pragma unroll
                for (int o = 1; o < 16; o <<= 1) { float u = __shfl_up_sync(0xffffu, y, o); if (lane >= o) y += u; }
                wsum[lane] = y;
            }
            __syncthreads();
            float off = (warp ? wsum[warp-1] : 0.f) + (s - tot);
            #pragma unroll
            for (int e = 0; e < 8; e++) s_pre[t0+e] = off + v[e];
        }
        __syncthreads();
        // suffix of wA*x
        {
            int rb = NA - 8 - t0;
            float4 wa = *(const float4*)&g_wA[h*NA + rb];
            float4 wb = *(const float4*)&g_wA[h*NA + rb + 4];
            float ws[8] = { wa.x, wa.y, wa.z, wa.w, wb.x, wb.y, wb.z, wb.w };
            float u[8];
            float run = ws[7]*sx[rb+7];  u[0] = run;
            #pragma unroll
            for (int e = 1; e < 8; e++) { run += ws[7-e]*sx[rb+7-e]; u[e] = run; }
            float tot = run, s = tot;
            #pragma unroll
            for (int o = 1; o < 32; o <<= 1) { float uu = __shfl_up_sync(0xffffffffu, s, o); if (lane >= o) s += uu; }
            if (lane == 31) wsum[warp] = s;
            __syncthreads();
            if (warp == 0 && lane < 16) {
                float y = wsum[lane];
                #pragma unroll
                for (int o = 1; o < 16; o <<= 1) { float uu = __shfl_up_sync(0xffffu, y, o); if (lane >= o) y += uu; }
                wsum[lane] = y;
            }
            __syncthreads();
            float off = (warp ? wsum[warp-1] : 0.f) + (s - tot);
            #pragma unroll
            for (int e = 0; e < 8; e++) s_suf[rb + 7 - e] = off + u[e];
        }
        __syncthreads();

        float bv = bias[c];
        #pragma unroll
        for (int l = 0; l < 8; l++) {
            int n = tid + l*512;
            int k = g_kcount[h*NA + n];
            float r = g_rn[h*NA + n];
            float invd = g_invd[h*NA + n];
            float Av = (k < NA) ? s_suf[k]     : 0.f;
            float Bv = (k > 0)  ? s_pre[k - 1] : 0.f;
            float val = (r*Av + Bv) * invd + bv;
            if (do_elu) val = (val > 0.f) ? val : expm1f(val);
            mn = fminf(mn, val); mx = fmaxf(mx, val);
            outT[(size_t)c*NA + n] = val;
        }
        __syncthreads();   // before reusing s_pre/s_suf
    }
    if (do_mm) {
        __shared__ float smn[512], smx[512];
        smn[tid] = mn; smx[tid] = mx; __syncthreads();
        for (int s = 256; s > 0; s >>= 1) {
            if (tid < s) {
                smn[tid] = fminf(smn[tid], smn[tid+s]);
                smx[tid] = fmaxf(smx[tid], smx[tid+s]);
            }
            __syncthreads();
        }
        if (tid == 0) { g_pmin[blockIdx.x] = smn[0]; g_pmax[blockIdx.x] = smx[0]; }
    }
}

// ---------------- fused policy + value head: 32 rows/block (grid 128) --------
__global__ void __launch_bounds__(256)
policyk(const float* __restrict__ A0, const float* __restrict__ A1T,
        const float* __restrict__ Wa, const float* __restrict__ ba,
        const float* __restrict__ Wv, const float* __restrict__ bv,
        float* __restrict__ out_logp, float* __restrict__ out_value,
        float* __restrict__ out_loss)
{
    if (blockIdx.x == 0 && threadIdx.x == 0) out_loss[0] = g_loss;
    __shared__ float As[16][36];
    __shared__ float Bs[16][68];
    __shared__ float Ss[32][65];
    int tid = threadIdx.x;
    int tx = tid % 16, ty = tid / 16;
    int row0 = blockIdx.x * 32;
    float acc[2][4] = {};
    float vacc = 0.f;

    for (int k0 = 0; k0 < 512; k0 += 16) {
        if (k0 < 256) {
            int lin = tid * 2;
            int m = lin >> 4, kk = lin & 15;
            float2 v = *(const float2*)&A0[(size_t)(row0+m)*256 + k0 + kk];
            As[kk][m] = v.x; As[kk+1][m] = v.y;
        } else {
            int lin = tid * 2;
            int kk = lin >> 5, m2 = lin & 31;
            float2 v = *(const float2*)&A1T[(size_t)(k0-256+kk)*NA + row0 + m2];
            As[kk][m2] = v.x; As[kk][m2+1] = v.y;
        }
        {
            int lin = tid * 4;
            int kk = lin >> 6, n = lin & 63;
            *(float4*)&Bs[kk][n] = *(const float4*)&Wa[(size_t)(k0+kk)*64 + n];
        }
        __syncthreads();
        #pragma unroll
        for (int kk = 0; kk < 16; kk++) {
            float a[2], bb[4];
            a[0] = As[kk][ty*2+0];
            a[1] = As[kk][ty*2+1];
            #pragma unroll
            for (int j = 0; j < 4; j++) bb[j] = Bs[kk][tx*4+j];
            #pragma unroll
            for (int i = 0; i < 2; i++)
                #pragma unroll
                for (int j = 0; j < 4; j++)
                    acc[i][j] = fmaf(a[i], bb[j], acc[i][j]);
        }
        if (tid < 32) {
            #pragma unroll
            for (int kk = 0; kk < 16; kk++)
                vacc = fmaf(As[kk][tid], Wv[k0+kk], vacc);
        }
        __syncthreads();
    }
    if (tid < 32) out_value[row0 + tid] = vacc + bv[0];

    #pragma unroll
    for (int i = 0; i < 2; i++)
        #pragma unroll
        for (int j = 0; j < 4; j++)
            Ss[ty*2+i][tx*4+j] = acc[i][j] + ba[tx*4+j];
    __syncthreads();

    if (tid < 128) {
        int row = tid >> 2, quad = tid & 3;
        float m = -1e30f;
        #pragma unroll
        for (int c = 0; c < 16; c++) m = fmaxf(m, Ss[row][quad*16 + c]);
        m = fmaxf(m, __shfl_xor_sync(0xffffffffu, m, 1));
        m = fmaxf(m, __shfl_xor_sync(0xffffffffu, m, 2));
        float s = 0.f;
        #pragma unroll
        for (int c = 0; c < 16; c++) s += expf(Ss[row][quad*16 + c] - m);
        s += __shfl_xor_sync(0xffffffffu, s, 1);
        s += __shfl_xor_sync(0xffffffffu, s, 2);
        float lse = m + logf(s);
        #pragma unroll
        for (int c = 0; c < 16; c++)
            out_logp[(size_t)(row0+row)*64 + quad*16 + c] = Ss[row][quad*16 + c] - lse;
    }
}

// ---------------- host ----------------
extern "C" void kernel_launch(void* const* d_in, const int* in_sizes, int n_in,
                              void* d_out, int out_size)
{
    const float* obs  = (const float*)d_in[0];
    const float* h0   = (const float*)d_in[1];
    const float* c0   = (const float*)d_in[2];
    const float* Wobs = (const float*)d_in[3];
    const float* bobs = (const float*)d_in[4];
    const float* Wih  = (const float*)d_in[5];
    const float* Whh  = (const float*)d_in[6];
    const float* bih  = (const float*)d_in[7];
    const float* bhh  = (const float*)d_in[8];
    const float* W1   = (const float*)d_in[9];
    const float* ai1  = (const float*)d_in[10];
    const float* aj1  = (const float*)d_in[11];
    const float* b1   = (const float*)d_in[12];
    const float* W2   = (const float*)d_in[13];
    const float* ai2  = (const float*)d_in[14];
    const float* aj2  = (const float*)d_in[15];
    const float* b2   = (const float*)d_in[16];
    const float* Wv   = (const float*)d_in[17];
    const float* bv   = (const float*)d_in[18];
    const float* Wa   = (const float*)d_in[19];
    const float* ba   = (const float*)d_in[20];

    float* out       = (float*)d_out;
    float* out_logp  = out;
    float* out_value = out + NA*ACT;
    float* out_h     = out_value + NA;
    float* out_c     = out_h + NA*HD;
    float* out_loss  = out_c + NA*HD;

    float *p_hWT, *p_commT, *p_bsum, *p_qscale;
    __nv_bfloat16 *p_Ah, *p_Al, *p_A2h, *p_A2l;
    __nv_bfloat16 *p_B0h, *p_B0l, *p_Bgh, *p_Bgl, *p_B1h, *p_B1l, *p_B2h, *p_B2l;
    cudaGetSymbolAddress((void**)&p_hWT,    g_hWT);
    cudaGetSymbolAddress((void**)&p_commT,  g_commT);
    cudaGetSymbolAddress((void**)&p_bsum,   g_bsum);
    cudaGetSymbolAddress((void**)&p_qscale, g_qscale);
    cudaGetSymbolAddress((void**)&p_Ah,     g_Ah);
    cudaGetSymbolAddress((void**)&p_Al,     g_Al);
    cudaGetSymbolAddress((void**)&p_A2h,    g_A2h);
    cudaGetSymbolAddress((void**)&p_A2l,    g_A2l);
    cudaGetSymbolAddress((void**)&p_B0h,    g_B0h);
    cudaGetSymbolAddress((void**)&p_B0l,    g_B0l);
    cudaGetSymbolAddress((void**)&p_Bgh,    g_Bgh);
    cudaGetSymbolAddress((void**)&p_Bgl,    g_Bgl);
    cudaGetSymbolAddress((void**)&p_B1h,    g_B1h);
    cudaGetSymbolAddress((void**)&p_B1l,    g_B1l);
    cudaGetSymbolAddress((void**)&p_B2h,    g_B2h);
    cudaGetSymbolAddress((void**)&p_B2l,    g_B2l);

    const int SM64   = TG_SMEM_BYTES(64);
    const int SMSORT = NA * 16;
    const int SMSCOMB = NA * 4 * (int)sizeof(float);   // 64 KB
    cudaFuncSetAttribute((const void*)tgemm<64,false>, cudaFuncAttributeMaxDynamicSharedMemorySize, SM64);
    cudaFuncSetAttribute((const void*)tgemm<64,true>,  cudaFuncAttributeMaxDynamicSharedMemorySize, SM64);
    cudaFuncSetAttribute((const void*)gatesk,          cudaFuncAttributeMaxDynamicSharedMemorySize, GW_SMEM);
    cudaFuncSetAttribute((const void*)sortk,           cudaFuncAttributeMaxDynamicSharedMemorySize, SMSORT);
    cudaFuncSetAttribute((const void*)scomb,           cudaFuncAttributeMaxDynamicSharedMemorySize, SMSCOMB);

    // 1. prep
    wprep<<<(WVTOT + 255)/256, 256>>>(obs, h0, Wobs, Wih, Whh, W1, W2, bih, bhh, bobs);
    // 2. weight-product GEMM -> Bg cols 0..255 (split output, 3-pass)
    tgemm<64,false><<<dim3(2, 16), 256, SM64>>>(p_A2h, p_A2l, p_B0h, p_B0l, nullptr, nullptr,
                                                p_Bgh, p_Bgl, 512,
                                                nullptr, nullptr, nullptr, 0, 256, 256);
    // 3. gates GEMM (128x256 tile, single wave) + fused LSTM
    gatesk<<<dim3(4, 32), 256, GW_SMEM>>>(p_Ah, p_Al, p_Bgh, p_Bgl, p_bsum,
                                          c0, out_h, out_c, 512);
    // 4. quant #1 -> exact q into A2h + g_qscale
    quantA<<<256, 256>>>(out_h, p_A2h, 128);
    // 5. GAT1 projection (2-pass, scaled epilogue) -> hWT + fused ci/cj
    tgemm<64,true><<<dim3(2, 64), 256, SM64>>>(p_A2h, nullptr, p_B1h, p_B1l, nullptr, p_qscale,
                                               nullptr, nullptr, 0,
                                               p_hWT, ai1, aj1, 64, 256, 256);
    // 6-7. GAT1 attention
    sortk<<<4, 1024, SMSORT>>>();
    scomb<<<128, 512, SMSCOMB>>>(b1, p_commT, 64, 1, 1);
    // 8. quant #2 (transposed input) -> exact q + g_qscale (128 partials now)
    quantT<<<dim3(NA/128, 8), dim3(32, 8)>>>(p_commT, p_A2h, 128);
    // 9. GAT2 projection (2-pass, scaled epilogue)
    tgemm<64,true><<<dim3(2, 64), 256, SM64>>>(p_A2h, nullptr, p_B2h, p_B2l, nullptr, p_qscale,
                                               nullptr, nullptr, 0,
                                               p_hWT, ai2, aj2, 256, 256, 256);
    // 10-11. GAT2 attention
    sortk<<<1, 1024, SMSORT>>>();
    scomb<<<128, 512, SMSCOMB>>>(b2, p_commT, 256, 0, 0);
    // 12. fused policy + value heads + loss (32 rows/block)
    policyk<<<NA/32, 256>>>(out_h, p_commT, Wa, ba, Wv, bv, out_logp, out_value, out_loss);
}